// round 9
// baseline (speedup 1.0000x reference)
#include <cuda_runtime.h>
#include <cuda_fp16.h>
#include <cstdint>

#define SQ   2048
#define HID  2560
#define NH   16
#define NKV  4
#define HD   128
#define QKV_DIM (NH*HD + 2*NKV*HD)   // 3072
#define EPS  1e-6f
#define ATT_SCALE 0.08838834764831845f  // 1/sqrt(128)
#define VOFF (NH*HD + NKV*HD)

// ---------------- scratch (device globals, no allocation) ----------------
__device__ __half g_qkv[(size_t)SQ * QKV_DIM];
__device__ __half g_att[(size_t)SQ * NH * HD];
__device__ __half g_hs_h[(size_t)SQ * HID];
__device__ __half g_wqkv_h[(size_t)QKV_DIM * HID];
__device__ __half g_wo_h[(size_t)HID * NH * HD];
__device__ __half g_vt[(size_t)NKV * HD * SQ];

__device__ __forceinline__ void mma_f16(float* d, const uint32_t* a, const uint32_t* b) {
    asm volatile(
        "mma.sync.aligned.m16n8k16.row.col.f32.f16.f16.f32 "
        "{%0,%1,%2,%3}, {%4,%5,%6,%7}, {%8,%9}, {%0,%1,%2,%3};\n"
        : "+f"(d[0]), "+f"(d[1]), "+f"(d[2]), "+f"(d[3])
        : "r"(a[0]), "r"(a[1]), "r"(a[2]), "r"(a[3]), "r"(b[0]), "r"(b[1]));
}

__device__ __forceinline__ void ldmx4(uint32_t* r, uint32_t addr) {
    asm volatile("ldmatrix.sync.aligned.m8n8.x4.shared.b16 {%0,%1,%2,%3}, [%4];"
        : "=r"(r[0]), "=r"(r[1]), "=r"(r[2]), "=r"(r[3]) : "r"(addr));
}

__device__ __forceinline__ void cpasync(uint32_t d, const void* s) {
    asm volatile("cp.async.cg.shared.global [%0], [%1], 16;\n" :: "r"(d), "l"(s));
}

__device__ __forceinline__ uint32_t h2u(__half2 h) {
    return *reinterpret_cast<uint32_t*>(&h);
}

// ---------------- fp16 tensor-core GEMM ----------------
// C[m,n] = alpha * sum_k A[m,k] * B[n,k]  (row-major NT), fp32 accumulate.
// 128x128 CTA tile, 256 thr (8 warps, 2Mx4N of 64x32), K chunks of 64,
// 3-stage cp.async with issue-before-compute, ldmatrix fragments, m16n8k16.
template<bool OUTF32>
__global__ void __launch_bounds__(256, 2) mma_gemm(
    const __half* __restrict__ A, const __half* __restrict__ B, void* __restrict__ Cv,
    int K, int lda, int ldb, int ldc, float alpha)
{
    const int bx = blockIdx.x, by = blockIdx.y;

    extern __shared__ char smem[];
    const uint32_t sbase = (uint32_t)__cvta_generic_to_shared(smem);

    const int t    = threadIdx.x;
    const int lane = t & 31, wid = t >> 5;
    const int wm   = (wid & 1) * 64;
    const int wn   = (wid >> 1) * 32;
    const int m0   = by * 128, n0 = bx * 128;
    const int grp  = lane >> 2, tid4 = lane & 3;

    const int l8    = lane & 7;
    const int aoff8 = ((lane >> 3) & 1) * 8;
    const int ags   = (lane >> 4) & 1;
    const int boff8 = ((lane >> 4) & 1) * 8;
    const int bgs   = (lane >> 3) & 1;
    uint32_t arow[4], brow[2];
    #pragma unroll
    for (int mt = 0; mt < 4; mt++) arow[mt] = (uint32_t)(wm + mt * 16 + aoff8 + l8) * 128u;
    #pragma unroll
    for (int pr = 0; pr < 2; pr++) brow[pr] = (uint32_t)(wn + pr * 16 + boff8 + l8) * 128u;

    const int lrow = t >> 1;
    const int cb   = (t & 1) * 4;
    const int x7   = lrow & 7;
    const __half* Aptr = A + (long long)(m0 + lrow) * lda;
    const __half* Bptr = B + (long long)(n0 + lrow) * ldb;

    float acc[4][4][4];
    #pragma unroll
    for (int i = 0; i < 4; i++)
        #pragma unroll
        for (int j = 0; j < 4; j++)
            #pragma unroll
            for (int r = 0; r < 4; r++) acc[i][j][r] = 0.f;

    const int nK = K >> 6;

    auto issue = [&](int st, int k0) {
        const uint32_t ab = sbase + st * 16384u + (uint32_t)lrow * 128u;
        const uint32_t bb = sbase + 49152u + st * 16384u + (uint32_t)lrow * 128u;
        #pragma unroll
        for (int c = 0; c < 4; c++)
            cpasync(ab + (uint32_t)(((cb + c) ^ x7) << 4), Aptr + k0 + (cb + c) * 8);
        #pragma unroll
        for (int c = 0; c < 4; c++)
            cpasync(bb + (uint32_t)(((cb + c) ^ x7) << 4), Bptr + k0 + (cb + c) * 8);
    };

    issue(0, 0);
    asm volatile("cp.async.commit_group;\n");
    issue(1, 64);
    asm volatile("cp.async.commit_group;\n");

    for (int kt = 0; kt < nK; kt++) {
        asm volatile("cp.async.wait_group 1;\n");
        __syncthreads();

        // issue next-next chunk BEFORE compute — barrier above guarantees
        // compute(kt-1), the last reader of stage (kt+2)%3, has finished.
        if (kt + 2 < nK) issue((kt + 2) - ((kt + 2) / 3) * 3, (kt + 2) << 6);
        asm volatile("cp.async.commit_group;\n");

        const int st = kt - (kt / 3) * 3;
        const uint32_t sA = sbase + st * 16384u;
        const uint32_t sB = sbase + 49152u + st * 16384u;

        #pragma unroll
        for (int j = 0; j < 4; j++) {
            const uint32_t ga = (uint32_t)(((2 * j + ags) ^ l8) << 4);
            const uint32_t gb = (uint32_t)(((2 * j + bgs) ^ l8) << 4);
            uint32_t af[4][4], bq[2][4];
            #pragma unroll
            for (int mt = 0; mt < 4; mt++) ldmx4(af[mt], sA + arow[mt] + ga);
            ldmx4(bq[0], sB + brow[0] + gb);
            ldmx4(bq[1], sB + brow[1] + gb);
            #pragma unroll
            for (int mt = 0; mt < 4; mt++) {
                mma_f16(acc[mt][0], af[mt], &bq[0][0]);
                mma_f16(acc[mt][1], af[mt], &bq[0][2]);
                mma_f16(acc[mt][2], af[mt], &bq[1][0]);
                mma_f16(acc[mt][3], af[mt], &bq[1][2]);
            }
        }
    }

    #pragma unroll
    for (int mt = 0; mt < 4; mt++) {
        #pragma unroll
        for (int nt = 0; nt < 4; nt++) {
            const int r0 = m0 + wm + mt * 16 + grp;
            const int col = n0 + wn + nt * 8 + tid4 * 2;
            if (OUTF32) {
                float* C = (float*)Cv;
                float2 lo, hi;
                lo.x = acc[mt][nt][0] * alpha; lo.y = acc[mt][nt][1] * alpha;
                hi.x = acc[mt][nt][2] * alpha; hi.y = acc[mt][nt][3] * alpha;
                *(float2*)(C + (long long)r0 * ldc + col)       = lo;
                *(float2*)(C + (long long)(r0 + 8) * ldc + col) = hi;
            } else {
                __half* C = (__half*)Cv;
                __half2 lo = __floats2half2_rn(acc[mt][nt][0] * alpha, acc[mt][nt][1] * alpha);
                __half2 hi = __floats2half2_rn(acc[mt][nt][2] * alpha, acc[mt][nt][3] * alpha);
                *(__half2*)(C + (long long)r0 * ldc + col)       = lo;
                *(__half2*)(C + (long long)(r0 + 8) * ldc + col) = hi;
            }
        }
    }
}

// ---------------- fused flash attention (fp16 operands, fp32 softmax/accum) ----------------
// grid (NH, 16 q-tiles), 256 thr, 2 CTAs/SM (112KB SMEM each -> one full wave).
__global__ void __launch_bounds__(256, 2) flash_kernel()
{
    extern __shared__ char fsm[];
    const uint32_t sb = (uint32_t)__cvta_generic_to_shared(fsm);
    const uint32_t Qb = sb;
    const uint32_t Kb = sb + 32768u;
    const uint32_t Vb = sb + 65536u;
    const uint32_t Pb = sb + 98304u;

    const int h  = blockIdx.x;
    const int yy = blockIdx.y;
    const int qt = (yy < 8) ? (15 - yy) : (yy - 8);   // heavy tiles first
    const int hkv = h >> 2;

    const int t = threadIdx.x, lane = t & 31, wid = t >> 5;
    const int grp = lane >> 2, tid4 = lane & 3;
    const int l8 = lane & 7;
    const int aoff8 = ((lane >> 3) & 1) * 8;
    const int ags   = (lane >> 4) & 1;
    const int boff8 = ((lane >> 4) & 1) * 8;
    const int bgs   = (lane >> 3) & 1;

    const __half* Qg  = g_qkv + h * HD;
    const __half* Kg  = g_qkv + NH * HD + hkv * HD;
    const __half* Vtg = g_vt + (size_t)hkv * HD * SQ;

    // ---- load Q tile once ----
    {
        const int r = t >> 1, cb = (t & 1) * 4, x7 = r & 7;
        const __half* src = Qg + (size_t)(qt * 128 + r) * QKV_DIM;
        #pragma unroll
        for (int kc = 0; kc < 2; kc++)
            #pragma unroll
            for (int c = 0; c < 4; c++)
                cpasync(Qb + kc * 16384u + (uint32_t)r * 128u +
                        ((uint32_t)((cb + c) ^ x7) << 4),
                        src + kc * 64 + (cb + c) * 8);
    }

    const int T = 2 * qt + 2;
    const int kr = t & 63, kkc = (t >> 6) & 1, kgh = t >> 7;
    const int vd = t >> 1, vcb = (t & 1) * 4;
    const int kx7 = kr & 7, vx7 = vd & 7;

    auto issueKV = [&](int st, int kv0) {
        const uint32_t Ks = Kb + (uint32_t)st * 16384u;
        const __half* ksrc = Kg + (size_t)(kv0 + kr) * QKV_DIM + kkc * 64;
        #pragma unroll
        for (int c = 0; c < 4; c++) {
            const int g = kgh * 4 + c;
            cpasync(Ks + kkc * 8192u + (uint32_t)kr * 128u + ((uint32_t)(g ^ kx7) << 4),
                    ksrc + g * 8);
        }
        const uint32_t Vs = Vb + (uint32_t)st * 16384u;
        const __half* vsrc = Vtg + (size_t)vd * SQ + kv0;
        #pragma unroll
        for (int c = 0; c < 4; c++) {
            const int g = vcb + c;
            cpasync(Vs + (uint32_t)vd * 128u + ((uint32_t)(g ^ vx7) << 4),
                    vsrc + g * 8);
        }
    };
    issueKV(0, 0);
    asm volatile("cp.async.commit_group;\n");

    const uint32_t aQrow = (uint32_t)(wid * 16 + aoff8 + l8) * 128u;
    uint32_t bKrow[4], bVrow[8];
    #pragma unroll
    for (int pr = 0; pr < 4; pr++) bKrow[pr] = (uint32_t)(pr * 16 + boff8 + l8) * 128u;
    #pragma unroll
    for (int pr = 0; pr < 8; pr++) bVrow[pr] = (uint32_t)(pr * 16 + boff8 + l8) * 128u;

    float m0 = -1e30f, m1 = -1e30f, l0 = 0.f, l1 = 0.f;
    float O[16][4];
    #pragma unroll
    for (int i = 0; i < 16; i++)
        #pragma unroll
        for (int e = 0; e < 4; e++) O[i][e] = 0.f;

    const int q0 = qt * 128 + wid * 16 + grp;

    for (int tl = 0; tl < T; tl++) {
        asm volatile("cp.async.wait_group 0;\n");
        __syncthreads();
        if (tl + 1 < T) issueKV((tl + 1) & 1, (tl + 1) * 64);
        asm volatile("cp.async.commit_group;\n");

        const uint32_t Ks = Kb + (uint32_t)(tl & 1) * 16384u;
        const uint32_t Vs = Vb + (uint32_t)(tl & 1) * 16384u;
        const int kv0 = tl * 64;

        // ---- S = Q K^T ----
        float s[8][4];
        #pragma unroll
        for (int i = 0; i < 8; i++)
            #pragma unroll
            for (int e = 0; e < 4; e++) s[i][e] = 0.f;

        #pragma unroll
        for (int j = 0; j < 8; j++) {
            const int kc = j >> 2, jj = j & 3;
            const uint32_t gA = (uint32_t)(((2 * jj + ags) ^ l8) << 4);
            const uint32_t gB = (uint32_t)(((2 * jj + bgs) ^ l8) << 4);
            uint32_t af[4], bq[4][4];
            ldmx4(af, Qb + kc * 16384u + aQrow + gA);
            #pragma unroll
            for (int pr = 0; pr < 4; pr++)
                ldmx4(bq[pr], Ks + kc * 8192u + bKrow[pr] + gB);
            #pragma unroll
            for (int nt = 0; nt < 8; nt++)
                mma_f16(s[nt], af, &bq[nt >> 1][(nt & 1) * 2]);
        }

        // ---- scale + causal mask + online softmax ----
        const bool msk = (tl >= 2 * qt);
        float rm0 = -1e30f, rm1 = -1e30f;
        #pragma unroll
        for (int nt = 0; nt < 8; nt++) {
            const int c0 = kv0 + nt * 8 + 2 * tid4;
            float v0 = s[nt][0] * ATT_SCALE, v1 = s[nt][1] * ATT_SCALE;
            float v2 = s[nt][2] * ATT_SCALE, v3 = s[nt][3] * ATT_SCALE;
            if (msk) {
                if (c0     > q0)     v0 = -1e30f;
                if (c0 + 1 > q0)     v1 = -1e30f;
                if (c0     > q0 + 8) v2 = -1e30f;
                if (c0 + 1 > q0 + 8) v3 = -1e30f;
            }
            s[nt][0] = v0; s[nt][1] = v1; s[nt][2] = v2; s[nt][3] = v3;
            rm0 = fmaxf(rm0, fmaxf(v0, v1));
            rm1 = fmaxf(rm1, fmaxf(v2, v3));
        }
        rm0 = fmaxf(rm0, __shfl_xor_sync(0xffffffffu, rm0, 1));
        rm0 = fmaxf(rm0, __shfl_xor_sync(0xffffffffu, rm0, 2));
        rm1 = fmaxf(rm1, __shfl_xor_sync(0xffffffffu, rm1, 1));
        rm1 = fmaxf(rm1, __shfl_xor_sync(0xffffffffu, rm1, 2));

        const float mn0 = fmaxf(m0, rm0), mn1 = fmaxf(m1, rm1);
        const float sc0 = __expf(m0 - mn0), sc1 = __expf(m1 - mn1);
        m0 = mn0; m1 = mn1;

        float sum0 = 0.f, sum1 = 0.f;
        #pragma unroll
        for (int nt = 0; nt < 8; nt++) {
            s[nt][0] = __expf(s[nt][0] - m0);
            s[nt][1] = __expf(s[nt][1] - m0);
            s[nt][2] = __expf(s[nt][2] - m1);
            s[nt][3] = __expf(s[nt][3] - m1);
            sum0 += s[nt][0] + s[nt][1];
            sum1 += s[nt][2] + s[nt][3];
        }
        sum0 += __shfl_xor_sync(0xffffffffu, sum0, 1);
        sum0 += __shfl_xor_sync(0xffffffffu, sum0, 2);
        sum1 += __shfl_xor_sync(0xffffffffu, sum1, 1);
        sum1 += __shfl_xor_sync(0xffffffffu, sum1, 2);
        l0 = l0 * sc0 + sum0;
        l1 = l1 * sc1 + sum1;

        #pragma unroll
        for (int nt = 0; nt < 16; nt++) {
            O[nt][0] *= sc0; O[nt][1] *= sc0;
            O[nt][2] *= sc1; O[nt][3] *= sc1;
        }

        // ---- write P (fp16) ----
        {
            const int r0w = wid * 16 + grp, r1w = r0w + 8;
            #pragma unroll
            for (int nt = 0; nt < 8; nt++) {
                const uint32_t a0 = Pb + (uint32_t)r0w * 128u +
                                    ((uint32_t)(nt ^ (r0w & 7)) << 4) + tid4 * 4;
                const uint32_t a1 = Pb + (uint32_t)r1w * 128u +
                                    ((uint32_t)(nt ^ (r1w & 7)) << 4) + tid4 * 4;
                asm volatile("st.shared.b32 [%0], %1;"
                             :: "r"(a0), "r"(h2u(__floats2half2_rn(s[nt][0], s[nt][1]))));
                asm volatile("st.shared.b32 [%0], %1;"
                             :: "r"(a1), "r"(h2u(__floats2half2_rn(s[nt][2], s[nt][3]))));
            }
        }
        __syncthreads();

        // ---- O += P @ V ----
        #pragma unroll
        for (int j = 0; j < 4; j++) {
            const uint32_t gA = (uint32_t)(((2 * j + ags) ^ l8) << 4);
            const uint32_t gB = (uint32_t)(((2 * j + bgs) ^ l8) << 4);
            uint32_t af[4], bq[8][4];
            ldmx4(af, Pb + aQrow + gA);
            #pragma unroll
            for (int pr = 0; pr < 8; pr++)
                ldmx4(bq[pr], Vs + bVrow[pr] + gB);
            #pragma unroll
            for (int nt = 0; nt < 16; nt++)
                mma_f16(O[nt], af, &bq[nt >> 1][(nt & 1) * 2]);
        }
    }

    // ---- epilogue ----
    const float inv0 = 1.f / l0, inv1 = 1.f / l1;
    const int row0 = qt * 128 + wid * 16 + grp;
    __half* o0 = g_att + (size_t)row0 * (NH * HD) + h * HD;
    __half* o1 = o0 + (size_t)8 * (NH * HD);
    #pragma unroll
    for (int nt = 0; nt < 16; nt++) {
        const int col = nt * 8 + 2 * tid4;
        *(__half2*)(o0 + col) = __floats2half2_rn(O[nt][0] * inv0, O[nt][1] * inv0);
        *(__half2*)(o1 + col) = __floats2half2_rn(O[nt][2] * inv1, O[nt][3] * inv1);
    }
}

// ---------------- fp32 -> fp16 convert ----------------
__global__ void __launch_bounds__(256) cvt_half(const float* __restrict__ src,
                                               __half* __restrict__ dst, int n4)
{
    int i = blockIdx.x * 256 + threadIdx.x;
    if (i < n4) {
        float4 v = ((const float4*)src)[i];
        uint2 u;
        u.x = h2u(__floats2half2_rn(v.x, v.y));
        u.y = h2u(__floats2half2_rn(v.z, v.w));
        ((uint2*)dst)[i] = u;
    }
}

// ---------------- V transpose (half) ----------------
__global__ void __launch_bounds__(256) vt_kernel()
{
    __shared__ __half tile[32][40];
    const int s0 = blockIdx.x * 32, d0 = blockIdx.y * 32;
    const int tx = threadIdx.x & 31, ty = threadIdx.x >> 5;
    #pragma unroll
    for (int r = ty; r < 32; r += 8)
        tile[r][tx] = g_qkv[(long long)(s0 + r) * QKV_DIM + VOFF + d0 + tx];
    __syncthreads();
    #pragma unroll
    for (int r = ty; r < 32; r += 8)
        g_vt[(long long)(d0 + r) * SQ + s0 + tx] = tile[tx][r];
}

// ---------------- fused RMSNorm + RoPE ----------------
__global__ void __launch_bounds__(128) norm_rope_kernel(
    const float* __restrict__ qw, const float* __restrict__ kw,
    const float* __restrict__ cosT, const float* __restrict__ sinT,
    const int* __restrict__ positions)
{
    const int tok = blockIdx.x;
    const int hh  = blockIdx.y;
    const int d   = threadIdx.x;

    __half* ptr;
    const float* w;
    if (hh < NH) { ptr = g_qkv + (long long)tok * QKV_DIM + hh * HD;            w = qw; }
    else         { ptr = g_qkv + (long long)tok * QKV_DIM + NH*HD + (hh-NH)*HD; w = kw; }

    __shared__ float x[HD];
    __shared__ float red[4];

    float v = __half2float(ptr[d]);
    float ss = v * v;
    #pragma unroll
    for (int o = 16; o > 0; o >>= 1) ss += __shfl_xor_sync(0xffffffffu, ss, o);
    if ((d & 31) == 0) red[d >> 5] = ss;
    __syncthreads();
    float tot = red[0] + red[1] + red[2] + red[3];
    float r = rsqrtf(tot * (1.0f / HD) + EPS);
    x[d] = v * r * w[d];
    __syncthreads();

    const int pos = positions[tok];
    const int p = d >> 1;
    const float c = cosT[pos * (HD/2) + p];
    const float s = sinT[pos * (HD/2) + p];
    float out;
    if ((d & 1) == 0) out = x[d] * c - x[d + 1] * s;
    else              out = x[d - 1] * s + x[d] * c;
    ptr[d] = __float2half_rn(out);
}

// ---------------- launch ----------------
extern "C" void kernel_launch(void* const* d_in, const int* in_sizes, int n_in,
                              void* d_out, int out_size)
{
    const float* hs     = (const float*)d_in[0];
    const float* w_qkv  = (const float*)d_in[1];
    const float* w_o    = (const float*)d_in[2];
    const float* qnw    = (const float*)d_in[3];
    const float* knw    = (const float*)d_in[4];
    const float* cosT   = (const float*)d_in[5];
    const float* sinT   = (const float*)d_in[6];
    const int* positions = (const int*)d_in[9];
    float* out = (float*)d_out;

    __half *qkv, *att, *hs_h, *wqkv_h, *wo_h;
    cudaGetSymbolAddress((void**)&qkv,    g_qkv);
    cudaGetSymbolAddress((void**)&att,    g_att);
    cudaGetSymbolAddress((void**)&hs_h,   g_hs_h);
    cudaGetSymbolAddress((void**)&wqkv_h, g_wqkv_h);
    cudaGetSymbolAddress((void**)&wo_h,   g_wo_h);

    const int GSMEM = 3 * 2 * 16384;   // 96 KB
    const int FSMEM = 114688;          // 112 KB
    cudaFuncSetAttribute(mma_gemm<false>, cudaFuncAttributeMaxDynamicSharedMemorySize, GSMEM);
    cudaFuncSetAttribute(mma_gemm<true >, cudaFuncAttributeMaxDynamicSharedMemorySize, GSMEM);
    cudaFuncSetAttribute(flash_kernel,    cudaFuncAttributeMaxDynamicSharedMemorySize, FSMEM);

    // 0) convert operands to fp16
    cvt_half<<<(SQ*HID/4 + 255)/256, 256>>>(hs, hs_h, SQ*HID/4);
    cvt_half<<<(QKV_DIM*HID/4 + 255)/256, 256>>>(w_qkv, wqkv_h, QKV_DIM*HID/4);
    cvt_half<<<(HID*NH*HD/4 + 255)/256, 256>>>(w_o, wo_h, HID*NH*HD/4);

    // 1) QKV projection (half out)
    mma_gemm<false><<<dim3(QKV_DIM/128, SQ/128, 1), 256, GSMEM>>>(
        hs_h, wqkv_h, qkv, HID, HID, HID, QKV_DIM, 1.0f);

    // 2) RMSNorm + RoPE in-place on q,k
    norm_rope_kernel<<<dim3(SQ, NH + NKV), 128>>>(qnw, knw, cosT, sinT, positions);

    // 3) V transpose -> g_vt [NKV*HD][SQ]
    vt_kernel<<<dim3(SQ/32, NKV*HD/32), 256>>>();

    // 4) fused flash attention -> g_att (half)
    flash_kernel<<<dim3(NH, 16), 256, FSMEM>>>();

    // 5) output projection (float out)
    mma_gemm<true><<<dim3(HID/128, SQ/128, 1), 256, GSMEM>>>(
        att, wo_h, out, NH*HD, NH*HD, NH*HD, HID, 1.0f);
}

// round 10
// speedup vs baseline: 1.0654x; 1.0654x over previous
#include <cuda_runtime.h>
#include <cuda_fp16.h>
#include <cstdint>

#define SQ   2048
#define HID  2560
#define NH   16
#define NKV  4
#define HD   128
#define QKV_DIM (NH*HD + 2*NKV*HD)   // 3072
#define EPS  1e-6f
#define ATT_SCALE 0.08838834764831845f  // 1/sqrt(128)
#define VOFF (NH*HD + NKV*HD)

// ---------------- scratch (device globals, no allocation) ----------------
__device__ __half g_qkv[(size_t)SQ * QKV_DIM];
__device__ __half g_att[(size_t)SQ * NH * HD];
__device__ __half g_hs_h[(size_t)SQ * HID];
__device__ __half g_wqkv_h[(size_t)QKV_DIM * HID];
__device__ __half g_wo_h[(size_t)HID * NH * HD];
__device__ __half g_vt[(size_t)NKV * HD * SQ];

__device__ __forceinline__ void mma_f16(float* d, const uint32_t* a, const uint32_t* b) {
    asm volatile(
        "mma.sync.aligned.m16n8k16.row.col.f32.f16.f16.f32 "
        "{%0,%1,%2,%3}, {%4,%5,%6,%7}, {%8,%9}, {%0,%1,%2,%3};\n"
        : "+f"(d[0]), "+f"(d[1]), "+f"(d[2]), "+f"(d[3])
        : "r"(a[0]), "r"(a[1]), "r"(a[2]), "r"(a[3]), "r"(b[0]), "r"(b[1]));
}

__device__ __forceinline__ void ldmx4(uint32_t* r, uint32_t addr) {
    asm volatile("ldmatrix.sync.aligned.m8n8.x4.shared.b16 {%0,%1,%2,%3}, [%4];"
        : "=r"(r[0]), "=r"(r[1]), "=r"(r[2]), "=r"(r[3]) : "r"(addr));
}

__device__ __forceinline__ void cpasync(uint32_t d, const void* s) {
    asm volatile("cp.async.cg.shared.global [%0], [%1], 16;\n" :: "r"(d), "l"(s));
}

__device__ __forceinline__ uint32_t h2u(__half2 h) {
    return *reinterpret_cast<uint32_t*>(&h);
}

// ---------------- fp16 tensor-core GEMM (R8 mainloop: issue AFTER compute) ----------------
template<bool OUTF32>
__global__ void __launch_bounds__(256, 2) mma_gemm(
    const __half* __restrict__ A, const __half* __restrict__ B, void* __restrict__ Cv,
    int K, int lda, int ldb, int ldc, float alpha)
{
    const int bx = blockIdx.x, by = blockIdx.y;

    extern __shared__ char smem[];
    const uint32_t sbase = (uint32_t)__cvta_generic_to_shared(smem);

    const int t    = threadIdx.x;
    const int lane = t & 31, wid = t >> 5;
    const int wm   = (wid & 1) * 64;
    const int wn   = (wid >> 1) * 32;
    const int m0   = by * 128, n0 = bx * 128;
    const int grp  = lane >> 2, tid4 = lane & 3;

    const int l8    = lane & 7;
    const int aoff8 = ((lane >> 3) & 1) * 8;
    const int ags   = (lane >> 4) & 1;
    const int boff8 = ((lane >> 4) & 1) * 8;
    const int bgs   = (lane >> 3) & 1;
    uint32_t arow[4], brow[2];
    #pragma unroll
    for (int mt = 0; mt < 4; mt++) arow[mt] = (uint32_t)(wm + mt * 16 + aoff8 + l8) * 128u;
    #pragma unroll
    for (int pr = 0; pr < 2; pr++) brow[pr] = (uint32_t)(wn + pr * 16 + boff8 + l8) * 128u;

    const int lrow = t >> 1;
    const int cb   = (t & 1) * 4;
    const int x7   = lrow & 7;
    const __half* Aptr = A + (long long)(m0 + lrow) * lda;
    const __half* Bptr = B + (long long)(n0 + lrow) * ldb;

    float acc[4][4][4];
    #pragma unroll
    for (int i = 0; i < 4; i++)
        #pragma unroll
        for (int j = 0; j < 4; j++)
            #pragma unroll
            for (int r = 0; r < 4; r++) acc[i][j][r] = 0.f;

    const int nK = K >> 6;

    auto issue = [&](int st, int k0) {
        const uint32_t ab = sbase + st * 16384u + (uint32_t)lrow * 128u;
        const uint32_t bb = sbase + 49152u + st * 16384u + (uint32_t)lrow * 128u;
        #pragma unroll
        for (int c = 0; c < 4; c++)
            cpasync(ab + (uint32_t)(((cb + c) ^ x7) << 4), Aptr + k0 + (cb + c) * 8);
        #pragma unroll
        for (int c = 0; c < 4; c++)
            cpasync(bb + (uint32_t)(((cb + c) ^ x7) << 4), Bptr + k0 + (cb + c) * 8);
    };

    issue(0, 0);
    asm volatile("cp.async.commit_group;\n");
    issue(1, 64);
    asm volatile("cp.async.commit_group;\n");

    for (int kt = 0; kt < nK; kt++) {
        asm volatile("cp.async.wait_group 1;\n");
        __syncthreads();

        const int st = kt - (kt / 3) * 3;
        const uint32_t sA = sbase + st * 16384u;
        const uint32_t sB = sbase + 49152u + st * 16384u;

        #pragma unroll
        for (int j = 0; j < 4; j++) {
            const uint32_t ga = (uint32_t)(((2 * j + ags) ^ l8) << 4);
            const uint32_t gb = (uint32_t)(((2 * j + bgs) ^ l8) << 4);
            uint32_t af[4][4], bq[2][4];
            #pragma unroll
            for (int mt = 0; mt < 4; mt++) ldmx4(af[mt], sA + arow[mt] + ga);
            ldmx4(bq[0], sB + brow[0] + gb);
            ldmx4(bq[1], sB + brow[1] + gb);
            #pragma unroll
            for (int mt = 0; mt < 4; mt++) {
                mma_f16(acc[mt][0], af[mt], &bq[0][0]);
                mma_f16(acc[mt][1], af[mt], &bq[0][2]);
                mma_f16(acc[mt][2], af[mt], &bq[1][0]);
                mma_f16(acc[mt][3], af[mt], &bq[1][2]);
            }
        }

        if (kt + 2 < nK) issue((kt + 2) - ((kt + 2) / 3) * 3, (kt + 2) << 6);
        asm volatile("cp.async.commit_group;\n");
    }

    #pragma unroll
    for (int mt = 0; mt < 4; mt++) {
        #pragma unroll
        for (int nt = 0; nt < 4; nt++) {
            const int r0 = m0 + wm + mt * 16 + grp;
            const int col = n0 + wn + nt * 8 + tid4 * 2;
            if (OUTF32) {
                float* C = (float*)Cv;
                float2 lo, hi;
                lo.x = acc[mt][nt][0] * alpha; lo.y = acc[mt][nt][1] * alpha;
                hi.x = acc[mt][nt][2] * alpha; hi.y = acc[mt][nt][3] * alpha;
                *(float2*)(C + (long long)r0 * ldc + col)       = lo;
                *(float2*)(C + (long long)(r0 + 8) * ldc + col) = hi;
            } else {
                __half* C = (__half*)Cv;
                __half2 lo = __floats2half2_rn(acc[mt][nt][0] * alpha, acc[mt][nt][1] * alpha);
                __half2 hi = __floats2half2_rn(acc[mt][nt][2] * alpha, acc[mt][nt][3] * alpha);
                *(__half2*)(C + (long long)r0 * ldc + col)       = lo;
                *(__half2*)(C + (long long)(r0 + 8) * ldc + col) = hi;
            }
        }
    }
}

// ---------------- fused flash attention, kv-tile 128 ----------------
// grid (NH, 16 q-tiles), 256 thr, 1 CTA/SM.
// SMEM: Q 32K | K 2st x 32K | Vt 2st x 32K | P 32K = 192KB.
// Chunk layout everywhere: [kc][row 128][8 granules of 16B], swizzle g^(row&7).
__global__ void __launch_bounds__(256, 1) flash_kernel()
{
    extern __shared__ char fsm[];
    const uint32_t sb = (uint32_t)__cvta_generic_to_shared(fsm);
    const uint32_t Qb = sb;
    const uint32_t Kb = sb + 32768u;
    const uint32_t Vb = sb + 98304u;
    const uint32_t Pb = sb + 163840u;

    const int h  = blockIdx.x;
    const int yy = blockIdx.y;
    const int qt = (yy < 8) ? (15 - yy) : (yy - 8);   // heavy tiles first
    const int hkv = h >> 2;

    const int t = threadIdx.x, lane = t & 31, wid = t >> 5;
    const int grp = lane >> 2, tid4 = lane & 3;
    const int l8 = lane & 7;
    const int aoff8 = ((lane >> 3) & 1) * 8;
    const int ags   = (lane >> 4) & 1;
    const int boff8 = ((lane >> 4) & 1) * 8;
    const int bgs   = (lane >> 3) & 1;

    const __half* Qg  = g_qkv + h * HD;
    const __half* Kg  = g_qkv + NH * HD + hkv * HD;
    const __half* Vtg = g_vt + (size_t)hkv * HD * SQ;

    const int r  = t >> 1;          // shared loader row (0..127)
    const int cb = (t & 1) * 4;     // granule base
    const int x7 = r & 7;

    // ---- load Q tile once ----
    {
        const __half* src = Qg + (size_t)(qt * 128 + r) * QKV_DIM;
        #pragma unroll
        for (int kc = 0; kc < 2; kc++)
            #pragma unroll
            for (int c = 0; c < 4; c++)
                cpasync(Qb + kc * 16384u + (uint32_t)r * 128u +
                        ((uint32_t)((cb + c) ^ x7) << 4),
                        src + kc * 64 + (cb + c) * 8);
    }

    const int T = qt + 1;   // 128-wide kv tiles

    auto issueKV = [&](int st, int kv0) {
        // K: row = kv, 2 d-chunks of 64
        const uint32_t Ks = Kb + (uint32_t)st * 32768u;
        const __half* ksrc = Kg + (size_t)(kv0 + r) * QKV_DIM;
        #pragma unroll
        for (int kc = 0; kc < 2; kc++)
            #pragma unroll
            for (int c = 0; c < 4; c++)
                cpasync(Ks + kc * 16384u + (uint32_t)r * 128u +
                        ((uint32_t)((cb + c) ^ x7) << 4),
                        ksrc + kc * 64 + (cb + c) * 8);
        // V: row = d, 2 kv-chunks of 64
        const uint32_t Vs = Vb + (uint32_t)st * 32768u;
        const __half* vsrc = Vtg + (size_t)r * SQ + kv0;
        #pragma unroll
        for (int kc = 0; kc < 2; kc++)
            #pragma unroll
            for (int c = 0; c < 4; c++)
                cpasync(Vs + kc * 16384u + (uint32_t)r * 128u +
                        ((uint32_t)((cb + c) ^ x7) << 4),
                        vsrc + kc * 64 + (cb + c) * 8);
    };
    issueKV(0, 0);
    asm volatile("cp.async.commit_group;\n");

    const uint32_t aQrow = (uint32_t)(wid * 16 + aoff8 + l8) * 128u;
    uint32_t bRow[8];
    #pragma unroll
    for (int pr = 0; pr < 8; pr++) bRow[pr] = (uint32_t)(pr * 16 + boff8 + l8) * 128u;

    float m0 = -1e30f, m1 = -1e30f, l0 = 0.f, l1 = 0.f;
    float O[16][4];
    #pragma unroll
    for (int i = 0; i < 16; i++)
        #pragma unroll
        for (int e = 0; e < 4; e++) O[i][e] = 0.f;

    const int q0 = qt * 128 + wid * 16 + grp;

    for (int tl = 0; tl < T; tl++) {
        asm volatile("cp.async.wait_group 0;\n");
        __syncthreads();
        if (tl + 1 < T) issueKV((tl + 1) & 1, (tl + 1) * 128);
        asm volatile("cp.async.commit_group;\n");

        const uint32_t Ks = Kb + (uint32_t)(tl & 1) * 32768u;
        const uint32_t Vs = Vb + (uint32_t)(tl & 1) * 32768u;
        const int kv0 = tl * 128;

        // ---- S = Q K^T (16q x 128kv, K=HD=128 -> 8 k16-steps) ----
        float s[16][4];
        #pragma unroll
        for (int i = 0; i < 16; i++)
            #pragma unroll
            for (int e = 0; e < 4; e++) s[i][e] = 0.f;

        #pragma unroll
        for (int j = 0; j < 8; j++) {
            const int kc = j >> 2, jj = j & 3;
            const uint32_t gA = (uint32_t)(((2 * jj + ags) ^ l8) << 4);
            const uint32_t gB = (uint32_t)(((2 * jj + bgs) ^ l8) << 4);
            uint32_t af[4], bq[8][4];
            ldmx4(af, Qb + kc * 16384u + aQrow + gA);
            #pragma unroll
            for (int pr = 0; pr < 8; pr++)
                ldmx4(bq[pr], Ks + kc * 16384u + bRow[pr] + gB);
            #pragma unroll
            for (int nt = 0; nt < 16; nt++)
                mma_f16(s[nt], af, &bq[nt >> 1][(nt & 1) * 2]);
        }

        // ---- scale + causal mask + online softmax (fp32) ----
        const bool msk = (tl == qt);   // only the diagonal tile needs masking
        float rm0 = -1e30f, rm1 = -1e30f;
        #pragma unroll
        for (int nt = 0; nt < 16; nt++) {
            const int c0 = kv0 + nt * 8 + 2 * tid4;
            float v0 = s[nt][0] * ATT_SCALE, v1 = s[nt][1] * ATT_SCALE;
            float v2 = s[nt][2] * ATT_SCALE, v3 = s[nt][3] * ATT_SCALE;
            if (msk) {
                if (c0     > q0)     v0 = -1e30f;
                if (c0 + 1 > q0)     v1 = -1e30f;
                if (c0     > q0 + 8) v2 = -1e30f;
                if (c0 + 1 > q0 + 8) v3 = -1e30f;
            }
            s[nt][0] = v0; s[nt][1] = v1; s[nt][2] = v2; s[nt][3] = v3;
            rm0 = fmaxf(rm0, fmaxf(v0, v1));
            rm1 = fmaxf(rm1, fmaxf(v2, v3));
        }
        rm0 = fmaxf(rm0, __shfl_xor_sync(0xffffffffu, rm0, 1));
        rm0 = fmaxf(rm0, __shfl_xor_sync(0xffffffffu, rm0, 2));
        rm1 = fmaxf(rm1, __shfl_xor_sync(0xffffffffu, rm1, 1));
        rm1 = fmaxf(rm1, __shfl_xor_sync(0xffffffffu, rm1, 2));

        const float mn0 = fmaxf(m0, rm0), mn1 = fmaxf(m1, rm1);
        const float sc0 = __expf(m0 - mn0), sc1 = __expf(m1 - mn1);
        m0 = mn0; m1 = mn1;

        float sum0 = 0.f, sum1 = 0.f;
        #pragma unroll
        for (int nt = 0; nt < 16; nt++) {
            s[nt][0] = __expf(s[nt][0] - m0);
            s[nt][1] = __expf(s[nt][1] - m0);
            s[nt][2] = __expf(s[nt][2] - m1);
            s[nt][3] = __expf(s[nt][3] - m1);
            sum0 += s[nt][0] + s[nt][1];
            sum1 += s[nt][2] + s[nt][3];
        }
        sum0 += __shfl_xor_sync(0xffffffffu, sum0, 1);
        sum0 += __shfl_xor_sync(0xffffffffu, sum0, 2);
        sum1 += __shfl_xor_sync(0xffffffffu, sum1, 1);
        sum1 += __shfl_xor_sync(0xffffffffu, sum1, 2);
        l0 = l0 * sc0 + sum0;
        l1 = l1 * sc1 + sum1;

        #pragma unroll
        for (int nt = 0; nt < 16; nt++) {
            O[nt][0] *= sc0; O[nt][1] *= sc0;
            O[nt][2] *= sc1; O[nt][3] *= sc1;
        }

        // ---- write P (fp16) to SMEM, chunked swizzled layout ----
        {
            const int r0w = wid * 16 + grp, r1w = r0w + 8;
            #pragma unroll
            for (int nt = 0; nt < 16; nt++) {
                const int kc = nt >> 3, gg = nt & 7;
                const uint32_t a0 = Pb + kc * 16384u + (uint32_t)r0w * 128u +
                                    ((uint32_t)(gg ^ (r0w & 7)) << 4) + tid4 * 4;
                const uint32_t a1 = Pb + kc * 16384u + (uint32_t)r1w * 128u +
                                    ((uint32_t)(gg ^ (r1w & 7)) << 4) + tid4 * 4;
                asm volatile("st.shared.b32 [%0], %1;"
                             :: "r"(a0), "r"(h2u(__floats2half2_rn(s[nt][0], s[nt][1]))));
                asm volatile("st.shared.b32 [%0], %1;"
                             :: "r"(a1), "r"(h2u(__floats2half2_rn(s[nt][2], s[nt][3]))));
            }
        }
        __syncthreads();

        // ---- O += P @ V (16q x 128d, K=128 kv -> 8 k16-steps) ----
        #pragma unroll
        for (int j = 0; j < 8; j++) {
            const int kc = j >> 2, jj = j & 3;
            const uint32_t gA = (uint32_t)(((2 * jj + ags) ^ l8) << 4);
            const uint32_t gB = (uint32_t)(((2 * jj + bgs) ^ l8) << 4);
            uint32_t af[4], bq[8][4];
            ldmx4(af, Pb + kc * 16384u + aQrow + gA);
            #pragma unroll
            for (int pr = 0; pr < 8; pr++)
                ldmx4(bq[pr], Vs + kc * 16384u + bRow[pr] + gB);
            #pragma unroll
            for (int nt = 0; nt < 16; nt++)
                mma_f16(O[nt], af, &bq[nt >> 1][(nt & 1) * 2]);
        }
    }

    // ---- epilogue ----
    const float inv0 = 1.f / l0, inv1 = 1.f / l1;
    const int row0 = qt * 128 + wid * 16 + grp;
    __half* o0 = g_att + (size_t)row0 * (NH * HD) + h * HD;
    __half* o1 = o0 + (size_t)8 * (NH * HD);
    #pragma unroll
    for (int nt = 0; nt < 16; nt++) {
        const int col = nt * 8 + 2 * tid4;
        *(__half2*)(o0 + col) = __floats2half2_rn(O[nt][0] * inv0, O[nt][1] * inv0);
        *(__half2*)(o1 + col) = __floats2half2_rn(O[nt][2] * inv1, O[nt][3] * inv1);
    }
}

// ---------------- fp32 -> fp16 convert ----------------
__global__ void __launch_bounds__(256) cvt_half(const float* __restrict__ src,
                                               __half* __restrict__ dst, int n4)
{
    int i = blockIdx.x * 256 + threadIdx.x;
    if (i < n4) {
        float4 v = ((const float4*)src)[i];
        uint2 u;
        u.x = h2u(__floats2half2_rn(v.x, v.y));
        u.y = h2u(__floats2half2_rn(v.z, v.w));
        ((uint2*)dst)[i] = u;
    }
}

// ---------------- V transpose (half) ----------------
__global__ void __launch_bounds__(256) vt_kernel()
{
    __shared__ __half tile[32][40];
    const int s0 = blockIdx.x * 32, d0 = blockIdx.y * 32;
    const int tx = threadIdx.x & 31, ty = threadIdx.x >> 5;
    #pragma unroll
    for (int r = ty; r < 32; r += 8)
        tile[r][tx] = g_qkv[(long long)(s0 + r) * QKV_DIM + VOFF + d0 + tx];
    __syncthreads();
    #pragma unroll
    for (int r = ty; r < 32; r += 8)
        g_vt[(long long)(d0 + r) * SQ + s0 + tx] = tile[tx][r];
}

// ---------------- fused RMSNorm + RoPE ----------------
__global__ void __launch_bounds__(128) norm_rope_kernel(
    const float* __restrict__ qw, const float* __restrict__ kw,
    const float* __restrict__ cosT, const float* __restrict__ sinT,
    const int* __restrict__ positions)
{
    const int tok = blockIdx.x;
    const int hh  = blockIdx.y;
    const int d   = threadIdx.x;

    __half* ptr;
    const float* w;
    if (hh < NH) { ptr = g_qkv + (long long)tok * QKV_DIM + hh * HD;            w = qw; }
    else         { ptr = g_qkv + (long long)tok * QKV_DIM + NH*HD + (hh-NH)*HD; w = kw; }

    __shared__ float x[HD];
    __shared__ float red[4];

    float v = __half2float(ptr[d]);
    float ss = v * v;
    #pragma unroll
    for (int o = 16; o > 0; o >>= 1) ss += __shfl_xor_sync(0xffffffffu, ss, o);
    if ((d & 31) == 0) red[d >> 5] = ss;
    __syncthreads();
    float tot = red[0] + red[1] + red[2] + red[3];
    float r = rsqrtf(tot * (1.0f / HD) + EPS);
    x[d] = v * r * w[d];
    __syncthreads();

    const int pos = positions[tok];
    const int p = d >> 1;
    const float c = cosT[pos * (HD/2) + p];
    const float s = sinT[pos * (HD/2) + p];
    float out;
    if ((d & 1) == 0) out = x[d] * c - x[d + 1] * s;
    else              out = x[d - 1] * s + x[d] * c;
    ptr[d] = __float2half_rn(out);
}

// ---------------- launch ----------------
extern "C" void kernel_launch(void* const* d_in, const int* in_sizes, int n_in,
                              void* d_out, int out_size)
{
    const float* hs     = (const float*)d_in[0];
    const float* w_qkv  = (const float*)d_in[1];
    const float* w_o    = (const float*)d_in[2];
    const float* qnw    = (const float*)d_in[3];
    const float* knw    = (const float*)d_in[4];
    const float* cosT   = (const float*)d_in[5];
    const float* sinT   = (const float*)d_in[6];
    const int* positions = (const int*)d_in[9];
    float* out = (float*)d_out;

    __half *qkv, *att, *hs_h, *wqkv_h, *wo_h;
    cudaGetSymbolAddress((void**)&qkv,    g_qkv);
    cudaGetSymbolAddress((void**)&att,    g_att);
    cudaGetSymbolAddress((void**)&hs_h,   g_hs_h);
    cudaGetSymbolAddress((void**)&wqkv_h, g_wqkv_h);
    cudaGetSymbolAddress((void**)&wo_h,   g_wo_h);

    const int GSMEM = 3 * 2 * 16384;   // 96 KB
    const int FSMEM = 196608;          // 192 KB
    cudaFuncSetAttribute(mma_gemm<false>, cudaFuncAttributeMaxDynamicSharedMemorySize, GSMEM);
    cudaFuncSetAttribute(mma_gemm<true >, cudaFuncAttributeMaxDynamicSharedMemorySize, GSMEM);
    cudaFuncSetAttribute(flash_kernel,    cudaFuncAttributeMaxDynamicSharedMemorySize, FSMEM);

    // 0) convert operands to fp16
    cvt_half<<<(SQ*HID/4 + 255)/256, 256>>>(hs, hs_h, SQ*HID/4);
    cvt_half<<<(QKV_DIM*HID/4 + 255)/256, 256>>>(w_qkv, wqkv_h, QKV_DIM*HID/4);
    cvt_half<<<(HID*NH*HD/4 + 255)/256, 256>>>(w_o, wo_h, HID*NH*HD/4);

    // 1) QKV projection (half out)
    mma_gemm<false><<<dim3(QKV_DIM/128, SQ/128, 1), 256, GSMEM>>>(
        hs_h, wqkv_h, qkv, HID, HID, HID, QKV_DIM, 1.0f);

    // 2) RMSNorm + RoPE in-place on q,k
    norm_rope_kernel<<<dim3(SQ, NH + NKV), 128>>>(qnw, knw, cosT, sinT, positions);

    // 3) V transpose -> g_vt [NKV*HD][SQ]
    vt_kernel<<<dim3(SQ/32, NKV*HD/32), 256>>>();

    // 4) fused flash attention -> g_att (half), kv-tile 128
    flash_kernel<<<dim3(NH, 16), 256, FSMEM>>>();

    // 5) output projection (float out)
    mma_gemm<true><<<dim3(HID/128, SQ/128, 1), 256, GSMEM>>>(
        att, wo_h, out, NH*HD, NH*HD, NH*HD, HID, 1.0f);
}

// round 11
// speedup vs baseline: 1.1425x; 1.0724x over previous
#include <cuda_runtime.h>
#include <cuda_fp16.h>
#include <cstdint>

#define SQ   2048
#define HID  2560
#define NH   16
#define NKV  4
#define HD   128
#define QKV_DIM (NH*HD + 2*NKV*HD)   // 3072
#define EPS  1e-6f
#define ATT_SCALE 0.08838834764831845f  // 1/sqrt(128)
#define VOFF (NH*HD + NKV*HD)

// ---------------- scratch (device globals, no allocation) ----------------
__device__ __half g_qkv[(size_t)SQ * QKV_DIM];
__device__ __half g_att[(size_t)SQ * NH * HD];
__device__ __half g_hs_h[(size_t)SQ * HID];
__device__ __half g_wqkv_h[(size_t)QKV_DIM * HID];
__device__ __half g_wo_h[(size_t)HID * NH * HD];
__device__ __half g_vt[(size_t)NKV * HD * SQ];

__device__ __forceinline__ void mma_f16(float* d, const uint32_t* a, const uint32_t* b) {
    asm volatile(
        "mma.sync.aligned.m16n8k16.row.col.f32.f16.f16.f32 "
        "{%0,%1,%2,%3}, {%4,%5,%6,%7}, {%8,%9}, {%0,%1,%2,%3};\n"
        : "+f"(d[0]), "+f"(d[1]), "+f"(d[2]), "+f"(d[3])
        : "r"(a[0]), "r"(a[1]), "r"(a[2]), "r"(a[3]), "r"(b[0]), "r"(b[1]));
}

__device__ __forceinline__ void ldmx4(uint32_t* r, uint32_t addr) {
    asm volatile("ldmatrix.sync.aligned.m8n8.x4.shared.b16 {%0,%1,%2,%3}, [%4];"
        : "=r"(r[0]), "=r"(r[1]), "=r"(r[2]), "=r"(r[3]) : "r"(addr));
}

__device__ __forceinline__ void cpasync(uint32_t d, const void* s) {
    asm volatile("cp.async.cg.shared.global [%0], [%1], 16;\n" :: "r"(d), "l"(s));
}

__device__ __forceinline__ uint32_t h2u(__half2 h) {
    return *reinterpret_cast<uint32_t*>(&h);
}

// ================= GEMM core macro-structure (shared by both GEMM kernels) ==========
// 128x128 CTA tile, 256 thr (8 warps, 2Mx4N of 64x32), K chunks of 64,
// 3-stage cp.async (issue AFTER compute), ldmatrix fragments, m16n8k16, fp32 accum.

// ---------------- QKV GEMM with fused RMSNorm + RoPE epilogue ----------------
// C tile (by: 128 tokens) x (bx: one head of 128 dims).
// bx<16: q head (norm+rope), 16..19: k head (norm+rope), 20..23: v head (plain).
__global__ void __launch_bounds__(256, 2) qkv_gemm(
    const __half* __restrict__ A, const __half* __restrict__ B, __half* __restrict__ C,
    const float* __restrict__ qnw, const float* __restrict__ knw,
    const float* __restrict__ cosT, const float* __restrict__ sinT,
    const int* __restrict__ positions)
{
    const int bx = blockIdx.x, by = blockIdx.y;
    const int K = HID, lda = HID, ldb = HID, ldc = QKV_DIM;

    extern __shared__ char smem[];
    const uint32_t sbase = (uint32_t)__cvta_generic_to_shared(smem);

    const int t    = threadIdx.x;
    const int lane = t & 31, wid = t >> 5;
    const int wm   = (wid & 1) * 64;
    const int wn   = (wid >> 1) * 32;
    const int m0   = by * 128, n0 = bx * 128;
    const int grp  = lane >> 2, tid4 = lane & 3;

    const int l8    = lane & 7;
    const int aoff8 = ((lane >> 3) & 1) * 8;
    const int ags   = (lane >> 4) & 1;
    const int boff8 = ((lane >> 4) & 1) * 8;
    const int bgs   = (lane >> 3) & 1;
    uint32_t arow[4], brow[2];
    #pragma unroll
    for (int mt = 0; mt < 4; mt++) arow[mt] = (uint32_t)(wm + mt * 16 + aoff8 + l8) * 128u;
    #pragma unroll
    for (int pr = 0; pr < 2; pr++) brow[pr] = (uint32_t)(wn + pr * 16 + boff8 + l8) * 128u;

    const int lrow = t >> 1;
    const int cb   = (t & 1) * 4;
    const int x7   = lrow & 7;
    const __half* Aptr = A + (long long)(m0 + lrow) * lda;
    const __half* Bptr = B + (long long)(n0 + lrow) * ldb;

    float acc[4][4][4];
    #pragma unroll
    for (int i = 0; i < 4; i++)
        #pragma unroll
        for (int j = 0; j < 4; j++)
            #pragma unroll
            for (int r = 0; r < 4; r++) acc[i][j][r] = 0.f;

    const int nK = K >> 6;

    auto issue = [&](int st, int k0) {
        const uint32_t ab = sbase + st * 16384u + (uint32_t)lrow * 128u;
        const uint32_t bb = sbase + 49152u + st * 16384u + (uint32_t)lrow * 128u;
        #pragma unroll
        for (int c = 0; c < 4; c++)
            cpasync(ab + (uint32_t)(((cb + c) ^ x7) << 4), Aptr + k0 + (cb + c) * 8);
        #pragma unroll
        for (int c = 0; c < 4; c++)
            cpasync(bb + (uint32_t)(((cb + c) ^ x7) << 4), Bptr + k0 + (cb + c) * 8);
    };

    issue(0, 0);
    asm volatile("cp.async.commit_group;\n");
    issue(1, 64);
    asm volatile("cp.async.commit_group;\n");

    for (int kt = 0; kt < nK; kt++) {
        asm volatile("cp.async.wait_group 1;\n");
        __syncthreads();

        const int st = kt - (kt / 3) * 3;
        const uint32_t sA = sbase + st * 16384u;
        const uint32_t sB = sbase + 49152u + st * 16384u;

        #pragma unroll
        for (int j = 0; j < 4; j++) {
            const uint32_t ga = (uint32_t)(((2 * j + ags) ^ l8) << 4);
            const uint32_t gb = (uint32_t)(((2 * j + bgs) ^ l8) << 4);
            uint32_t af[4][4], bq[2][4];
            #pragma unroll
            for (int mt = 0; mt < 4; mt++) ldmx4(af[mt], sA + arow[mt] + ga);
            ldmx4(bq[0], sB + brow[0] + gb);
            ldmx4(bq[1], sB + brow[1] + gb);
            #pragma unroll
            for (int mt = 0; mt < 4; mt++) {
                mma_f16(acc[mt][0], af[mt], &bq[0][0]);
                mma_f16(acc[mt][1], af[mt], &bq[0][2]);
                mma_f16(acc[mt][2], af[mt], &bq[1][0]);
                mma_f16(acc[mt][3], af[mt], &bq[1][2]);
            }
        }

        if (kt + 2 < nK) issue((kt + 2) - ((kt + 2) / 3) * 3, (kt + 2) << 6);
        asm volatile("cp.async.commit_group;\n");
    }

    // ================== fused epilogue ==================
    const bool is_q = (bx < NH);
    const bool is_k = (bx >= NH) && (bx < NH + NKV);

    if (is_q || is_k) {
        const float* w = is_q ? qnw : knw;
        float* red = (float*)smem;   // [4 N-warps][128 rows] = 2KB

        __syncthreads();   // mainloop SMEM reads done before reuse as `red`

        const int nw = wid >> 1;
        float rn0[4], rn1[4];

        // partial sum of squares per (row, N-warp)
        #pragma unroll
        for (int mt = 0; mt < 4; mt++) {
            float p0 = 0.f, p1 = 0.f;
            #pragma unroll
            for (int nt = 0; nt < 4; nt++) {
                p0 += acc[mt][nt][0] * acc[mt][nt][0] + acc[mt][nt][1] * acc[mt][nt][1];
                p1 += acc[mt][nt][2] * acc[mt][nt][2] + acc[mt][nt][3] * acc[mt][nt][3];
            }
            p0 += __shfl_xor_sync(0xffffffffu, p0, 1);
            p0 += __shfl_xor_sync(0xffffffffu, p0, 2);
            p1 += __shfl_xor_sync(0xffffffffu, p1, 1);
            p1 += __shfl_xor_sync(0xffffffffu, p1, 2);
            if (tid4 == 0) {
                red[nw * 128 + wm + mt * 16 + grp]     = p0;
                red[nw * 128 + wm + mt * 16 + grp + 8] = p1;
            }
        }
        __syncthreads();

        #pragma unroll
        for (int mt = 0; mt < 4; mt++) {
            const int r0 = wm + mt * 16 + grp;
            float s0 = red[r0] + red[128 + r0] + red[256 + r0] + red[384 + r0];
            float s1 = red[r0 + 8] + red[128 + r0 + 8] + red[256 + r0 + 8] + red[384 + r0 + 8];
            rn0[mt] = rsqrtf(s0 * (1.0f / HD) + EPS);
            rn1[mt] = rsqrtf(s1 * (1.0f / HD) + EPS);
        }

        #pragma unroll
        for (int mt = 0; mt < 4; mt++) {
            const int tok0 = m0 + wm + mt * 16 + grp;
            const int tok1 = tok0 + 8;
            const int pos0 = positions[tok0];
            const int pos1 = positions[tok1];
            #pragma unroll
            for (int nt = 0; nt < 4; nt++) {
                const int col = wn + nt * 8 + tid4 * 2;
                const int p   = col >> 1;
                const float w0 = w[col], w1 = w[col + 1];
                const float c0 = cosT[pos0 * (HD/2) + p], sn0 = sinT[pos0 * (HD/2) + p];
                const float c1 = cosT[pos1 * (HD/2) + p], sn1 = sinT[pos1 * (HD/2) + p];

                float x0 = acc[mt][nt][0] * rn0[mt] * w0;
                float x1 = acc[mt][nt][1] * rn0[mt] * w1;
                float y0 = acc[mt][nt][2] * rn1[mt] * w0;
                float y1 = acc[mt][nt][3] * rn1[mt] * w1;

                __half2 lo = __floats2half2_rn(x0 * c0 - x1 * sn0, x0 * sn0 + x1 * c0);
                __half2 hi = __floats2half2_rn(y0 * c1 - y1 * sn1, y0 * sn1 + y1 * c1);
                *(__half2*)(C + (long long)tok0 * ldc + n0 + col) = lo;
                *(__half2*)(C + (long long)tok1 * ldc + n0 + col) = hi;
            }
        }
    } else {
        // v head: plain store
        #pragma unroll
        for (int mt = 0; mt < 4; mt++) {
            #pragma unroll
            for (int nt = 0; nt < 4; nt++) {
                const int r0 = m0 + wm + mt * 16 + grp;
                const int col = n0 + wn + nt * 8 + tid4 * 2;
                __half2 lo = __floats2half2_rn(acc[mt][nt][0], acc[mt][nt][1]);
                __half2 hi = __floats2half2_rn(acc[mt][nt][2], acc[mt][nt][3]);
                *(__half2*)(C + (long long)r0 * ldc + col)       = lo;
                *(__half2*)(C + (long long)(r0 + 8) * ldc + col) = hi;
            }
        }
    }
}

// ---------------- O-projection GEMM (fp32 out) ----------------
__global__ void __launch_bounds__(256, 2) mma_gemm(
    const __half* __restrict__ A, const __half* __restrict__ B, float* __restrict__ C,
    int K, int lda, int ldb, int ldc)
{
    const int bx = blockIdx.x, by = blockIdx.y;

    extern __shared__ char smem[];
    const uint32_t sbase = (uint32_t)__cvta_generic_to_shared(smem);

    const int t    = threadIdx.x;
    const int lane = t & 31, wid = t >> 5;
    const int wm   = (wid & 1) * 64;
    const int wn   = (wid >> 1) * 32;
    const int m0   = by * 128, n0 = bx * 128;
    const int grp  = lane >> 2, tid4 = lane & 3;

    const int l8    = lane & 7;
    const int aoff8 = ((lane >> 3) & 1) * 8;
    const int ags   = (lane >> 4) & 1;
    const int boff8 = ((lane >> 4) & 1) * 8;
    const int bgs   = (lane >> 3) & 1;
    uint32_t arow[4], brow[2];
    #pragma unroll
    for (int mt = 0; mt < 4; mt++) arow[mt] = (uint32_t)(wm + mt * 16 + aoff8 + l8) * 128u;
    #pragma unroll
    for (int pr = 0; pr < 2; pr++) brow[pr] = (uint32_t)(wn + pr * 16 + boff8 + l8) * 128u;

    const int lrow = t >> 1;
    const int cb   = (t & 1) * 4;
    const int x7   = lrow & 7;
    const __half* Aptr = A + (long long)(m0 + lrow) * lda;
    const __half* Bptr = B + (long long)(n0 + lrow) * ldb;

    float acc[4][4][4];
    #pragma unroll
    for (int i = 0; i < 4; i++)
        #pragma unroll
        for (int j = 0; j < 4; j++)
            #pragma unroll
            for (int r = 0; r < 4; r++) acc[i][j][r] = 0.f;

    const int nK = K >> 6;

    auto issue = [&](int st, int k0) {
        const uint32_t ab = sbase + st * 16384u + (uint32_t)lrow * 128u;
        const uint32_t bb = sbase + 49152u + st * 16384u + (uint32_t)lrow * 128u;
        #pragma unroll
        for (int c = 0; c < 4; c++)
            cpasync(ab + (uint32_t)(((cb + c) ^ x7) << 4), Aptr + k0 + (cb + c) * 8);
        #pragma unroll
        for (int c = 0; c < 4; c++)
            cpasync(bb + (uint32_t)(((cb + c) ^ x7) << 4), Bptr + k0 + (cb + c) * 8);
    };

    issue(0, 0);
    asm volatile("cp.async.commit_group;\n");
    issue(1, 64);
    asm volatile("cp.async.commit_group;\n");

    for (int kt = 0; kt < nK; kt++) {
        asm volatile("cp.async.wait_group 1;\n");
        __syncthreads();

        const int st = kt - (kt / 3) * 3;
        const uint32_t sA = sbase + st * 16384u;
        const uint32_t sB = sbase + 49152u + st * 16384u;

        #pragma unroll
        for (int j = 0; j < 4; j++) {
            const uint32_t ga = (uint32_t)(((2 * j + ags) ^ l8) << 4);
            const uint32_t gb = (uint32_t)(((2 * j + bgs) ^ l8) << 4);
            uint32_t af[4][4], bq[2][4];
            #pragma unroll
            for (int mt = 0; mt < 4; mt++) ldmx4(af[mt], sA + arow[mt] + ga);
            ldmx4(bq[0], sB + brow[0] + gb);
            ldmx4(bq[1], sB + brow[1] + gb);
            #pragma unroll
            for (int mt = 0; mt < 4; mt++) {
                mma_f16(acc[mt][0], af[mt], &bq[0][0]);
                mma_f16(acc[mt][1], af[mt], &bq[0][2]);
                mma_f16(acc[mt][2], af[mt], &bq[1][0]);
                mma_f16(acc[mt][3], af[mt], &bq[1][2]);
            }
        }

        if (kt + 2 < nK) issue((kt + 2) - ((kt + 2) / 3) * 3, (kt + 2) << 6);
        asm volatile("cp.async.commit_group;\n");
    }

    #pragma unroll
    for (int mt = 0; mt < 4; mt++) {
        #pragma unroll
        for (int nt = 0; nt < 4; nt++) {
            const int r0 = m0 + wm + mt * 16 + grp;
            const int col = n0 + wn + nt * 8 + tid4 * 2;
            float2 lo, hi;
            lo.x = acc[mt][nt][0]; lo.y = acc[mt][nt][1];
            hi.x = acc[mt][nt][2]; hi.y = acc[mt][nt][3];
            *(float2*)(C + (long long)r0 * ldc + col)       = lo;
            *(float2*)(C + (long long)(r0 + 8) * ldc + col) = hi;
        }
    }
}

// ---------------- fused flash attention, kv-tile 128, Q in registers ----------------
// grid (NH, 16 q-tiles), 256 thr, 1 CTA/SM.
// SMEM: Q 32K | K 2st x 32K | Vt 2st x 32K | P 32K = 192KB.
__global__ void __launch_bounds__(256, 1) flash_kernel()
{
    extern __shared__ char fsm[];
    const uint32_t sb = (uint32_t)__cvta_generic_to_shared(fsm);
    const uint32_t Qb = sb;
    const uint32_t Kb = sb + 32768u;
    const uint32_t Vb = sb + 98304u;
    const uint32_t Pb = sb + 163840u;

    const int h  = blockIdx.x;
    const int yy = blockIdx.y;
    const int qt = (yy < 8) ? (15 - yy) : (yy - 8);   // heavy tiles first
    const int hkv = h >> 2;

    const int t = threadIdx.x, lane = t & 31, wid = t >> 5;
    const int grp = lane >> 2, tid4 = lane & 3;
    const int l8 = lane & 7;
    const int aoff8 = ((lane >> 3) & 1) * 8;
    const int ags   = (lane >> 4) & 1;
    const int boff8 = ((lane >> 4) & 1) * 8;
    const int bgs   = (lane >> 3) & 1;

    const __half* Qg  = g_qkv + h * HD;
    const __half* Kg  = g_qkv + NH * HD + hkv * HD;
    const __half* Vtg = g_vt + (size_t)hkv * HD * SQ;

    const int r  = t >> 1;
    const int cb = (t & 1) * 4;
    const int x7 = r & 7;

    // ---- load Q tile (group A) ----
    {
        const __half* src = Qg + (size_t)(qt * 128 + r) * QKV_DIM;
        #pragma unroll
        for (int kc = 0; kc < 2; kc++)
            #pragma unroll
            for (int c = 0; c < 4; c++)
                cpasync(Qb + kc * 16384u + (uint32_t)r * 128u +
                        ((uint32_t)((cb + c) ^ x7) << 4),
                        src + kc * 64 + (cb + c) * 8);
    }
    asm volatile("cp.async.commit_group;\n");

    const int T = qt + 1;

    auto issueKV = [&](int st, int kv0) {
        const uint32_t Ks = Kb + (uint32_t)st * 32768u;
        const __half* ksrc = Kg + (size_t)(kv0 + r) * QKV_DIM;
        #pragma unroll
        for (int kc = 0; kc < 2; kc++)
            #pragma unroll
            for (int c = 0; c < 4; c++)
                cpasync(Ks + kc * 16384u + (uint32_t)r * 128u +
                        ((uint32_t)((cb + c) ^ x7) << 4),
                        ksrc + kc * 64 + (cb + c) * 8);
        const uint32_t Vs = Vb + (uint32_t)st * 32768u;
        const __half* vsrc = Vtg + (size_t)r * SQ + kv0;
        #pragma unroll
        for (int kc = 0; kc < 2; kc++)
            #pragma unroll
            for (int c = 0; c < 4; c++)
                cpasync(Vs + kc * 16384u + (uint32_t)r * 128u +
                        ((uint32_t)((cb + c) ^ x7) << 4),
                        vsrc + kc * 64 + (cb + c) * 8);
    };
    issueKV(0, 0);
    asm volatile("cp.async.commit_group;\n");

    const uint32_t aQrow = (uint32_t)(wid * 16 + aoff8 + l8) * 128u;
    uint32_t bRow[8];
    #pragma unroll
    for (int pr = 0; pr < 8; pr++) bRow[pr] = (uint32_t)(pr * 16 + boff8 + l8) * 128u;

    // ---- preload Q fragments into registers (group A done) ----
    uint32_t qf[8][4];
    asm volatile("cp.async.wait_group 1;\n");
    __syncthreads();
    #pragma unroll
    for (int j = 0; j < 8; j++) {
        const int kc = j >> 2, jj = j & 3;
        const uint32_t gA = (uint32_t)(((2 * jj + ags) ^ l8) << 4);
        ldmx4(qf[j], Qb + kc * 16384u + aQrow + gA);
    }

    float m0 = -1e30f, m1 = -1e30f, l0 = 0.f, l1 = 0.f;
    float O[16][4];
    #pragma unroll
    for (int i = 0; i < 16; i++)
        #pragma unroll
        for (int e = 0; e < 4; e++) O[i][e] = 0.f;

    const int q0 = qt * 128 + wid * 16 + grp;

    for (int tl = 0; tl < T; tl++) {
        asm volatile("cp.async.wait_group 0;\n");
        __syncthreads();
        if (tl + 1 < T) issueKV((tl + 1) & 1, (tl + 1) * 128);
        asm volatile("cp.async.commit_group;\n");

        const uint32_t Ks = Kb + (uint32_t)(tl & 1) * 32768u;
        const uint32_t Vs = Vb + (uint32_t)(tl & 1) * 32768u;
        const int kv0 = tl * 128;

        // ---- S = Q K^T ----
        float s[16][4];
        #pragma unroll
        for (int i = 0; i < 16; i++)
            #pragma unroll
            for (int e = 0; e < 4; e++) s[i][e] = 0.f;

        #pragma unroll
        for (int j = 0; j < 8; j++) {
            const int kc = j >> 2, jj = j & 3;
            const uint32_t gB = (uint32_t)(((2 * jj + bgs) ^ l8) << 4);
            uint32_t bq[8][4];
            #pragma unroll
            for (int pr = 0; pr < 8; pr++)
                ldmx4(bq[pr], Ks + kc * 16384u + bRow[pr] + gB);
            #pragma unroll
            for (int nt = 0; nt < 16; nt++)
                mma_f16(s[nt], qf[j], &bq[nt >> 1][(nt & 1) * 2]);
        }

        // ---- scale + causal mask + online softmax (fp32) ----
        const bool msk = (tl == qt);
        float rm0 = -1e30f, rm1 = -1e30f;
        #pragma unroll
        for (int nt = 0; nt < 16; nt++) {
            const int c0 = kv0 + nt * 8 + 2 * tid4;
            float v0 = s[nt][0] * ATT_SCALE, v1 = s[nt][1] * ATT_SCALE;
            float v2 = s[nt][2] * ATT_SCALE, v3 = s[nt][3] * ATT_SCALE;
            if (msk) {
                if (c0     > q0)     v0 = -1e30f;
                if (c0 + 1 > q0)     v1 = -1e30f;
                if (c0     > q0 + 8) v2 = -1e30f;
                if (c0 + 1 > q0 + 8) v3 = -1e30f;
            }
            s[nt][0] = v0; s[nt][1] = v1; s[nt][2] = v2; s[nt][3] = v3;
            rm0 = fmaxf(rm0, fmaxf(v0, v1));
            rm1 = fmaxf(rm1, fmaxf(v2, v3));
        }
        rm0 = fmaxf(rm0, __shfl_xor_sync(0xffffffffu, rm0, 1));
        rm0 = fmaxf(rm0, __shfl_xor_sync(0xffffffffu, rm0, 2));
        rm1 = fmaxf(rm1, __shfl_xor_sync(0xffffffffu, rm1, 1));
        rm1 = fmaxf(rm1, __shfl_xor_sync(0xffffffffu, rm1, 2));

        const float mn0 = fmaxf(m0, rm0), mn1 = fmaxf(m1, rm1);
        const float sc0 = __expf(m0 - mn0), sc1 = __expf(m1 - mn1);
        m0 = mn0; m1 = mn1;

        float sum0 = 0.f, sum1 = 0.f;
        #pragma unroll
        for (int nt = 0; nt < 16; nt++) {
            s[nt][0] = __expf(s[nt][0] - m0);
            s[nt][1] = __expf(s[nt][1] - m0);
            s[nt][2] = __expf(s[nt][2] - m1);
            s[nt][3] = __expf(s[nt][3] - m1);
            sum0 += s[nt][0] + s[nt][1];
            sum1 += s[nt][2] + s[nt][3];
        }
        sum0 += __shfl_xor_sync(0xffffffffu, sum0, 1);
        sum0 += __shfl_xor_sync(0xffffffffu, sum0, 2);
        sum1 += __shfl_xor_sync(0xffffffffu, sum1, 1);
        sum1 += __shfl_xor_sync(0xffffffffu, sum1, 2);
        l0 = l0 * sc0 + sum0;
        l1 = l1 * sc1 + sum1;

        #pragma unroll
        for (int nt = 0; nt < 16; nt++) {
            O[nt][0] *= sc0; O[nt][1] *= sc0;
            O[nt][2] *= sc1; O[nt][3] *= sc1;
        }

        // ---- write P (fp16) to SMEM ----
        {
            const int r0w = wid * 16 + grp, r1w = r0w + 8;
            #pragma unroll
            for (int nt = 0; nt < 16; nt++) {
                const int kc = nt >> 3, gg = nt & 7;
                const uint32_t a0 = Pb + kc * 16384u + (uint32_t)r0w * 128u +
                                    ((uint32_t)(gg ^ (r0w & 7)) << 4) + tid4 * 4;
                const uint32_t a1 = Pb + kc * 16384u + (uint32_t)r1w * 128u +
                                    ((uint32_t)(gg ^ (r1w & 7)) << 4) + tid4 * 4;
                asm volatile("st.shared.b32 [%0], %1;"
                             :: "r"(a0), "r"(h2u(__floats2half2_rn(s[nt][0], s[nt][1]))));
                asm volatile("st.shared.b32 [%0], %1;"
                             :: "r"(a1), "r"(h2u(__floats2half2_rn(s[nt][2], s[nt][3]))));
            }
        }
        __syncthreads();

        // ---- O += P @ V ----
        #pragma unroll
        for (int j = 0; j < 8; j++) {
            const int kc = j >> 2, jj = j & 3;
            const uint32_t gA = (uint32_t)(((2 * jj + ags) ^ l8) << 4);
            const uint32_t gB = (uint32_t)(((2 * jj + bgs) ^ l8) << 4);
            uint32_t af[4], bq[8][4];
            ldmx4(af, Pb + kc * 16384u + aQrow + gA);
            #pragma unroll
            for (int pr = 0; pr < 8; pr++)
                ldmx4(bq[pr], Vs + kc * 16384u + bRow[pr] + gB);
            #pragma unroll
            for (int nt = 0; nt < 16; nt++)
                mma_f16(O[nt], af, &bq[nt >> 1][(nt & 1) * 2]);
        }
    }

    // ---- epilogue ----
    const float inv0 = 1.f / l0, inv1 = 1.f / l1;
    const int row0 = qt * 128 + wid * 16 + grp;
    __half* o0 = g_att + (size_t)row0 * (NH * HD) + h * HD;
    __half* o1 = o0 + (size_t)8 * (NH * HD);
    #pragma unroll
    for (int nt = 0; nt < 16; nt++) {
        const int col = nt * 8 + 2 * tid4;
        *(__half2*)(o0 + col) = __floats2half2_rn(O[nt][0] * inv0, O[nt][1] * inv0);
        *(__half2*)(o1 + col) = __floats2half2_rn(O[nt][2] * inv1, O[nt][3] * inv1);
    }
}

// ---------------- fp32 -> fp16 convert ----------------
__global__ void __launch_bounds__(256) cvt_half(const float* __restrict__ src,
                                               __half* __restrict__ dst, int n4)
{
    int i = blockIdx.x * 256 + threadIdx.x;
    if (i < n4) {
        float4 v = ((const float4*)src)[i];
        uint2 u;
        u.x = h2u(__floats2half2_rn(v.x, v.y));
        u.y = h2u(__floats2half2_rn(v.z, v.w));
        ((uint2*)dst)[i] = u;
    }
}

// ---------------- V transpose (half) ----------------
__global__ void __launch_bounds__(256) vt_kernel()
{
    __shared__ __half tile[32][40];
    const int s0 = blockIdx.x * 32, d0 = blockIdx.y * 32;
    const int tx = threadIdx.x & 31, ty = threadIdx.x >> 5;
    #pragma unroll
    for (int r = ty; r < 32; r += 8)
        tile[r][tx] = g_qkv[(long long)(s0 + r) * QKV_DIM + VOFF + d0 + tx];
    __syncthreads();
    #pragma unroll
    for (int r = ty; r < 32; r += 8)
        g_vt[(long long)(d0 + r) * SQ + s0 + tx] = tile[tx][r];
}

// ---------------- launch ----------------
extern "C" void kernel_launch(void* const* d_in, const int* in_sizes, int n_in,
                              void* d_out, int out_size)
{
    const float* hs     = (const float*)d_in[0];
    const float* w_qkv  = (const float*)d_in[1];
    const float* w_o    = (const float*)d_in[2];
    const float* qnw    = (const float*)d_in[3];
    const float* knw    = (const float*)d_in[4];
    const float* cosT   = (const float*)d_in[5];
    const float* sinT   = (const float*)d_in[6];
    const int* positions = (const int*)d_in[9];
    float* out = (float*)d_out;

    __half *qkv, *att, *hs_h, *wqkv_h, *wo_h;
    cudaGetSymbolAddress((void**)&qkv,    g_qkv);
    cudaGetSymbolAddress((void**)&att,    g_att);
    cudaGetSymbolAddress((void**)&hs_h,   g_hs_h);
    cudaGetSymbolAddress((void**)&wqkv_h, g_wqkv_h);
    cudaGetSymbolAddress((void**)&wo_h,   g_wo_h);

    const int GSMEM = 3 * 2 * 16384;   // 96 KB
    const int FSMEM = 196608;          // 192 KB
    cudaFuncSetAttribute(qkv_gemm,     cudaFuncAttributeMaxDynamicSharedMemorySize, GSMEM);
    cudaFuncSetAttribute(mma_gemm,     cudaFuncAttributeMaxDynamicSharedMemorySize, GSMEM);
    cudaFuncSetAttribute(flash_kernel, cudaFuncAttributeMaxDynamicSharedMemorySize, FSMEM);

    // 0) convert operands to fp16
    cvt_half<<<(SQ*HID/4 + 255)/256, 256>>>(hs, hs_h, SQ*HID/4);
    cvt_half<<<(QKV_DIM*HID/4 + 255)/256, 256>>>(w_qkv, wqkv_h, QKV_DIM*HID/4);
    cvt_half<<<(HID*NH*HD/4 + 255)/256, 256>>>(w_o, wo_h, HID*NH*HD/4);

    // 1) QKV projection + fused RMSNorm + RoPE
    qkv_gemm<<<dim3(QKV_DIM/128, SQ/128, 1), 256, GSMEM>>>(
        hs_h, wqkv_h, qkv, qnw, knw, cosT, sinT, positions);

    // 2) V transpose -> g_vt [NKV*HD][SQ]
    vt_kernel<<<dim3(SQ/32, NKV*HD/32), 256>>>();

    // 3) fused flash attention -> g_att (half)
    flash_kernel<<<dim3(NH, 16), 256, FSMEM>>>();

    // 4) output projection (float out)
    mma_gemm<<<dim3(HID/128, SQ/128, 1), 256, GSMEM>>>(
        att, wo_h, out, NH*HD, NH*HD, NH*HD, HID);
}

// round 12
// speedup vs baseline: 1.1718x; 1.0257x over previous
#include <cuda_runtime.h>
#include <cuda_fp16.h>
#include <cstdint>

#define SQ   2048
#define HID  2560
#define NH   16
#define NKV  4
#define HD   128
#define QKV_DIM (NH*HD + 2*NKV*HD)   // 3072
#define EPS  1e-6f
#define ATT_SCALE 0.08838834764831845f  // 1/sqrt(128)
#define LOG2E 1.4426950408889634f
#define SCL2  (ATT_SCALE * LOG2E)       // fold scale into exp2 argument
#define VOFF (NH*HD + NKV*HD)

// ---------------- scratch (device globals, no allocation) ----------------
__device__ __half g_qkv[(size_t)SQ * QKV_DIM];
__device__ __half g_att[(size_t)SQ * NH * HD];
__device__ __half g_hs_h[(size_t)SQ * HID];
__device__ __half g_wqkv_h[(size_t)QKV_DIM * HID];
__device__ __half g_wo_h[(size_t)HID * NH * HD];
__device__ __half g_vt[(size_t)NKV * HD * SQ];

__device__ __forceinline__ void mma_f16(float* d, const uint32_t* a, const uint32_t* b) {
    asm volatile(
        "mma.sync.aligned.m16n8k16.row.col.f32.f16.f16.f32 "
        "{%0,%1,%2,%3}, {%4,%5,%6,%7}, {%8,%9}, {%0,%1,%2,%3};\n"
        : "+f"(d[0]), "+f"(d[1]), "+f"(d[2]), "+f"(d[3])
        : "r"(a[0]), "r"(a[1]), "r"(a[2]), "r"(a[3]), "r"(b[0]), "r"(b[1]));
}

__device__ __forceinline__ void ldmx4(uint32_t* r, uint32_t addr) {
    asm volatile("ldmatrix.sync.aligned.m8n8.x4.shared.b16 {%0,%1,%2,%3}, [%4];"
        : "=r"(r[0]), "=r"(r[1]), "=r"(r[2]), "=r"(r[3]) : "r"(addr));
}

__device__ __forceinline__ void cpasync(uint32_t d, const void* s) {
    asm volatile("cp.async.cg.shared.global [%0], [%1], 16;\n" :: "r"(d), "l"(s));
}

__device__ __forceinline__ uint32_t h2u(__half2 h) {
    return *reinterpret_cast<uint32_t*>(&h);
}
__device__ __forceinline__ uint32_t ex2h2(uint32_t x) {
    uint32_t r;
    asm("ex2.approx.f16x2 %0, %1;" : "=r"(r) : "r"(x));
    return r;
}

// ---------------- QKV GEMM with fused RMSNorm + RoPE epilogue ----------------
__global__ void __launch_bounds__(256, 2) qkv_gemm(
    const __half* __restrict__ A, const __half* __restrict__ B, __half* __restrict__ C,
    const float* __restrict__ qnw, const float* __restrict__ knw,
    const float* __restrict__ cosT, const float* __restrict__ sinT,
    const int* __restrict__ positions)
{
    const int bx = blockIdx.x, by = blockIdx.y;
    const int K = HID, lda = HID, ldb = HID, ldc = QKV_DIM;

    extern __shared__ char smem[];
    const uint32_t sbase = (uint32_t)__cvta_generic_to_shared(smem);

    const int t    = threadIdx.x;
    const int lane = t & 31, wid = t >> 5;
    const int wm   = (wid & 1) * 64;
    const int wn   = (wid >> 1) * 32;
    const int m0   = by * 128, n0 = bx * 128;
    const int grp  = lane >> 2, tid4 = lane & 3;

    const int l8    = lane & 7;
    const int aoff8 = ((lane >> 3) & 1) * 8;
    const int ags   = (lane >> 4) & 1;
    const int boff8 = ((lane >> 4) & 1) * 8;
    const int bgs   = (lane >> 3) & 1;
    uint32_t arow[4], brow[2];
    #pragma unroll
    for (int mt = 0; mt < 4; mt++) arow[mt] = (uint32_t)(wm + mt * 16 + aoff8 + l8) * 128u;
    #pragma unroll
    for (int pr = 0; pr < 2; pr++) brow[pr] = (uint32_t)(wn + pr * 16 + boff8 + l8) * 128u;

    const int lrow = t >> 1;
    const int cb   = (t & 1) * 4;
    const int x7   = lrow & 7;
    const __half* Aptr = A + (long long)(m0 + lrow) * lda;
    const __half* Bptr = B + (long long)(n0 + lrow) * ldb;

    float acc[4][4][4];
    #pragma unroll
    for (int i = 0; i < 4; i++)
        #pragma unroll
        for (int j = 0; j < 4; j++)
            #pragma unroll
            for (int r = 0; r < 4; r++) acc[i][j][r] = 0.f;

    const int nK = K >> 6;

    auto issue = [&](int st, int k0) {
        const uint32_t ab = sbase + st * 16384u + (uint32_t)lrow * 128u;
        const uint32_t bb = sbase + 49152u + st * 16384u + (uint32_t)lrow * 128u;
        #pragma unroll
        for (int c = 0; c < 4; c++)
            cpasync(ab + (uint32_t)(((cb + c) ^ x7) << 4), Aptr + k0 + (cb + c) * 8);
        #pragma unroll
        for (int c = 0; c < 4; c++)
            cpasync(bb + (uint32_t)(((cb + c) ^ x7) << 4), Bptr + k0 + (cb + c) * 8);
    };

    issue(0, 0);
    asm volatile("cp.async.commit_group;\n");
    issue(1, 64);
    asm volatile("cp.async.commit_group;\n");

    for (int kt = 0; kt < nK; kt++) {
        asm volatile("cp.async.wait_group 1;\n");
        __syncthreads();

        const int st = kt - (kt / 3) * 3;
        const uint32_t sA = sbase + st * 16384u;
        const uint32_t sB = sbase + 49152u + st * 16384u;

        #pragma unroll
        for (int j = 0; j < 4; j++) {
            const uint32_t ga = (uint32_t)(((2 * j + ags) ^ l8) << 4);
            const uint32_t gb = (uint32_t)(((2 * j + bgs) ^ l8) << 4);
            uint32_t af[4][4], bq[2][4];
            #pragma unroll
            for (int mt = 0; mt < 4; mt++) ldmx4(af[mt], sA + arow[mt] + ga);
            ldmx4(bq[0], sB + brow[0] + gb);
            ldmx4(bq[1], sB + brow[1] + gb);
            #pragma unroll
            for (int mt = 0; mt < 4; mt++) {
                mma_f16(acc[mt][0], af[mt], &bq[0][0]);
                mma_f16(acc[mt][1], af[mt], &bq[0][2]);
                mma_f16(acc[mt][2], af[mt], &bq[1][0]);
                mma_f16(acc[mt][3], af[mt], &bq[1][2]);
            }
        }

        if (kt + 2 < nK) issue((kt + 2) - ((kt + 2) / 3) * 3, (kt + 2) << 6);
        asm volatile("cp.async.commit_group;\n");
    }

    // ---- fused epilogue ----
    const bool is_q = (bx < NH);
    const bool is_k = (bx >= NH) && (bx < NH + NKV);

    if (is_q || is_k) {
        const float* w = is_q ? qnw : knw;
        float* red = (float*)smem;
        __syncthreads();

        const int nw = wid >> 1;
        float rn0[4], rn1[4];

        #pragma unroll
        for (int mt = 0; mt < 4; mt++) {
            float p0 = 0.f, p1 = 0.f;
            #pragma unroll
            for (int nt = 0; nt < 4; nt++) {
                p0 += acc[mt][nt][0] * acc[mt][nt][0] + acc[mt][nt][1] * acc[mt][nt][1];
                p1 += acc[mt][nt][2] * acc[mt][nt][2] + acc[mt][nt][3] * acc[mt][nt][3];
            }
            p0 += __shfl_xor_sync(0xffffffffu, p0, 1);
            p0 += __shfl_xor_sync(0xffffffffu, p0, 2);
            p1 += __shfl_xor_sync(0xffffffffu, p1, 1);
            p1 += __shfl_xor_sync(0xffffffffu, p1, 2);
            if (tid4 == 0) {
                red[nw * 128 + wm + mt * 16 + grp]     = p0;
                red[nw * 128 + wm + mt * 16 + grp + 8] = p1;
            }
        }
        __syncthreads();

        #pragma unroll
        for (int mt = 0; mt < 4; mt++) {
            const int r0 = wm + mt * 16 + grp;
            float s0 = red[r0] + red[128 + r0] + red[256 + r0] + red[384 + r0];
            float s1 = red[r0 + 8] + red[128 + r0 + 8] + red[256 + r0 + 8] + red[384 + r0 + 8];
            rn0[mt] = rsqrtf(s0 * (1.0f / HD) + EPS);
            rn1[mt] = rsqrtf(s1 * (1.0f / HD) + EPS);
        }

        #pragma unroll
        for (int mt = 0; mt < 4; mt++) {
            const int tok0 = m0 + wm + mt * 16 + grp;
            const int tok1 = tok0 + 8;
            const int pos0 = positions[tok0];
            const int pos1 = positions[tok1];
            #pragma unroll
            for (int nt = 0; nt < 4; nt++) {
                const int col = wn + nt * 8 + tid4 * 2;
                const int p   = col >> 1;
                const float w0 = w[col], w1 = w[col + 1];
                const float c0 = cosT[pos0 * (HD/2) + p], sn0 = sinT[pos0 * (HD/2) + p];
                const float c1 = cosT[pos1 * (HD/2) + p], sn1 = sinT[pos1 * (HD/2) + p];

                float x0 = acc[mt][nt][0] * rn0[mt] * w0;
                float x1 = acc[mt][nt][1] * rn0[mt] * w1;
                float y0 = acc[mt][nt][2] * rn1[mt] * w0;
                float y1 = acc[mt][nt][3] * rn1[mt] * w1;

                __half2 lo = __floats2half2_rn(x0 * c0 - x1 * sn0, x0 * sn0 + x1 * c0);
                __half2 hi = __floats2half2_rn(y0 * c1 - y1 * sn1, y0 * sn1 + y1 * c1);
                *(__half2*)(C + (long long)tok0 * ldc + n0 + col) = lo;
                *(__half2*)(C + (long long)tok1 * ldc + n0 + col) = hi;
            }
        }
    } else {
        #pragma unroll
        for (int mt = 0; mt < 4; mt++) {
            #pragma unroll
            for (int nt = 0; nt < 4; nt++) {
                const int r0 = m0 + wm + mt * 16 + grp;
                const int col = n0 + wn + nt * 8 + tid4 * 2;
                __half2 lo = __floats2half2_rn(acc[mt][nt][0], acc[mt][nt][1]);
                __half2 hi = __floats2half2_rn(acc[mt][nt][2], acc[mt][nt][3]);
                *(__half2*)(C + (long long)r0 * ldc + col)       = lo;
                *(__half2*)(C + (long long)(r0 + 8) * ldc + col) = hi;
            }
        }
    }
}

// ---------------- O-projection GEMM (fp32 out) ----------------
__global__ void __launch_bounds__(256, 2) mma_gemm(
    const __half* __restrict__ A, const __half* __restrict__ B, float* __restrict__ C,
    int K, int lda, int ldb, int ldc)
{
    const int bx = blockIdx.x, by = blockIdx.y;

    extern __shared__ char smem[];
    const uint32_t sbase = (uint32_t)__cvta_generic_to_shared(smem);

    const int t    = threadIdx.x;
    const int lane = t & 31, wid = t >> 5;
    const int wm   = (wid & 1) * 64;
    const int wn   = (wid >> 1) * 32;
    const int m0   = by * 128, n0 = bx * 128;
    const int grp  = lane >> 2, tid4 = lane & 3;

    const int l8    = lane & 7;
    const int aoff8 = ((lane >> 3) & 1) * 8;
    const int ags   = (lane >> 4) & 1;
    const int boff8 = ((lane >> 4) & 1) * 8;
    const int bgs   = (lane >> 3) & 1;
    uint32_t arow[4], brow[2];
    #pragma unroll
    for (int mt = 0; mt < 4; mt++) arow[mt] = (uint32_t)(wm + mt * 16 + aoff8 + l8) * 128u;
    #pragma unroll
    for (int pr = 0; pr < 2; pr++) brow[pr] = (uint32_t)(wn + pr * 16 + boff8 + l8) * 128u;

    const int lrow = t >> 1;
    const int cb   = (t & 1) * 4;
    const int x7   = lrow & 7;
    const __half* Aptr = A + (long long)(m0 + lrow) * lda;
    const __half* Bptr = B + (long long)(n0 + lrow) * ldb;

    float acc[4][4][4];
    #pragma unroll
    for (int i = 0; i < 4; i++)
        #pragma unroll
        for (int j = 0; j < 4; j++)
            #pragma unroll
            for (int r = 0; r < 4; r++) acc[i][j][r] = 0.f;

    const int nK = K >> 6;

    auto issue = [&](int st, int k0) {
        const uint32_t ab = sbase + st * 16384u + (uint32_t)lrow * 128u;
        const uint32_t bb = sbase + 49152u + st * 16384u + (uint32_t)lrow * 128u;
        #pragma unroll
        for (int c = 0; c < 4; c++)
            cpasync(ab + (uint32_t)(((cb + c) ^ x7) << 4), Aptr + k0 + (cb + c) * 8);
        #pragma unroll
        for (int c = 0; c < 4; c++)
            cpasync(bb + (uint32_t)(((cb + c) ^ x7) << 4), Bptr + k0 + (cb + c) * 8);
    };

    issue(0, 0);
    asm volatile("cp.async.commit_group;\n");
    issue(1, 64);
    asm volatile("cp.async.commit_group;\n");

    for (int kt = 0; kt < nK; kt++) {
        asm volatile("cp.async.wait_group 1;\n");
        __syncthreads();

        const int st = kt - (kt / 3) * 3;
        const uint32_t sA = sbase + st * 16384u;
        const uint32_t sB = sbase + 49152u + st * 16384u;

        #pragma unroll
        for (int j = 0; j < 4; j++) {
            const uint32_t ga = (uint32_t)(((2 * j + ags) ^ l8) << 4);
            const uint32_t gb = (uint32_t)(((2 * j + bgs) ^ l8) << 4);
            uint32_t af[4][4], bq[2][4];
            #pragma unroll
            for (int mt = 0; mt < 4; mt++) ldmx4(af[mt], sA + arow[mt] + ga);
            ldmx4(bq[0], sB + brow[0] + gb);
            ldmx4(bq[1], sB + brow[1] + gb);
            #pragma unroll
            for (int mt = 0; mt < 4; mt++) {
                mma_f16(acc[mt][0], af[mt], &bq[0][0]);
                mma_f16(acc[mt][1], af[mt], &bq[0][2]);
                mma_f16(acc[mt][2], af[mt], &bq[1][0]);
                mma_f16(acc[mt][3], af[mt], &bq[1][2]);
            }
        }

        if (kt + 2 < nK) issue((kt + 2) - ((kt + 2) / 3) * 3, (kt + 2) << 6);
        asm volatile("cp.async.commit_group;\n");
    }

    #pragma unroll
    for (int mt = 0; mt < 4; mt++) {
        #pragma unroll
        for (int nt = 0; nt < 4; nt++) {
            const int r0 = m0 + wm + mt * 16 + grp;
            const int col = n0 + wn + nt * 8 + tid4 * 2;
            float2 lo, hi;
            lo.x = acc[mt][nt][0]; lo.y = acc[mt][nt][1];
            hi.x = acc[mt][nt][2]; hi.y = acc[mt][nt][3];
            *(float2*)(C + (long long)r0 * ldc + col)       = lo;
            *(float2*)(C + (long long)(r0 + 8) * ldc + col) = hi;
        }
    }
}

// ---------------- fused flash attention, kv-tile 128, f16x2 exp ----------------
__global__ void __launch_bounds__(256, 1) flash_kernel()
{
    extern __shared__ char fsm[];
    const uint32_t sb = (uint32_t)__cvta_generic_to_shared(fsm);
    const uint32_t Qb = sb;
    const uint32_t Kb = sb + 32768u;
    const uint32_t Vb = sb + 98304u;
    const uint32_t Pb = sb + 163840u;

    const int h  = blockIdx.x;
    const int yy = blockIdx.y;
    const int qt = (yy < 8) ? (15 - yy) : (yy - 8);
    const int hkv = h >> 2;

    const int t = threadIdx.x, lane = t & 31, wid = t >> 5;
    const int grp = lane >> 2, tid4 = lane & 3;
    const int l8 = lane & 7;
    const int aoff8 = ((lane >> 3) & 1) * 8;
    const int ags   = (lane >> 4) & 1;
    const int boff8 = ((lane >> 4) & 1) * 8;
    const int bgs   = (lane >> 3) & 1;

    const __half* Qg  = g_qkv + h * HD;
    const __half* Kg  = g_qkv + NH * HD + hkv * HD;
    const __half* Vtg = g_vt + (size_t)hkv * HD * SQ;

    const int r  = t >> 1;
    const int cb = (t & 1) * 4;
    const int x7 = r & 7;

    // ---- load Q tile ----
    {
        const __half* src = Qg + (size_t)(qt * 128 + r) * QKV_DIM;
        #pragma unroll
        for (int kc = 0; kc < 2; kc++)
            #pragma unroll
            for (int c = 0; c < 4; c++)
                cpasync(Qb + kc * 16384u + (uint32_t)r * 128u +
                        ((uint32_t)((cb + c) ^ x7) << 4),
                        src + kc * 64 + (cb + c) * 8);
    }
    asm volatile("cp.async.commit_group;\n");

    const int T = qt + 1;

    auto issueKV = [&](int st, int kv0) {
        const uint32_t Ks = Kb + (uint32_t)st * 32768u;
        const __half* ksrc = Kg + (size_t)(kv0 + r) * QKV_DIM;
        #pragma unroll
        for (int kc = 0; kc < 2; kc++)
            #pragma unroll
            for (int c = 0; c < 4; c++)
                cpasync(Ks + kc * 16384u + (uint32_t)r * 128u +
                        ((uint32_t)((cb + c) ^ x7) << 4),
                        ksrc + kc * 64 + (cb + c) * 8);
        const uint32_t Vs = Vb + (uint32_t)st * 32768u;
        const __half* vsrc = Vtg + (size_t)r * SQ + kv0;
        #pragma unroll
        for (int kc = 0; kc < 2; kc++)
            #pragma unroll
            for (int c = 0; c < 4; c++)
                cpasync(Vs + kc * 16384u + (uint32_t)r * 128u +
                        ((uint32_t)((cb + c) ^ x7) << 4),
                        vsrc + kc * 64 + (cb + c) * 8);
    };
    issueKV(0, 0);
    asm volatile("cp.async.commit_group;\n");

    const uint32_t aQrow = (uint32_t)(wid * 16 + aoff8 + l8) * 128u;
    uint32_t bRow[8];
    #pragma unroll
    for (int pr = 0; pr < 8; pr++) bRow[pr] = (uint32_t)(pr * 16 + boff8 + l8) * 128u;

    uint32_t qf[8][4];
    asm volatile("cp.async.wait_group 1;\n");
    __syncthreads();
    #pragma unroll
    for (int j = 0; j < 8; j++) {
        const int kc = j >> 2, jj = j & 3;
        const uint32_t gA = (uint32_t)(((2 * jj + ags) ^ l8) << 4);
        ldmx4(qf[j], Qb + kc * 16384u + aQrow + gA);
    }

    float m0 = -1e30f, m1 = -1e30f, l0 = 0.f, l1 = 0.f;
    float O[16][4];
    #pragma unroll
    for (int i = 0; i < 16; i++)
        #pragma unroll
        for (int e = 0; e < 4; e++) O[i][e] = 0.f;

    const int q0 = qt * 128 + wid * 16 + grp;

    for (int tl = 0; tl < T; tl++) {
        asm volatile("cp.async.wait_group 0;\n");
        __syncthreads();
        if (tl + 1 < T) issueKV((tl + 1) & 1, (tl + 1) * 128);
        asm volatile("cp.async.commit_group;\n");

        const uint32_t Ks = Kb + (uint32_t)(tl & 1) * 32768u;
        const uint32_t Vs = Vb + (uint32_t)(tl & 1) * 32768u;
        const int kv0 = tl * 128;

        // ---- S = Q K^T (raw, unscaled) ----
        float s[16][4];
        #pragma unroll
        for (int i = 0; i < 16; i++)
            #pragma unroll
            for (int e = 0; e < 4; e++) s[i][e] = 0.f;

        #pragma unroll
        for (int j = 0; j < 8; j++) {
            const int kc = j >> 2, jj = j & 3;
            const uint32_t gB = (uint32_t)(((2 * jj + bgs) ^ l8) << 4);
            uint32_t bq[8][4];
            #pragma unroll
            for (int pr = 0; pr < 8; pr++)
                ldmx4(bq[pr], Ks + kc * 16384u + bRow[pr] + gB);
            #pragma unroll
            for (int nt = 0; nt < 16; nt++)
                mma_f16(s[nt], qf[j], &bq[nt >> 1][(nt & 1) * 2]);
        }

        // ---- mask (raw) + row max (raw; scale>0 commutes with max) ----
        const bool msk = (tl == qt);
        float rm0 = -1e30f, rm1 = -1e30f;
        #pragma unroll
        for (int nt = 0; nt < 16; nt++) {
            const int c0 = kv0 + nt * 8 + 2 * tid4;
            if (msk) {
                if (c0     > q0)     s[nt][0] = -1e30f;
                if (c0 + 1 > q0)     s[nt][1] = -1e30f;
                if (c0     > q0 + 8) s[nt][2] = -1e30f;
                if (c0 + 1 > q0 + 8) s[nt][3] = -1e30f;
            }
            rm0 = fmaxf(rm0, fmaxf(s[nt][0], s[nt][1]));
            rm1 = fmaxf(rm1, fmaxf(s[nt][2], s[nt][3]));
        }
        rm0 = fmaxf(rm0, __shfl_xor_sync(0xffffffffu, rm0, 1));
        rm0 = fmaxf(rm0, __shfl_xor_sync(0xffffffffu, rm0, 2));
        rm1 = fmaxf(rm1, __shfl_xor_sync(0xffffffffu, rm1, 1));
        rm1 = fmaxf(rm1, __shfl_xor_sync(0xffffffffu, rm1, 2));

        const float mn0 = fmaxf(m0, rm0), mn1 = fmaxf(m1, rm1);
        const float sc0 = exp2f((m0 - mn0) * SCL2), sc1 = exp2f((m1 - mn1) * SCL2);
        m0 = mn0; m1 = mn1;

        // ---- exp via ex2.approx.f16x2; P stored fp16; l summed from SAME fp16 P ----
        const int r0w = wid * 16 + grp, r1w = r0w + 8;
        float sum0 = 0.f, sum1 = 0.f;
        #pragma unroll
        for (int nt = 0; nt < 16; nt++) {
            __half2 a01 = __floats2half2_rn((s[nt][0] - m0) * SCL2, (s[nt][1] - m0) * SCL2);
            __half2 a23 = __floats2half2_rn((s[nt][2] - m1) * SCL2, (s[nt][3] - m1) * SCL2);
            uint32_t p01 = ex2h2(h2u(a01));
            uint32_t p23 = ex2h2(h2u(a23));
            float2 f01 = __half22float2(*reinterpret_cast<__half2*>(&p01));
            float2 f23 = __half22float2(*reinterpret_cast<__half2*>(&p23));
            sum0 += f01.x + f01.y;
            sum1 += f23.x + f23.y;
            const int kc = nt >> 3, gg = nt & 7;
            const uint32_t a0 = Pb + kc * 16384u + (uint32_t)r0w * 128u +
                                ((uint32_t)(gg ^ (r0w & 7)) << 4) + tid4 * 4;
            const uint32_t a1 = Pb + kc * 16384u + (uint32_t)r1w * 128u +
                                ((uint32_t)(gg ^ (r1w & 7)) << 4) + tid4 * 4;
            asm volatile("st.shared.b32 [%0], %1;" :: "r"(a0), "r"(p01));
            asm volatile("st.shared.b32 [%0], %1;" :: "r"(a1), "r"(p23));
        }
        sum0 += __shfl_xor_sync(0xffffffffu, sum0, 1);
        sum0 += __shfl_xor_sync(0xffffffffu, sum0, 2);
        sum1 += __shfl_xor_sync(0xffffffffu, sum1, 1);
        sum1 += __shfl_xor_sync(0xffffffffu, sum1, 2);
        l0 = l0 * sc0 + sum0;
        l1 = l1 * sc1 + sum1;

        #pragma unroll
        for (int nt = 0; nt < 16; nt++) {
            O[nt][0] *= sc0; O[nt][1] *= sc0;
            O[nt][2] *= sc1; O[nt][3] *= sc1;
        }
        __syncthreads();

        // ---- O += P @ V ----
        #pragma unroll
        for (int j = 0; j < 8; j++) {
            const int kc = j >> 2, jj = j & 3;
            const uint32_t gA = (uint32_t)(((2 * jj + ags) ^ l8) << 4);
            const uint32_t gB = (uint32_t)(((2 * jj + bgs) ^ l8) << 4);
            uint32_t af[4], bq[8][4];
            ldmx4(af, Pb + kc * 16384u + aQrow + gA);
            #pragma unroll
            for (int pr = 0; pr < 8; pr++)
                ldmx4(bq[pr], Vs + kc * 16384u + bRow[pr] + gB);
            #pragma unroll
            for (int nt = 0; nt < 16; nt++)
                mma_f16(O[nt], af, &bq[nt >> 1][(nt & 1) * 2]);
        }
    }

    // ---- epilogue ----
    const float inv0 = 1.f / l0, inv1 = 1.f / l1;
    const int row0 = qt * 128 + wid * 16 + grp;
    __half* o0 = g_att + (size_t)row0 * (NH * HD) + h * HD;
    __half* o1 = o0 + (size_t)8 * (NH * HD);
    #pragma unroll
    for (int nt = 0; nt < 16; nt++) {
        const int col = nt * 8 + 2 * tid4;
        *(__half2*)(o0 + col) = __floats2half2_rn(O[nt][0] * inv0, O[nt][1] * inv0);
        *(__half2*)(o1 + col) = __floats2half2_rn(O[nt][2] * inv1, O[nt][3] * inv1);
    }
}

// ---------------- fp32 -> fp16 convert (all 3 operands, one launch) ----------------
__global__ void __launch_bounds__(256) cvt_all(
    const float* __restrict__ a, const float* __restrict__ b, const float* __restrict__ c,
    __half* __restrict__ da, __half* __restrict__ db, __half* __restrict__ dc,
    int na4, int nb4, int nc4)
{
    int i = blockIdx.x * 256 + threadIdx.x;
    const float* src; __half* dst;
    if (i < na4)            { src = a; dst = da; }
    else if (i < na4 + nb4) { i -= na4; src = b; dst = db; }
    else if (i < na4 + nb4 + nc4) { i -= na4 + nb4; src = c; dst = dc; }
    else return;
    float4 v = ((const float4*)src)[i];
    uint2 u;
    u.x = h2u(__floats2half2_rn(v.x, v.y));
    u.y = h2u(__floats2half2_rn(v.z, v.w));
    ((uint2*)dst)[i] = u;
}

// ---------------- V transpose (half) ----------------
__global__ void __launch_bounds__(256) vt_kernel()
{
    __shared__ __half tile[32][40];
    const int s0 = blockIdx.x * 32, d0 = blockIdx.y * 32;
    const int tx = threadIdx.x & 31, ty = threadIdx.x >> 5;
    #pragma unroll
    for (int r = ty; r < 32; r += 8)
        tile[r][tx] = g_qkv[(long long)(s0 + r) * QKV_DIM + VOFF + d0 + tx];
    __syncthreads();
    #pragma unroll
    for (int r = ty; r < 32; r += 8)
        g_vt[(long long)(d0 + r) * SQ + s0 + tx] = tile[tx][r];
}

// ---------------- launch ----------------
extern "C" void kernel_launch(void* const* d_in, const int* in_sizes, int n_in,
                              void* d_out, int out_size)
{
    const float* hs     = (const float*)d_in[0];
    const float* w_qkv  = (const float*)d_in[1];
    const float* w_o    = (const float*)d_in[2];
    const float* qnw    = (const float*)d_in[3];
    const float* knw    = (const float*)d_in[4];
    const float* cosT   = (const float*)d_in[5];
    const float* sinT   = (const float*)d_in[6];
    const int* positions = (const int*)d_in[9];
    float* out = (float*)d_out;

    __half *qkv, *att, *hs_h, *wqkv_h, *wo_h;
    cudaGetSymbolAddress((void**)&qkv,    g_qkv);
    cudaGetSymbolAddress((void**)&att,    g_att);
    cudaGetSymbolAddress((void**)&hs_h,   g_hs_h);
    cudaGetSymbolAddress((void**)&wqkv_h, g_wqkv_h);
    cudaGetSymbolAddress((void**)&wo_h,   g_wo_h);

    const int GSMEM = 3 * 2 * 16384;   // 96 KB
    const int FSMEM = 196608;          // 192 KB
    cudaFuncSetAttribute(qkv_gemm,     cudaFuncAttributeMaxDynamicSharedMemorySize, GSMEM);
    cudaFuncSetAttribute(mma_gemm,     cudaFuncAttributeMaxDynamicSharedMemorySize, GSMEM);
    cudaFuncSetAttribute(flash_kernel, cudaFuncAttributeMaxDynamicSharedMemorySize, FSMEM);

    // 0) convert all operands to fp16 in one launch
    const int na4 = SQ*HID/4, nb4 = QKV_DIM*HID/4, nc4 = HID*NH*HD/4;
    cvt_all<<<(na4 + nb4 + nc4 + 255)/256, 256>>>(
        hs, w_qkv, w_o, hs_h, wqkv_h, wo_h, na4, nb4, nc4);

    // 1) QKV projection + fused RMSNorm + RoPE
    qkv_gemm<<<dim3(QKV_DIM/128, SQ/128, 1), 256, GSMEM>>>(
        hs_h, wqkv_h, qkv, qnw, knw, cosT, sinT, positions);

    // 2) V transpose -> g_vt [NKV*HD][SQ]
    vt_kernel<<<dim3(SQ/32, NKV*HD/32), 256>>>();

    // 3) fused flash attention -> g_att (half)
    flash_kernel<<<dim3(NH, 16), 256, FSMEM>>>();

    // 4) output projection (float out)
    mma_gemm<<<dim3(HID/128, SQ/128, 1), 256, GSMEM>>>(
        att, wo_h, out, NH*HD, NH*HD, NH*HD, HID);
}

// round 13
// speedup vs baseline: 1.2055x; 1.0287x over previous
#include <cuda_runtime.h>
#include <cuda_fp16.h>
#include <cstdint>

#define SQ   2048
#define HID  2560
#define NH   16
#define NKV  4
#define HD   128
#define QKV_DIM (NH*HD + 2*NKV*HD)   // 3072
#define EPS  1e-6f
#define ATT_SCALE 0.08838834764831845f  // 1/sqrt(128)
#define LOG2E 1.4426950408889634f
#define SCL2  (ATT_SCALE * LOG2E)
#define VOFF (NH*HD + NKV*HD)

// ---------------- scratch (device globals, no allocation) ----------------
__device__ __half g_qkv[(size_t)SQ * QKV_DIM];
__device__ __half g_att[(size_t)SQ * NH * HD];
__device__ __half g_hs_h[(size_t)SQ * HID];
__device__ __half g_wqkv_h[(size_t)QKV_DIM * HID];
__device__ __half g_wo_h[(size_t)HID * NH * HD];
__device__ __half g_vt[(size_t)NKV * HD * SQ];

__device__ __forceinline__ void mma_f16(float* d, const uint32_t* a, const uint32_t* b) {
    asm volatile(
        "mma.sync.aligned.m16n8k16.row.col.f32.f16.f16.f32 "
        "{%0,%1,%2,%3}, {%4,%5,%6,%7}, {%8,%9}, {%0,%1,%2,%3};\n"
        : "+f"(d[0]), "+f"(d[1]), "+f"(d[2]), "+f"(d[3])
        : "r"(a[0]), "r"(a[1]), "r"(a[2]), "r"(a[3]), "r"(b[0]), "r"(b[1]));
}

__device__ __forceinline__ void ldmx4(uint32_t* r, uint32_t addr) {
    asm volatile("ldmatrix.sync.aligned.m8n8.x4.shared.b16 {%0,%1,%2,%3}, [%4];"
        : "=r"(r[0]), "=r"(r[1]), "=r"(r[2]), "=r"(r[3]) : "r"(addr));
}

__device__ __forceinline__ void cpasync(uint32_t d, const void* s) {
    asm volatile("cp.async.cg.shared.global [%0], [%1], 16;\n" :: "r"(d), "l"(s));
}

__device__ __forceinline__ uint32_t h2u(__half2 h) {
    return *reinterpret_cast<uint32_t*>(&h);
}
__device__ __forceinline__ uint32_t ex2h2(uint32_t x) {
    uint32_t r;
    asm("ex2.approx.f16x2 %0, %1;" : "=r"(r) : "r"(x));
    return r;
}

// ---------------- QKV GEMM, fused RMSNorm+RoPE (q,k) / transpose (v) epilogue ----------------
__global__ void __launch_bounds__(256, 2) qkv_gemm(
    const __half* __restrict__ A, const __half* __restrict__ B, __half* __restrict__ C,
    const float* __restrict__ qnw, const float* __restrict__ knw,
    const float* __restrict__ cosT, const float* __restrict__ sinT,
    const int* __restrict__ positions)
{
    const int bx = blockIdx.x, by = blockIdx.y;
    const int K = HID, lda = HID, ldb = HID, ldc = QKV_DIM;

    extern __shared__ char smem[];
    const uint32_t sbase = (uint32_t)__cvta_generic_to_shared(smem);

    const int t    = threadIdx.x;
    const int lane = t & 31, wid = t >> 5;
    const int wm   = (wid & 1) * 64;
    const int wn   = (wid >> 1) * 32;
    const int m0   = by * 128, n0 = bx * 128;
    const int grp  = lane >> 2, tid4 = lane & 3;

    const int l8    = lane & 7;
    const int aoff8 = ((lane >> 3) & 1) * 8;
    const int ags   = (lane >> 4) & 1;
    const int boff8 = ((lane >> 4) & 1) * 8;
    const int bgs   = (lane >> 3) & 1;
    uint32_t arow[4], brow[2];
    #pragma unroll
    for (int mt = 0; mt < 4; mt++) arow[mt] = (uint32_t)(wm + mt * 16 + aoff8 + l8) * 128u;
    #pragma unroll
    for (int pr = 0; pr < 2; pr++) brow[pr] = (uint32_t)(wn + pr * 16 + boff8 + l8) * 128u;

    const int lrow = t >> 1;
    const int cb   = (t & 1) * 4;
    const int x7   = lrow & 7;
    const __half* Aptr = A + (long long)(m0 + lrow) * lda;
    const __half* Bptr = B + (long long)(n0 + lrow) * ldb;

    float acc[4][4][4];
    #pragma unroll
    for (int i = 0; i < 4; i++)
        #pragma unroll
        for (int j = 0; j < 4; j++)
            #pragma unroll
            for (int r = 0; r < 4; r++) acc[i][j][r] = 0.f;

    const int nK = K >> 6;

    auto issue = [&](int st, int k0) {
        const uint32_t ab = sbase + st * 16384u + (uint32_t)lrow * 128u;
        const uint32_t bb = sbase + 49152u + st * 16384u + (uint32_t)lrow * 128u;
        #pragma unroll
        for (int c = 0; c < 4; c++)
            cpasync(ab + (uint32_t)(((cb + c) ^ x7) << 4), Aptr + k0 + (cb + c) * 8);
        #pragma unroll
        for (int c = 0; c < 4; c++)
            cpasync(bb + (uint32_t)(((cb + c) ^ x7) << 4), Bptr + k0 + (cb + c) * 8);
    };

    issue(0, 0);
    asm volatile("cp.async.commit_group;\n");
    issue(1, 64);
    asm volatile("cp.async.commit_group;\n");

    for (int kt = 0; kt < nK; kt++) {
        asm volatile("cp.async.wait_group 1;\n");
        __syncthreads();

        const int st = kt - (kt / 3) * 3;
        const uint32_t sA = sbase + st * 16384u;
        const uint32_t sB = sbase + 49152u + st * 16384u;

        #pragma unroll
        for (int j = 0; j < 4; j++) {
            const uint32_t ga = (uint32_t)(((2 * j + ags) ^ l8) << 4);
            const uint32_t gb = (uint32_t)(((2 * j + bgs) ^ l8) << 4);
            uint32_t af[4][4], bq[2][4];
            #pragma unroll
            for (int mt = 0; mt < 4; mt++) ldmx4(af[mt], sA + arow[mt] + ga);
            ldmx4(bq[0], sB + brow[0] + gb);
            ldmx4(bq[1], sB + brow[1] + gb);
            #pragma unroll
            for (int mt = 0; mt < 4; mt++) {
                mma_f16(acc[mt][0], af[mt], &bq[0][0]);
                mma_f16(acc[mt][1], af[mt], &bq[0][2]);
                mma_f16(acc[mt][2], af[mt], &bq[1][0]);
                mma_f16(acc[mt][3], af[mt], &bq[1][2]);
            }
        }

        if (kt + 2 < nK) issue((kt + 2) - ((kt + 2) / 3) * 3, (kt + 2) << 6);
        asm volatile("cp.async.commit_group;\n");
    }

    // ---- fused epilogue ----
    const bool is_q = (bx < NH);
    const bool is_k = (bx >= NH) && (bx < NH + NKV);

    if (is_q || is_k) {
        const float* w = is_q ? qnw : knw;
        float* red = (float*)smem;
        __syncthreads();

        const int nw = wid >> 1;
        float rn0[4], rn1[4];

        #pragma unroll
        for (int mt = 0; mt < 4; mt++) {
            float p0 = 0.f, p1 = 0.f;
            #pragma unroll
            for (int nt = 0; nt < 4; nt++) {
                p0 += acc[mt][nt][0] * acc[mt][nt][0] + acc[mt][nt][1] * acc[mt][nt][1];
                p1 += acc[mt][nt][2] * acc[mt][nt][2] + acc[mt][nt][3] * acc[mt][nt][3];
            }
            p0 += __shfl_xor_sync(0xffffffffu, p0, 1);
            p0 += __shfl_xor_sync(0xffffffffu, p0, 2);
            p1 += __shfl_xor_sync(0xffffffffu, p1, 1);
            p1 += __shfl_xor_sync(0xffffffffu, p1, 2);
            if (tid4 == 0) {
                red[nw * 128 + wm + mt * 16 + grp]     = p0;
                red[nw * 128 + wm + mt * 16 + grp + 8] = p1;
            }
        }
        __syncthreads();

        #pragma unroll
        for (int mt = 0; mt < 4; mt++) {
            const int r0 = wm + mt * 16 + grp;
            float s0 = red[r0] + red[128 + r0] + red[256 + r0] + red[384 + r0];
            float s1 = red[r0 + 8] + red[128 + r0 + 8] + red[256 + r0 + 8] + red[384 + r0 + 8];
            rn0[mt] = rsqrtf(s0 * (1.0f / HD) + EPS);
            rn1[mt] = rsqrtf(s1 * (1.0f / HD) + EPS);
        }

        #pragma unroll
        for (int mt = 0; mt < 4; mt++) {
            const int tok0 = m0 + wm + mt * 16 + grp;
            const int tok1 = tok0 + 8;
            const int pos0 = positions[tok0];
            const int pos1 = positions[tok1];
            #pragma unroll
            for (int nt = 0; nt < 4; nt++) {
                const int col = wn + nt * 8 + tid4 * 2;
                const int p   = col >> 1;
                const float w0 = w[col], w1 = w[col + 1];
                const float c0 = cosT[pos0 * (HD/2) + p], sn0 = sinT[pos0 * (HD/2) + p];
                const float c1 = cosT[pos1 * (HD/2) + p], sn1 = sinT[pos1 * (HD/2) + p];

                float x0 = acc[mt][nt][0] * rn0[mt] * w0;
                float x1 = acc[mt][nt][1] * rn0[mt] * w1;
                float y0 = acc[mt][nt][2] * rn1[mt] * w0;
                float y1 = acc[mt][nt][3] * rn1[mt] * w1;

                __half2 lo = __floats2half2_rn(x0 * c0 - x1 * sn0, x0 * sn0 + x1 * c0);
                __half2 hi = __floats2half2_rn(y0 * c1 - y1 * sn1, y0 * sn1 + y1 * c1);
                *(__half2*)(C + (long long)tok0 * ldc + n0 + col) = lo;
                *(__half2*)(C + (long long)tok1 * ldc + n0 + col) = hi;
            }
        }
    } else {
        // v head: transpose through SMEM, write g_vt [hkv*HD + d][tok] coalesced
        __half* tsm = (__half*)smem;   // [128 d][136 tok]
        __syncthreads();

        #pragma unroll
        for (int mt = 0; mt < 4; mt++) {
            const int tok0 = wm + mt * 16 + grp;
            const int tok1 = tok0 + 8;
            #pragma unroll
            for (int nt = 0; nt < 4; nt++) {
                const int d = wn + nt * 8 + tid4 * 2;
                tsm[(d    ) * 136 + tok0] = __float2half_rn(acc[mt][nt][0]);
                tsm[(d + 1) * 136 + tok0] = __float2half_rn(acc[mt][nt][1]);
                tsm[(d    ) * 136 + tok1] = __float2half_rn(acc[mt][nt][2]);
                tsm[(d + 1) * 136 + tok1] = __float2half_rn(acc[mt][nt][3]);
            }
        }
        __syncthreads();

        const int hkv = bx - (NH + NKV);
        #pragma unroll
        for (int i = t; i < 128 * 16; i += 256) {
            const int dr  = i >> 4;
            const int seg = i & 15;
            uint4 v = *(const uint4*)(tsm + dr * 136 + seg * 8);
            *(uint4*)(g_vt + (size_t)(hkv * HD + dr) * SQ + m0 + seg * 8) = v;
        }
    }
}

// ---------------- O-projection GEMM (fp32 out) ----------------
__global__ void __launch_bounds__(256, 2) mma_gemm(
    const __half* __restrict__ A, const __half* __restrict__ B, float* __restrict__ C,
    int K, int lda, int ldb, int ldc)
{
    const int bx = blockIdx.x, by = blockIdx.y;

    extern __shared__ char smem[];
    const uint32_t sbase = (uint32_t)__cvta_generic_to_shared(smem);

    const int t    = threadIdx.x;
    const int lane = t & 31, wid = t >> 5;
    const int wm   = (wid & 1) * 64;
    const int wn   = (wid >> 1) * 32;
    const int m0   = by * 128, n0 = bx * 128;
    const int grp  = lane >> 2, tid4 = lane & 3;

    const int l8    = lane & 7;
    const int aoff8 = ((lane >> 3) & 1) * 8;
    const int ags   = (lane >> 4) & 1;
    const int boff8 = ((lane >> 4) & 1) * 8;
    const int bgs   = (lane >> 3) & 1;
    uint32_t arow[4], brow[2];
    #pragma unroll
    for (int mt = 0; mt < 4; mt++) arow[mt] = (uint32_t)(wm + mt * 16 + aoff8 + l8) * 128u;
    #pragma unroll
    for (int pr = 0; pr < 2; pr++) brow[pr] = (uint32_t)(wn + pr * 16 + boff8 + l8) * 128u;

    const int lrow = t >> 1;
    const int cb   = (t & 1) * 4;
    const int x7   = lrow & 7;
    const __half* Aptr = A + (long long)(m0 + lrow) * lda;
    const __half* Bptr = B + (long long)(n0 + lrow) * ldb;

    float acc[4][4][4];
    #pragma unroll
    for (int i = 0; i < 4; i++)
        #pragma unroll
        for (int j = 0; j < 4; j++)
            #pragma unroll
            for (int r = 0; r < 4; r++) acc[i][j][r] = 0.f;

    const int nK = K >> 6;

    auto issue = [&](int st, int k0) {
        const uint32_t ab = sbase + st * 16384u + (uint32_t)lrow * 128u;
        const uint32_t bb = sbase + 49152u + st * 16384u + (uint32_t)lrow * 128u;
        #pragma unroll
        for (int c = 0; c < 4; c++)
            cpasync(ab + (uint32_t)(((cb + c) ^ x7) << 4), Aptr + k0 + (cb + c) * 8);
        #pragma unroll
        for (int c = 0; c < 4; c++)
            cpasync(bb + (uint32_t)(((cb + c) ^ x7) << 4), Bptr + k0 + (cb + c) * 8);
    };

    issue(0, 0);
    asm volatile("cp.async.commit_group;\n");
    issue(1, 64);
    asm volatile("cp.async.commit_group;\n");

    for (int kt = 0; kt < nK; kt++) {
        asm volatile("cp.async.wait_group 1;\n");
        __syncthreads();

        const int st = kt - (kt / 3) * 3;
        const uint32_t sA = sbase + st * 16384u;
        const uint32_t sB = sbase + 49152u + st * 16384u;

        #pragma unroll
        for (int j = 0; j < 4; j++) {
            const uint32_t ga = (uint32_t)(((2 * j + ags) ^ l8) << 4);
            const uint32_t gb = (uint32_t)(((2 * j + bgs) ^ l8) << 4);
            uint32_t af[4][4], bq[2][4];
            #pragma unroll
            for (int mt = 0; mt < 4; mt++) ldmx4(af[mt], sA + arow[mt] + ga);
            ldmx4(bq[0], sB + brow[0] + gb);
            ldmx4(bq[1], sB + brow[1] + gb);
            #pragma unroll
            for (int mt = 0; mt < 4; mt++) {
                mma_f16(acc[mt][0], af[mt], &bq[0][0]);
                mma_f16(acc[mt][1], af[mt], &bq[0][2]);
                mma_f16(acc[mt][2], af[mt], &bq[1][0]);
                mma_f16(acc[mt][3], af[mt], &bq[1][2]);
            }
        }

        if (kt + 2 < nK) issue((kt + 2) - ((kt + 2) / 3) * 3, (kt + 2) << 6);
        asm volatile("cp.async.commit_group;\n");
    }

    #pragma unroll
    for (int mt = 0; mt < 4; mt++) {
        #pragma unroll
        for (int nt = 0; nt < 4; nt++) {
            const int r0 = m0 + wm + mt * 16 + grp;
            const int col = n0 + wn + nt * 8 + tid4 * 2;
            float2 lo, hi;
            lo.x = acc[mt][nt][0]; lo.y = acc[mt][nt][1];
            hi.x = acc[mt][nt][2]; hi.y = acc[mt][nt][3];
            *(float2*)(C + (long long)r0 * ldc + col)       = lo;
            *(float2*)(C + (long long)(r0 + 8) * ldc + col) = hi;
        }
    }
}

// ---------------- fused flash attention: kv-tile 128, P kept in registers ----------------
// SMEM: Q 32K | K 2st x 32K | Vt 2st x 32K = 160KB. One barrier per tile.
__global__ void __launch_bounds__(256, 1) flash_kernel()
{
    extern __shared__ char fsm[];
    const uint32_t sb = (uint32_t)__cvta_generic_to_shared(fsm);
    const uint32_t Qb = sb;
    const uint32_t Kb = sb + 32768u;
    const uint32_t Vb = sb + 98304u;

    const int h  = blockIdx.x;
    const int yy = blockIdx.y;
    const int qt = (yy < 8) ? (15 - yy) : (yy - 8);
    const int hkv = h >> 2;

    const int t = threadIdx.x, lane = t & 31, wid = t >> 5;
    const int grp = lane >> 2, tid4 = lane & 3;
    const int l8 = lane & 7;
    const int aoff8 = ((lane >> 3) & 1) * 8;
    const int ags   = (lane >> 4) & 1;
    const int boff8 = ((lane >> 4) & 1) * 8;
    const int bgs   = (lane >> 3) & 1;

    const __half* Qg  = g_qkv + h * HD;
    const __half* Kg  = g_qkv + NH * HD + hkv * HD;
    const __half* Vtg = g_vt + (size_t)hkv * HD * SQ;

    const int r  = t >> 1;
    const int cb = (t & 1) * 4;
    const int x7 = r & 7;

    // ---- load Q tile ----
    {
        const __half* src = Qg + (size_t)(qt * 128 + r) * QKV_DIM;
        #pragma unroll
        for (int kc = 0; kc < 2; kc++)
            #pragma unroll
            for (int c = 0; c < 4; c++)
                cpasync(Qb + kc * 16384u + (uint32_t)r * 128u +
                        ((uint32_t)((cb + c) ^ x7) << 4),
                        src + kc * 64 + (cb + c) * 8);
    }
    asm volatile("cp.async.commit_group;\n");

    const int T = qt + 1;

    auto issueKV = [&](int st, int kv0) {
        const uint32_t Ks = Kb + (uint32_t)st * 32768u;
        const __half* ksrc = Kg + (size_t)(kv0 + r) * QKV_DIM;
        #pragma unroll
        for (int kc = 0; kc < 2; kc++)
            #pragma unroll
            for (int c = 0; c < 4; c++)
                cpasync(Ks + kc * 16384u + (uint32_t)r * 128u +
                        ((uint32_t)((cb + c) ^ x7) << 4),
                        ksrc + kc * 64 + (cb + c) * 8);
        const uint32_t Vs = Vb + (uint32_t)st * 32768u;
        const __half* vsrc = Vtg + (size_t)r * SQ + kv0;
        #pragma unroll
        for (int kc = 0; kc < 2; kc++)
            #pragma unroll
            for (int c = 0; c < 4; c++)
                cpasync(Vs + kc * 16384u + (uint32_t)r * 128u +
                        ((uint32_t)((cb + c) ^ x7) << 4),
                        vsrc + kc * 64 + (cb + c) * 8);
    };
    issueKV(0, 0);
    asm volatile("cp.async.commit_group;\n");

    const uint32_t aQrow = (uint32_t)(wid * 16 + aoff8 + l8) * 128u;
    uint32_t bRow[8];
    #pragma unroll
    for (int pr = 0; pr < 8; pr++) bRow[pr] = (uint32_t)(pr * 16 + boff8 + l8) * 128u;

    uint32_t qf[8][4];
    asm volatile("cp.async.wait_group 1;\n");
    __syncthreads();
    #pragma unroll
    for (int j = 0; j < 8; j++) {
        const int kc = j >> 2, jj = j & 3;
        const uint32_t gA = (uint32_t)(((2 * jj + ags) ^ l8) << 4);
        ldmx4(qf[j], Qb + kc * 16384u + aQrow + gA);
    }

    float m0 = -1e30f, m1 = -1e30f, l0 = 0.f, l1 = 0.f;
    float O[16][4];
    #pragma unroll
    for (int i = 0; i < 16; i++)
        #pragma unroll
        for (int e = 0; e < 4; e++) O[i][e] = 0.f;

    const int q0 = qt * 128 + wid * 16 + grp;

    for (int tl = 0; tl < T; tl++) {
        asm volatile("cp.async.wait_group 0;\n");
        __syncthreads();
        if (tl + 1 < T) issueKV((tl + 1) & 1, (tl + 1) * 128);
        asm volatile("cp.async.commit_group;\n");

        const uint32_t Ks = Kb + (uint32_t)(tl & 1) * 32768u;
        const uint32_t Vs = Vb + (uint32_t)(tl & 1) * 32768u;
        const int kv0 = tl * 128;

        // ---- S = Q K^T (raw) ----
        float s[16][4];
        #pragma unroll
        for (int i = 0; i < 16; i++)
            #pragma unroll
            for (int e = 0; e < 4; e++) s[i][e] = 0.f;

        #pragma unroll
        for (int j = 0; j < 8; j++) {
            const int kc = j >> 2, jj = j & 3;
            const uint32_t gB = (uint32_t)(((2 * jj + bgs) ^ l8) << 4);
            uint32_t bq[8][4];
            #pragma unroll
            for (int pr = 0; pr < 8; pr++)
                ldmx4(bq[pr], Ks + kc * 16384u + bRow[pr] + gB);
            #pragma unroll
            for (int nt = 0; nt < 16; nt++)
                mma_f16(s[nt], qf[j], &bq[nt >> 1][(nt & 1) * 2]);
        }

        // ---- mask + row max (raw; positive scale commutes with max) ----
        const bool msk = (tl == qt);
        float rm0 = -1e30f, rm1 = -1e30f;
        #pragma unroll
        for (int nt = 0; nt < 16; nt++) {
            const int c0 = kv0 + nt * 8 + 2 * tid4;
            if (msk) {
                if (c0     > q0)     s[nt][0] = -1e30f;
                if (c0 + 1 > q0)     s[nt][1] = -1e30f;
                if (c0     > q0 + 8) s[nt][2] = -1e30f;
                if (c0 + 1 > q0 + 8) s[nt][3] = -1e30f;
            }
            rm0 = fmaxf(rm0, fmaxf(s[nt][0], s[nt][1]));
            rm1 = fmaxf(rm1, fmaxf(s[nt][2], s[nt][3]));
        }
        rm0 = fmaxf(rm0, __shfl_xor_sync(0xffffffffu, rm0, 1));
        rm0 = fmaxf(rm0, __shfl_xor_sync(0xffffffffu, rm0, 2));
        rm1 = fmaxf(rm1, __shfl_xor_sync(0xffffffffu, rm1, 1));
        rm1 = fmaxf(rm1, __shfl_xor_sync(0xffffffffu, rm1, 2));

        const float mn0 = fmaxf(m0, rm0), mn1 = fmaxf(m1, rm1);
        const float sc0 = exp2f((m0 - mn0) * SCL2), sc1 = exp2f((m1 - mn1) * SCL2);
        m0 = mn0; m1 = mn1;

        // ---- exp via ex2.approx.f16x2; P stays in REGISTERS (= PV A fragments) ----
        uint32_t P01[16], P23[16];
        float sum0 = 0.f, sum1 = 0.f;
        #pragma unroll
        for (int nt = 0; nt < 16; nt++) {
            __half2 a01 = __floats2half2_rn((s[nt][0] - m0) * SCL2, (s[nt][1] - m0) * SCL2);
            __half2 a23 = __floats2half2_rn((s[nt][2] - m1) * SCL2, (s[nt][3] - m1) * SCL2);
            P01[nt] = ex2h2(h2u(a01));
            P23[nt] = ex2h2(h2u(a23));
            float2 f01 = __half22float2(*reinterpret_cast<__half2*>(&P01[nt]));
            float2 f23 = __half22float2(*reinterpret_cast<__half2*>(&P23[nt]));
            sum0 += f01.x + f01.y;
            sum1 += f23.x + f23.y;
        }
        sum0 += __shfl_xor_sync(0xffffffffu, sum0, 1);
        sum0 += __shfl_xor_sync(0xffffffffu, sum0, 2);
        sum1 += __shfl_xor_sync(0xffffffffu, sum1, 1);
        sum1 += __shfl_xor_sync(0xffffffffu, sum1, 2);
        l0 = l0 * sc0 + sum0;
        l1 = l1 * sc1 + sum1;

        #pragma unroll
        for (int nt = 0; nt < 16; nt++) {
            O[nt][0] *= sc0; O[nt][1] *= sc0;
            O[nt][2] *= sc1; O[nt][3] *= sc1;
        }

        // ---- O += P @ V (A operand straight from registers) ----
        #pragma unroll
        for (int j = 0; j < 8; j++) {
            const int kc = j >> 2, jj = j & 3;
            const uint32_t gB = (uint32_t)(((2 * jj + bgs) ^ l8) << 4);
            uint32_t af[4] = { P01[2 * j], P23[2 * j], P01[2 * j + 1], P23[2 * j + 1] };
            uint32_t bq[8][4];
            #pragma unroll
            for (int pr = 0; pr < 8; pr++)
                ldmx4(bq[pr], Vs + kc * 16384u + bRow[pr] + gB);
            #pragma unroll
            for (int nt = 0; nt < 16; nt++)
                mma_f16(O[nt], af, &bq[nt >> 1][(nt & 1) * 2]);
        }
    }

    // ---- epilogue ----
    const float inv0 = 1.f / l0, inv1 = 1.f / l1;
    const int row0 = qt * 128 + wid * 16 + grp;
    __half* o0 = g_att + (size_t)row0 * (NH * HD) + h * HD;
    __half* o1 = o0 + (size_t)8 * (NH * HD);
    #pragma unroll
    for (int nt = 0; nt < 16; nt++) {
        const int col = nt * 8 + 2 * tid4;
        *(__half2*)(o0 + col) = __floats2half2_rn(O[nt][0] * inv0, O[nt][1] * inv0);
        *(__half2*)(o1 + col) = __floats2half2_rn(O[nt][2] * inv1, O[nt][3] * inv1);
    }
}

// ---------------- fp32 -> fp16 convert (all 3 operands, one launch) ----------------
__global__ void __launch_bounds__(256) cvt_all(
    const float* __restrict__ a, const float* __restrict__ b, const float* __restrict__ c,
    __half* __restrict__ da, __half* __restrict__ db, __half* __restrict__ dc,
    int na4, int nb4, int nc4)
{
    int i = blockIdx.x * 256 + threadIdx.x;
    const float* src; __half* dst;
    if (i < na4)            { src = a; dst = da; }
    else if (i < na4 + nb4) { i -= na4; src = b; dst = db; }
    else if (i < na4 + nb4 + nc4) { i -= na4 + nb4; src = c; dst = dc; }
    else return;
    float4 v = ((const float4*)src)[i];
    uint2 u;
    u.x = h2u(__floats2half2_rn(v.x, v.y));
    u.y = h2u(__floats2half2_rn(v.z, v.w));
    ((uint2*)dst)[i] = u;
}

// ---------------- launch ----------------
extern "C" void kernel_launch(void* const* d_in, const int* in_sizes, int n_in,
                              void* d_out, int out_size)
{
    const float* hs     = (const float*)d_in[0];
    const float* w_qkv  = (const float*)d_in[1];
    const float* w_o    = (const float*)d_in[2];
    const float* qnw    = (const float*)d_in[3];
    const float* knw    = (const float*)d_in[4];
    const float* cosT   = (const float*)d_in[5];
    const float* sinT   = (const float*)d_in[6];
    const int* positions = (const int*)d_in[9];
    float* out = (float*)d_out;

    __half *qkv, *att, *hs_h, *wqkv_h, *wo_h;
    cudaGetSymbolAddress((void**)&qkv,    g_qkv);
    cudaGetSymbolAddress((void**)&att,    g_att);
    cudaGetSymbolAddress((void**)&hs_h,   g_hs_h);
    cudaGetSymbolAddress((void**)&wqkv_h, g_wqkv_h);
    cudaGetSymbolAddress((void**)&wo_h,   g_wo_h);

    const int GSMEM = 3 * 2 * 16384;   // 96 KB
    const int FSMEM = 163840;          // 160 KB
    cudaFuncSetAttribute(qkv_gemm,     cudaFuncAttributeMaxDynamicSharedMemorySize, GSMEM);
    cudaFuncSetAttribute(mma_gemm,     cudaFuncAttributeMaxDynamicSharedMemorySize, GSMEM);
    cudaFuncSetAttribute(flash_kernel, cudaFuncAttributeMaxDynamicSharedMemorySize, FSMEM);

    // 0) convert all operands to fp16 in one launch
    const int na4 = SQ*HID/4, nb4 = QKV_DIM*HID/4, nc4 = HID*NH*HD/4;
    cvt_all<<<(na4 + nb4 + nc4 + 255)/256, 256>>>(
        hs, w_qkv, w_o, hs_h, wqkv_h, wo_h, na4, nb4, nc4);

    // 1) QKV projection + fused RMSNorm+RoPE (q,k) + fused V transpose (v)
    qkv_gemm<<<dim3(QKV_DIM/128, SQ/128, 1), 256, GSMEM>>>(
        hs_h, wqkv_h, qkv, qnw, knw, cosT, sinT, positions);

    // 2) fused flash attention -> g_att (half)
    flash_kernel<<<dim3(NH, 16), 256, FSMEM>>>();

    // 3) output projection (float out)
    mma_gemm<<<dim3(HID/128, SQ/128, 1), 256, GSMEM>>>(
        att, wo_h, out, NH*HD, NH*HD, NH*HD, HID);
}

// round 14
// speedup vs baseline: 1.2243x; 1.0156x over previous
#include <cuda_runtime.h>
#include <cuda_fp16.h>
#include <cstdint>

#define SQ   2048
#define HID  2560
#define NH   16
#define NKV  4
#define HD   128
#define QKV_DIM (NH*HD + 2*NKV*HD)   // 3072
#define EPS  1e-6f
#define ATT_SCALE 0.08838834764831845f
#define LOG2E 1.4426950408889634f
#define SCL2  (ATT_SCALE * LOG2E)
#define VOFF (NH*HD + NKV*HD)

// ---------------- scratch (device globals, no allocation) ----------------
__device__ __half g_qkv[(size_t)SQ * QKV_DIM];
__device__ __half g_att[(size_t)SQ * NH * HD];
__device__ __half g_hs_h[(size_t)SQ * HID];
__device__ __half g_wqkv_h[(size_t)QKV_DIM * HID];
__device__ __half g_wo_h[(size_t)HID * NH * HD];
__device__ __half g_vt[(size_t)NKV * HD * SQ];

__device__ __forceinline__ void mma_f16(float* d, const uint32_t* a, const uint32_t* b) {
    asm volatile(
        "mma.sync.aligned.m16n8k16.row.col.f32.f16.f16.f32 "
        "{%0,%1,%2,%3}, {%4,%5,%6,%7}, {%8,%9}, {%0,%1,%2,%3};\n"
        : "+f"(d[0]), "+f"(d[1]), "+f"(d[2]), "+f"(d[3])
        : "r"(a[0]), "r"(a[1]), "r"(a[2]), "r"(a[3]), "r"(b[0]), "r"(b[1]));
}

__device__ __forceinline__ void ldmx4(uint32_t* r, uint32_t addr) {
    asm volatile("ldmatrix.sync.aligned.m8n8.x4.shared.b16 {%0,%1,%2,%3}, [%4];"
        : "=r"(r[0]), "=r"(r[1]), "=r"(r[2]), "=r"(r[3]) : "r"(addr));
}

__device__ __forceinline__ void cpasync(uint32_t d, const void* s) {
    asm volatile("cp.async.cg.shared.global [%0], [%1], 16;\n" :: "r"(d), "l"(s));
}

__device__ __forceinline__ uint32_t h2u(__half2 h) {
    return *reinterpret_cast<uint32_t*>(&h);
}
__device__ __forceinline__ uint32_t ex2h2(uint32_t x) {
    uint32_t r;
    asm("ex2.approx.f16x2 %0, %1;" : "=r"(r) : "r"(x));
    return r;
}

// ================= 64x128 GEMM engine, 3 CTAs/SM =================
// C[m,n] = sum_k A[m,k] * B[n,k] (row-major NT), fp32 accumulate.
// M-tile 64 (by), N-tile 128 (bx). 256 thr, 8 warps as 2Mx4N of 32x32.
// K chunks of 64 halves, 3-stage cp.async (issue after compute).
// SMEM: A [3][64][8x16B] @ st*8192, B [3][128][8x16B] @ 24576 + st*16384. 72KB.
// EPI: 0 = QKV (fused RMSNorm+RoPE for q/k heads, V-transpose for v heads)
//      1 = plain fp32 store (O-projection)
template<int EPI>
__global__ void __launch_bounds__(256, 3) gemm64(
    const __half* __restrict__ A, const __half* __restrict__ B, void* __restrict__ Cv,
    int K, int lda, int ldb, int ldc,
    const float* __restrict__ qnw, const float* __restrict__ knw,
    const float* __restrict__ cosT, const float* __restrict__ sinT,
    const int* __restrict__ positions)
{
    const int bx = blockIdx.x, by = blockIdx.y;

    extern __shared__ char smem[];
    const uint32_t sbase = (uint32_t)__cvta_generic_to_shared(smem);

    const int t    = threadIdx.x;
    const int lane = t & 31, wid = t >> 5;
    const int wm   = (wid & 1) * 32;
    const int wn   = (wid >> 1) * 32;
    const int m0   = by * 64, n0 = bx * 128;
    const int grp  = lane >> 2, tid4 = lane & 3;

    const int l8    = lane & 7;
    const int aoff8 = ((lane >> 3) & 1) * 8;
    const int ags   = (lane >> 4) & 1;
    const int boff8 = ((lane >> 4) & 1) * 8;
    const int bgs   = (lane >> 3) & 1;
    uint32_t arow[2], brow[2];
    #pragma unroll
    for (int mt = 0; mt < 2; mt++) arow[mt] = (uint32_t)(wm + mt * 16 + aoff8 + l8) * 128u;
    #pragma unroll
    for (int pr = 0; pr < 2; pr++) brow[pr] = (uint32_t)(wn + pr * 16 + boff8 + l8) * 128u;

    // loaders: A row t>>2, 2 granules at (t&3)*2; B row t>>1, 4 granules at (t&1)*4
    const int lrA = t >> 2, cbA = (t & 3) * 2, x7A = lrA & 7;
    const int lrB = t >> 1, cbB = (t & 1) * 4, x7B = lrB & 7;
    const __half* Aptr = A + (long long)(m0 + lrA) * lda;
    const __half* Bptr = B + (long long)(n0 + lrB) * ldb;

    float acc[2][4][4];
    #pragma unroll
    for (int i = 0; i < 2; i++)
        #pragma unroll
        for (int j = 0; j < 4; j++)
            #pragma unroll
            for (int r = 0; r < 4; r++) acc[i][j][r] = 0.f;

    const int nK = K >> 6;

    auto issue = [&](int st, int k0) {
        const uint32_t ab = sbase + st * 8192u + (uint32_t)lrA * 128u;
        #pragma unroll
        for (int c = 0; c < 2; c++)
            cpasync(ab + (uint32_t)(((cbA + c) ^ x7A) << 4), Aptr + k0 + (cbA + c) * 8);
        const uint32_t bb = sbase + 24576u + st * 16384u + (uint32_t)lrB * 128u;
        #pragma unroll
        for (int c = 0; c < 4; c++)
            cpasync(bb + (uint32_t)(((cbB + c) ^ x7B) << 4), Bptr + k0 + (cbB + c) * 8);
    };

    issue(0, 0);
    asm volatile("cp.async.commit_group;\n");
    issue(1, 64);
    asm volatile("cp.async.commit_group;\n");

    for (int kt = 0; kt < nK; kt++) {
        asm volatile("cp.async.wait_group 1;\n");
        __syncthreads();

        const int st = kt - (kt / 3) * 3;
        const uint32_t sA = sbase + st * 8192u;
        const uint32_t sB = sbase + 24576u + st * 16384u;

        #pragma unroll
        for (int j = 0; j < 4; j++) {
            const uint32_t ga = (uint32_t)(((2 * j + ags) ^ l8) << 4);
            const uint32_t gb = (uint32_t)(((2 * j + bgs) ^ l8) << 4);
            uint32_t af[2][4], bq[2][4];
            ldmx4(af[0], sA + arow[0] + ga);
            ldmx4(af[1], sA + arow[1] + ga);
            ldmx4(bq[0], sB + brow[0] + gb);
            ldmx4(bq[1], sB + brow[1] + gb);
            #pragma unroll
            for (int mt = 0; mt < 2; mt++) {
                mma_f16(acc[mt][0], af[mt], &bq[0][0]);
                mma_f16(acc[mt][1], af[mt], &bq[0][2]);
                mma_f16(acc[mt][2], af[mt], &bq[1][0]);
                mma_f16(acc[mt][3], af[mt], &bq[1][2]);
            }
        }

        if (kt + 2 < nK) issue((kt + 2) - ((kt + 2) / 3) * 3, (kt + 2) << 6);
        asm volatile("cp.async.commit_group;\n");
    }

    if (EPI == 1) {
        // ---- plain fp32 store ----
        float* C = (float*)Cv;
        #pragma unroll
        for (int mt = 0; mt < 2; mt++) {
            #pragma unroll
            for (int nt = 0; nt < 4; nt++) {
                const int r0 = m0 + wm + mt * 16 + grp;
                const int col = n0 + wn + nt * 8 + tid4 * 2;
                float2 lo, hi;
                lo.x = acc[mt][nt][0]; lo.y = acc[mt][nt][1];
                hi.x = acc[mt][nt][2]; hi.y = acc[mt][nt][3];
                *(float2*)(C + (long long)r0 * ldc + col)       = lo;
                *(float2*)(C + (long long)(r0 + 8) * ldc + col) = hi;
            }
        }
        return;
    }

    // ---- QKV fused epilogue ----
    __half* C = (__half*)Cv;
    const bool is_q = (bx < NH);
    const bool is_k = (bx >= NH) && (bx < NH + NKV);

    if (is_q || is_k) {
        const float* w = is_q ? qnw : knw;
        float* red = (float*)smem;   // [4 N-warps][64 rows] = 1KB
        __syncthreads();

        const int nw = wid >> 1;
        float rn0[2], rn1[2];

        #pragma unroll
        for (int mt = 0; mt < 2; mt++) {
            float p0 = 0.f, p1 = 0.f;
            #pragma unroll
            for (int nt = 0; nt < 4; nt++) {
                p0 += acc[mt][nt][0] * acc[mt][nt][0] + acc[mt][nt][1] * acc[mt][nt][1];
                p1 += acc[mt][nt][2] * acc[mt][nt][2] + acc[mt][nt][3] * acc[mt][nt][3];
            }
            p0 += __shfl_xor_sync(0xffffffffu, p0, 1);
            p0 += __shfl_xor_sync(0xffffffffu, p0, 2);
            p1 += __shfl_xor_sync(0xffffffffu, p1, 1);
            p1 += __shfl_xor_sync(0xffffffffu, p1, 2);
            if (tid4 == 0) {
                red[nw * 64 + wm + mt * 16 + grp]     = p0;
                red[nw * 64 + wm + mt * 16 + grp + 8] = p1;
            }
        }
        __syncthreads();

        #pragma unroll
        for (int mt = 0; mt < 2; mt++) {
            const int r0 = wm + mt * 16 + grp;
            float s0 = red[r0] + red[64 + r0] + red[128 + r0] + red[192 + r0];
            float s1 = red[r0 + 8] + red[64 + r0 + 8] + red[128 + r0 + 8] + red[192 + r0 + 8];
            rn0[mt] = rsqrtf(s0 * (1.0f / HD) + EPS);
            rn1[mt] = rsqrtf(s1 * (1.0f / HD) + EPS);
        }

        #pragma unroll
        for (int mt = 0; mt < 2; mt++) {
            const int tok0 = m0 + wm + mt * 16 + grp;
            const int tok1 = tok0 + 8;
            const int pos0 = positions[tok0];
            const int pos1 = positions[tok1];
            #pragma unroll
            for (int nt = 0; nt < 4; nt++) {
                const int col = wn + nt * 8 + tid4 * 2;
                const int p   = col >> 1;
                const float w0 = w[col], w1 = w[col + 1];
                const float c0 = cosT[pos0 * (HD/2) + p], sn0 = sinT[pos0 * (HD/2) + p];
                const float c1 = cosT[pos1 * (HD/2) + p], sn1 = sinT[pos1 * (HD/2) + p];

                float x0 = acc[mt][nt][0] * rn0[mt] * w0;
                float x1 = acc[mt][nt][1] * rn0[mt] * w1;
                float y0 = acc[mt][nt][2] * rn1[mt] * w0;
                float y1 = acc[mt][nt][3] * rn1[mt] * w1;

                __half2 lo = __floats2half2_rn(x0 * c0 - x1 * sn0, x0 * sn0 + x1 * c0);
                __half2 hi = __floats2half2_rn(y0 * c1 - y1 * sn1, y0 * sn1 + y1 * c1);
                *(__half2*)(C + (long long)tok0 * ldc + n0 + col) = lo;
                *(__half2*)(C + (long long)tok1 * ldc + n0 + col) = hi;
            }
        }
    } else {
        // v head: transpose 64 tok x 128 d through SMEM, write g_vt coalesced
        __half* tsm = (__half*)smem;   // [128 d][72 tok] halves = 18KB
        __syncthreads();

        #pragma unroll
        for (int mt = 0; mt < 2; mt++) {
            const int tok0 = wm + mt * 16 + grp;
            const int tok1 = tok0 + 8;
            #pragma unroll
            for (int nt = 0; nt < 4; nt++) {
                const int d = wn + nt * 8 + tid4 * 2;
                tsm[(d    ) * 72 + tok0] = __float2half_rn(acc[mt][nt][0]);
                tsm[(d + 1) * 72 + tok0] = __float2half_rn(acc[mt][nt][1]);
                tsm[(d    ) * 72 + tok1] = __float2half_rn(acc[mt][nt][2]);
                tsm[(d + 1) * 72 + tok1] = __float2half_rn(acc[mt][nt][3]);
            }
        }
        __syncthreads();

        const int hkv = bx - (NH + NKV);
        #pragma unroll
        for (int i = t; i < 128 * 8; i += 256) {
            const int dr  = i >> 3;
            const int seg = i & 7;
            uint4 v = *(const uint4*)(tsm + dr * 72 + seg * 8);
            *(uint4*)(g_vt + (size_t)(hkv * HD + dr) * SQ + m0 + seg * 8) = v;
        }
    }
}

// ---------------- fused flash attention: kv-tile 128, P kept in registers ----------------
__global__ void __launch_bounds__(256, 1) flash_kernel()
{
    extern __shared__ char fsm[];
    const uint32_t sb = (uint32_t)__cvta_generic_to_shared(fsm);
    const uint32_t Qb = sb;
    const uint32_t Kb = sb + 32768u;
    const uint32_t Vb = sb + 98304u;

    const int h  = blockIdx.x;
    const int yy = blockIdx.y;
    const int qt = (yy < 8) ? (15 - yy) : (yy - 8);
    const int hkv = h >> 2;

    const int t = threadIdx.x, lane = t & 31, wid = t >> 5;
    const int grp = lane >> 2, tid4 = lane & 3;
    const int l8 = lane & 7;
    const int aoff8 = ((lane >> 3) & 1) * 8;
    const int ags   = (lane >> 4) & 1;
    const int boff8 = ((lane >> 4) & 1) * 8;
    const int bgs   = (lane >> 3) & 1;

    const __half* Qg  = g_qkv + h * HD;
    const __half* Kg  = g_qkv + NH * HD + hkv * HD;
    const __half* Vtg = g_vt + (size_t)hkv * HD * SQ;

    const int r  = t >> 1;
    const int cb = (t & 1) * 4;
    const int x7 = r & 7;

    {
        const __half* src = Qg + (size_t)(qt * 128 + r) * QKV_DIM;
        #pragma unroll
        for (int kc = 0; kc < 2; kc++)
            #pragma unroll
            for (int c = 0; c < 4; c++)
                cpasync(Qb + kc * 16384u + (uint32_t)r * 128u +
                        ((uint32_t)((cb + c) ^ x7) << 4),
                        src + kc * 64 + (cb + c) * 8);
    }
    asm volatile("cp.async.commit_group;\n");

    const int T = qt + 1;

    auto issueKV = [&](int st, int kv0) {
        const uint32_t Ks = Kb + (uint32_t)st * 32768u;
        const __half* ksrc = Kg + (size_t)(kv0 + r) * QKV_DIM;
        #pragma unroll
        for (int kc = 0; kc < 2; kc++)
            #pragma unroll
            for (int c = 0; c < 4; c++)
                cpasync(Ks + kc * 16384u + (uint32_t)r * 128u +
                        ((uint32_t)((cb + c) ^ x7) << 4),
                        ksrc + kc * 64 + (cb + c) * 8);
        const uint32_t Vs = Vb + (uint32_t)st * 32768u;
        const __half* vsrc = Vtg + (size_t)r * SQ + kv0;
        #pragma unroll
        for (int kc = 0; kc < 2; kc++)
            #pragma unroll
            for (int c = 0; c < 4; c++)
                cpasync(Vs + kc * 16384u + (uint32_t)r * 128u +
                        ((uint32_t)((cb + c) ^ x7) << 4),
                        vsrc + kc * 64 + (cb + c) * 8);
    };
    issueKV(0, 0);
    asm volatile("cp.async.commit_group;\n");

    const uint32_t aQrow = (uint32_t)(wid * 16 + aoff8 + l8) * 128u;
    uint32_t bRow[8];
    #pragma unroll
    for (int pr = 0; pr < 8; pr++) bRow[pr] = (uint32_t)(pr * 16 + boff8 + l8) * 128u;

    uint32_t qf[8][4];
    asm volatile("cp.async.wait_group 1;\n");
    __syncthreads();
    #pragma unroll
    for (int j = 0; j < 8; j++) {
        const int kc = j >> 2, jj = j & 3;
        const uint32_t gA = (uint32_t)(((2 * jj + ags) ^ l8) << 4);
        ldmx4(qf[j], Qb + kc * 16384u + aQrow + gA);
    }

    float m0 = -1e30f, m1 = -1e30f, l0 = 0.f, l1 = 0.f;
    float O[16][4];
    #pragma unroll
    for (int i = 0; i < 16; i++)
        #pragma unroll
        for (int e = 0; e < 4; e++) O[i][e] = 0.f;

    const int q0 = qt * 128 + wid * 16 + grp;

    for (int tl = 0; tl < T; tl++) {
        asm volatile("cp.async.wait_group 0;\n");
        __syncthreads();
        if (tl + 1 < T) issueKV((tl + 1) & 1, (tl + 1) * 128);
        asm volatile("cp.async.commit_group;\n");

        const uint32_t Ks = Kb + (uint32_t)(tl & 1) * 32768u;
        const uint32_t Vs = Vb + (uint32_t)(tl & 1) * 32768u;
        const int kv0 = tl * 128;

        float s[16][4];
        #pragma unroll
        for (int i = 0; i < 16; i++)
            #pragma unroll
            for (int e = 0; e < 4; e++) s[i][e] = 0.f;

        #pragma unroll
        for (int j = 0; j < 8; j++) {
            const int kc = j >> 2, jj = j & 3;
            const uint32_t gB = (uint32_t)(((2 * jj + bgs) ^ l8) << 4);
            uint32_t bq[8][4];
            #pragma unroll
            for (int pr = 0; pr < 8; pr++)
                ldmx4(bq[pr], Ks + kc * 16384u + bRow[pr] + gB);
            #pragma unroll
            for (int nt = 0; nt < 16; nt++)
                mma_f16(s[nt], qf[j], &bq[nt >> 1][(nt & 1) * 2]);
        }

        const bool msk = (tl == qt);
        float rm0 = -1e30f, rm1 = -1e30f;
        #pragma unroll
        for (int nt = 0; nt < 16; nt++) {
            const int c0 = kv0 + nt * 8 + 2 * tid4;
            if (msk) {
                if (c0     > q0)     s[nt][0] = -1e30f;
                if (c0 + 1 > q0)     s[nt][1] = -1e30f;
                if (c0     > q0 + 8) s[nt][2] = -1e30f;
                if (c0 + 1 > q0 + 8) s[nt][3] = -1e30f;
            }
            rm0 = fmaxf(rm0, fmaxf(s[nt][0], s[nt][1]));
            rm1 = fmaxf(rm1, fmaxf(s[nt][2], s[nt][3]));
        }
        rm0 = fmaxf(rm0, __shfl_xor_sync(0xffffffffu, rm0, 1));
        rm0 = fmaxf(rm0, __shfl_xor_sync(0xffffffffu, rm0, 2));
        rm1 = fmaxf(rm1, __shfl_xor_sync(0xffffffffu, rm1, 1));
        rm1 = fmaxf(rm1, __shfl_xor_sync(0xffffffffu, rm1, 2));

        const float mn0 = fmaxf(m0, rm0), mn1 = fmaxf(m1, rm1);
        const float sc0 = exp2f((m0 - mn0) * SCL2), sc1 = exp2f((m1 - mn1) * SCL2);
        m0 = mn0; m1 = mn1;

        uint32_t P01[16], P23[16];
        float sum0 = 0.f, sum1 = 0.f;
        #pragma unroll
        for (int nt = 0; nt < 16; nt++) {
            __half2 a01 = __floats2half2_rn((s[nt][0] - m0) * SCL2, (s[nt][1] - m0) * SCL2);
            __half2 a23 = __floats2half2_rn((s[nt][2] - m1) * SCL2, (s[nt][3] - m1) * SCL2);
            P01[nt] = ex2h2(h2u(a01));
            P23[nt] = ex2h2(h2u(a23));
            float2 f01 = __half22float2(*reinterpret_cast<__half2*>(&P01[nt]));
            float2 f23 = __half22float2(*reinterpret_cast<__half2*>(&P23[nt]));
            sum0 += f01.x + f01.y;
            sum1 += f23.x + f23.y;
        }
        sum0 += __shfl_xor_sync(0xffffffffu, sum0, 1);
        sum0 += __shfl_xor_sync(0xffffffffu, sum0, 2);
        sum1 += __shfl_xor_sync(0xffffffffu, sum1, 1);
        sum1 += __shfl_xor_sync(0xffffffffu, sum1, 2);
        l0 = l0 * sc0 + sum0;
        l1 = l1 * sc1 + sum1;

        #pragma unroll
        for (int nt = 0; nt < 16; nt++) {
            O[nt][0] *= sc0; O[nt][1] *= sc0;
            O[nt][2] *= sc1; O[nt][3] *= sc1;
        }

        #pragma unroll
        for (int j = 0; j < 8; j++) {
            const int kc = j >> 2, jj = j & 3;
            const uint32_t gB = (uint32_t)(((2 * jj + bgs) ^ l8) << 4);
            uint32_t af[4] = { P01[2 * j], P23[2 * j], P01[2 * j + 1], P23[2 * j + 1] };
            uint32_t bq[8][4];
            #pragma unroll
            for (int pr = 0; pr < 8; pr++)
                ldmx4(bq[pr], Vs + kc * 16384u + bRow[pr] + gB);
            #pragma unroll
            for (int nt = 0; nt < 16; nt++)
                mma_f16(O[nt], af, &bq[nt >> 1][(nt & 1) * 2]);
        }
    }

    const float inv0 = 1.f / l0, inv1 = 1.f / l1;
    const int row0 = qt * 128 + wid * 16 + grp;
    __half* o0 = g_att + (size_t)row0 * (NH * HD) + h * HD;
    __half* o1 = o0 + (size_t)8 * (NH * HD);
    #pragma unroll
    for (int nt = 0; nt < 16; nt++) {
        const int col = nt * 8 + 2 * tid4;
        *(__half2*)(o0 + col) = __floats2half2_rn(O[nt][0] * inv0, O[nt][1] * inv0);
        *(__half2*)(o1 + col) = __floats2half2_rn(O[nt][2] * inv1, O[nt][3] * inv1);
    }
}

// ---------------- fp32 -> fp16 convert (all 3 operands, one launch) ----------------
__global__ void __launch_bounds__(256) cvt_all(
    const float* __restrict__ a, const float* __restrict__ b, const float* __restrict__ c,
    __half* __restrict__ da, __half* __restrict__ db, __half* __restrict__ dc,
    int na4, int nb4, int nc4)
{
    int i = blockIdx.x * 256 + threadIdx.x;
    const float* src; __half* dst;
    if (i < na4)            { src = a; dst = da; }
    else if (i < na4 + nb4) { i -= na4; src = b; dst = db; }
    else if (i < na4 + nb4 + nc4) { i -= na4 + nb4; src = c; dst = dc; }
    else return;
    float4 v = ((const float4*)src)[i];
    uint2 u;
    u.x = h2u(__floats2half2_rn(v.x, v.y));
    u.y = h2u(__floats2half2_rn(v.z, v.w));
    ((uint2*)dst)[i] = u;
}

// ---------------- launch ----------------
extern "C" void kernel_launch(void* const* d_in, const int* in_sizes, int n_in,
                              void* d_out, int out_size)
{
    const float* hs     = (const float*)d_in[0];
    const float* w_qkv  = (const float*)d_in[1];
    const float* w_o    = (const float*)d_in[2];
    const float* qnw    = (const float*)d_in[3];
    const float* knw    = (const float*)d_in[4];
    const float* cosT   = (const float*)d_in[5];
    const float* sinT   = (const float*)d_in[6];
    const int* positions = (const int*)d_in[9];
    float* out = (float*)d_out;

    __half *qkv, *att, *hs_h, *wqkv_h, *wo_h;
    cudaGetSymbolAddress((void**)&qkv,    g_qkv);
    cudaGetSymbolAddress((void**)&att,    g_att);
    cudaGetSymbolAddress((void**)&hs_h,   g_hs_h);
    cudaGetSymbolAddress((void**)&wqkv_h, g_wqkv_h);
    cudaGetSymbolAddress((void**)&wo_h,   g_wo_h);

    const int GSMEM = 73728;    // 72 KB (A 3x8KB + B 3x16KB)
    const int FSMEM = 163840;   // 160 KB
    cudaFuncSetAttribute(gemm64<0>,    cudaFuncAttributeMaxDynamicSharedMemorySize, GSMEM);
    cudaFuncSetAttribute(gemm64<1>,    cudaFuncAttributeMaxDynamicSharedMemorySize, GSMEM);
    cudaFuncSetAttribute(flash_kernel, cudaFuncAttributeMaxDynamicSharedMemorySize, FSMEM);

    // 0) convert all operands to fp16 in one launch
    const int na4 = SQ*HID/4, nb4 = QKV_DIM*HID/4, nc4 = HID*NH*HD/4;
    cvt_all<<<(na4 + nb4 + nc4 + 255)/256, 256>>>(
        hs, w_qkv, w_o, hs_h, wqkv_h, wo_h, na4, nb4, nc4);

    // 1) QKV projection + fused RMSNorm+RoPE (q,k) + fused V transpose (v)
    gemm64<0><<<dim3(QKV_DIM/128, SQ/64, 1), 256, GSMEM>>>(
        hs_h, wqkv_h, qkv, HID, HID, HID, QKV_DIM,
        qnw, knw, cosT, sinT, positions);

    // 2) fused flash attention -> g_att (half)
    flash_kernel<<<dim3(NH, 16), 256, FSMEM>>>();

    // 3) output projection (float out)
    gemm64<1><<<dim3(HID/128, SQ/64, 1), 256, GSMEM>>>(
        att, wo_h, out, NH*HD, NH*HD, NH*HD, HID,
        nullptr, nullptr, nullptr, nullptr, nullptr);
}

// round 15
// speedup vs baseline: 1.2832x; 1.0482x over previous
#include <cuda_runtime.h>
#include <cuda_fp16.h>
#include <cstdint>

#define SQ   2048
#define HID  2560
#define NH   16
#define NKV  4
#define HD   128
#define QKV_DIM (NH*HD + 2*NKV*HD)   // 3072
#define EPS  1e-6f
#define ATT_SCALE 0.08838834764831845f
#define LOG2E 1.4426950408889634f
#define SCL2  (ATT_SCALE * LOG2E)
#define VOFF (NH*HD + NKV*HD)
#define NJOBS (NH * 16)              // 256 (head, q-tile) jobs

// ---------------- scratch (device globals, no allocation) ----------------
__device__ __half g_qkv[(size_t)SQ * QKV_DIM];
__device__ __half g_att[(size_t)SQ * NH * HD];
__device__ __half g_hs_h[(size_t)SQ * HID];
__device__ __half g_wqkv_h[(size_t)QKV_DIM * HID];
__device__ __half g_wo_h[(size_t)HID * NH * HD];
__device__ __half g_vt[(size_t)NKV * HD * SQ];
__device__ int    g_job;

__device__ __forceinline__ void mma_f16(float* d, const uint32_t* a, const uint32_t* b) {
    asm volatile(
        "mma.sync.aligned.m16n8k16.row.col.f32.f16.f16.f32 "
        "{%0,%1,%2,%3}, {%4,%5,%6,%7}, {%8,%9}, {%0,%1,%2,%3};\n"
        : "+f"(d[0]), "+f"(d[1]), "+f"(d[2]), "+f"(d[3])
        : "r"(a[0]), "r"(a[1]), "r"(a[2]), "r"(a[3]), "r"(b[0]), "r"(b[1]));
}

__device__ __forceinline__ void ldmx4(uint32_t* r, uint32_t addr) {
    asm volatile("ldmatrix.sync.aligned.m8n8.x4.shared.b16 {%0,%1,%2,%3}, [%4];"
        : "=r"(r[0]), "=r"(r[1]), "=r"(r[2]), "=r"(r[3]) : "r"(addr));
}

__device__ __forceinline__ void cpasync(uint32_t d, const void* s) {
    asm volatile("cp.async.cg.shared.global [%0], [%1], 16;\n" :: "r"(d), "l"(s));
}

__device__ __forceinline__ uint32_t h2u(__half2 h) {
    return *reinterpret_cast<uint32_t*>(&h);
}
__device__ __forceinline__ uint32_t ex2h2(uint32_t x) {
    uint32_t r;
    asm("ex2.approx.f16x2 %0, %1;" : "=r"(r) : "r"(x));
    return r;
}

// ================= 64x128 GEMM engine, 3 CTAs/SM (R14, unchanged) =================
template<int EPI>
__global__ void __launch_bounds__(256, 3) gemm64(
    const __half* __restrict__ A, const __half* __restrict__ B, void* __restrict__ Cv,
    int K, int lda, int ldb, int ldc,
    const float* __restrict__ qnw, const float* __restrict__ knw,
    const float* __restrict__ cosT, const float* __restrict__ sinT,
    const int* __restrict__ positions)
{
    const int bx = blockIdx.x, by = blockIdx.y;

    extern __shared__ char smem[];
    const uint32_t sbase = (uint32_t)__cvta_generic_to_shared(smem);

    const int t    = threadIdx.x;
    const int lane = t & 31, wid = t >> 5;
    const int wm   = (wid & 1) * 32;
    const int wn   = (wid >> 1) * 32;
    const int m0   = by * 64, n0 = bx * 128;
    const int grp  = lane >> 2, tid4 = lane & 3;

    const int l8    = lane & 7;
    const int aoff8 = ((lane >> 3) & 1) * 8;
    const int ags   = (lane >> 4) & 1;
    const int boff8 = ((lane >> 4) & 1) * 8;
    const int bgs   = (lane >> 3) & 1;
    uint32_t arow[2], brow[2];
    #pragma unroll
    for (int mt = 0; mt < 2; mt++) arow[mt] = (uint32_t)(wm + mt * 16 + aoff8 + l8) * 128u;
    #pragma unroll
    for (int pr = 0; pr < 2; pr++) brow[pr] = (uint32_t)(wn + pr * 16 + boff8 + l8) * 128u;

    const int lrA = t >> 2, cbA = (t & 3) * 2, x7A = lrA & 7;
    const int lrB = t >> 1, cbB = (t & 1) * 4, x7B = lrB & 7;
    const __half* Aptr = A + (long long)(m0 + lrA) * lda;
    const __half* Bptr = B + (long long)(n0 + lrB) * ldb;

    float acc[2][4][4];
    #pragma unroll
    for (int i = 0; i < 2; i++)
        #pragma unroll
        for (int j = 0; j < 4; j++)
            #pragma unroll
            for (int r = 0; r < 4; r++) acc[i][j][r] = 0.f;

    const int nK = K >> 6;

    auto issue = [&](int st, int k0) {
        const uint32_t ab = sbase + st * 8192u + (uint32_t)lrA * 128u;
        #pragma unroll
        for (int c = 0; c < 2; c++)
            cpasync(ab + (uint32_t)(((cbA + c) ^ x7A) << 4), Aptr + k0 + (cbA + c) * 8);
        const uint32_t bb = sbase + 24576u + st * 16384u + (uint32_t)lrB * 128u;
        #pragma unroll
        for (int c = 0; c < 4; c++)
            cpasync(bb + (uint32_t)(((cbB + c) ^ x7B) << 4), Bptr + k0 + (cbB + c) * 8);
    };

    issue(0, 0);
    asm volatile("cp.async.commit_group;\n");
    issue(1, 64);
    asm volatile("cp.async.commit_group;\n");

    for (int kt = 0; kt < nK; kt++) {
        asm volatile("cp.async.wait_group 1;\n");
        __syncthreads();

        const int st = kt - (kt / 3) * 3;
        const uint32_t sA = sbase + st * 8192u;
        const uint32_t sB = sbase + 24576u + st * 16384u;

        #pragma unroll
        for (int j = 0; j < 4; j++) {
            const uint32_t ga = (uint32_t)(((2 * j + ags) ^ l8) << 4);
            const uint32_t gb = (uint32_t)(((2 * j + bgs) ^ l8) << 4);
            uint32_t af[2][4], bq[2][4];
            ldmx4(af[0], sA + arow[0] + ga);
            ldmx4(af[1], sA + arow[1] + ga);
            ldmx4(bq[0], sB + brow[0] + gb);
            ldmx4(bq[1], sB + brow[1] + gb);
            #pragma unroll
            for (int mt = 0; mt < 2; mt++) {
                mma_f16(acc[mt][0], af[mt], &bq[0][0]);
                mma_f16(acc[mt][1], af[mt], &bq[0][2]);
                mma_f16(acc[mt][2], af[mt], &bq[1][0]);
                mma_f16(acc[mt][3], af[mt], &bq[1][2]);
            }
        }

        if (kt + 2 < nK) issue((kt + 2) - ((kt + 2) / 3) * 3, (kt + 2) << 6);
        asm volatile("cp.async.commit_group;\n");
    }

    if (EPI == 1) {
        float* C = (float*)Cv;
        #pragma unroll
        for (int mt = 0; mt < 2; mt++) {
            #pragma unroll
            for (int nt = 0; nt < 4; nt++) {
                const int r0 = m0 + wm + mt * 16 + grp;
                const int col = n0 + wn + nt * 8 + tid4 * 2;
                float2 lo, hi;
                lo.x = acc[mt][nt][0]; lo.y = acc[mt][nt][1];
                hi.x = acc[mt][nt][2]; hi.y = acc[mt][nt][3];
                *(float2*)(C + (long long)r0 * ldc + col)       = lo;
                *(float2*)(C + (long long)(r0 + 8) * ldc + col) = hi;
            }
        }
        return;
    }

    __half* C = (__half*)Cv;
    const bool is_q = (bx < NH);
    const bool is_k = (bx >= NH) && (bx < NH + NKV);

    if (is_q || is_k) {
        const float* w = is_q ? qnw : knw;
        float* red = (float*)smem;
        __syncthreads();

        const int nw = wid >> 1;
        float rn0[2], rn1[2];

        #pragma unroll
        for (int mt = 0; mt < 2; mt++) {
            float p0 = 0.f, p1 = 0.f;
            #pragma unroll
            for (int nt = 0; nt < 4; nt++) {
                p0 += acc[mt][nt][0] * acc[mt][nt][0] + acc[mt][nt][1] * acc[mt][nt][1];
                p1 += acc[mt][nt][2] * acc[mt][nt][2] + acc[mt][nt][3] * acc[mt][nt][3];
            }
            p0 += __shfl_xor_sync(0xffffffffu, p0, 1);
            p0 += __shfl_xor_sync(0xffffffffu, p0, 2);
            p1 += __shfl_xor_sync(0xffffffffu, p1, 1);
            p1 += __shfl_xor_sync(0xffffffffu, p1, 2);
            if (tid4 == 0) {
                red[nw * 64 + wm + mt * 16 + grp]     = p0;
                red[nw * 64 + wm + mt * 16 + grp + 8] = p1;
            }
        }
        __syncthreads();

        #pragma unroll
        for (int mt = 0; mt < 2; mt++) {
            const int r0 = wm + mt * 16 + grp;
            float s0 = red[r0] + red[64 + r0] + red[128 + r0] + red[192 + r0];
            float s1 = red[r0 + 8] + red[64 + r0 + 8] + red[128 + r0 + 8] + red[192 + r0 + 8];
            rn0[mt] = rsqrtf(s0 * (1.0f / HD) + EPS);
            rn1[mt] = rsqrtf(s1 * (1.0f / HD) + EPS);
        }

        #pragma unroll
        for (int mt = 0; mt < 2; mt++) {
            const int tok0 = m0 + wm + mt * 16 + grp;
            const int tok1 = tok0 + 8;
            const int pos0 = positions[tok0];
            const int pos1 = positions[tok1];
            #pragma unroll
            for (int nt = 0; nt < 4; nt++) {
                const int col = wn + nt * 8 + tid4 * 2;
                const int p   = col >> 1;
                const float w0 = w[col], w1 = w[col + 1];
                const float c0 = cosT[pos0 * (HD/2) + p], sn0 = sinT[pos0 * (HD/2) + p];
                const float c1 = cosT[pos1 * (HD/2) + p], sn1 = sinT[pos1 * (HD/2) + p];

                float x0 = acc[mt][nt][0] * rn0[mt] * w0;
                float x1 = acc[mt][nt][1] * rn0[mt] * w1;
                float y0 = acc[mt][nt][2] * rn1[mt] * w0;
                float y1 = acc[mt][nt][3] * rn1[mt] * w1;

                __half2 lo = __floats2half2_rn(x0 * c0 - x1 * sn0, x0 * sn0 + x1 * c0);
                __half2 hi = __floats2half2_rn(y0 * c1 - y1 * sn1, y0 * sn1 + y1 * c1);
                *(__half2*)(C + (long long)tok0 * ldc + n0 + col) = lo;
                *(__half2*)(C + (long long)tok1 * ldc + n0 + col) = hi;
            }
        }
    } else {
        __half* tsm = (__half*)smem;   // [128 d][72 tok]
        __syncthreads();

        #pragma unroll
        for (int mt = 0; mt < 2; mt++) {
            const int tok0 = wm + mt * 16 + grp;
            const int tok1 = tok0 + 8;
            #pragma unroll
            for (int nt = 0; nt < 4; nt++) {
                const int d = wn + nt * 8 + tid4 * 2;
                tsm[(d    ) * 72 + tok0] = __float2half_rn(acc[mt][nt][0]);
                tsm[(d + 1) * 72 + tok0] = __float2half_rn(acc[mt][nt][1]);
                tsm[(d    ) * 72 + tok1] = __float2half_rn(acc[mt][nt][2]);
                tsm[(d + 1) * 72 + tok1] = __float2half_rn(acc[mt][nt][3]);
            }
        }
        __syncthreads();

        const int hkv = bx - (NH + NKV);
        #pragma unroll
        for (int i = t; i < 128 * 8; i += 256) {
            const int dr  = i >> 3;
            const int seg = i & 7;
            uint4 v = *(const uint4*)(tsm + dr * 72 + seg * 8);
            *(uint4*)(g_vt + (size_t)(hkv * HD + dr) * SQ + m0 + seg * 8) = v;
        }
    }
}

// ---------------- persistent fused flash attention ----------------
// 148 CTAs, atomic job queue over NJOBS (head, q-tile) jobs, heavy-first.
// SMEM: Q 32K | K 2st x 32K | Vt 2st x 32K | job slot = 160KB + 16B.
__global__ void __launch_bounds__(256, 1) flash_kernel()
{
    extern __shared__ char fsm[];
    const uint32_t sb = (uint32_t)__cvta_generic_to_shared(fsm);
    const uint32_t Qb = sb;
    const uint32_t Kb = sb + 32768u;
    const uint32_t Vb = sb + 98304u;
    int* jobslot = (int*)(fsm + 163840);

    const int t = threadIdx.x, lane = t & 31, wid = t >> 5;
    const int grp = lane >> 2, tid4 = lane & 3;
    const int l8 = lane & 7;
    const int aoff8 = ((lane >> 3) & 1) * 8;
    const int ags   = (lane >> 4) & 1;
    const int boff8 = ((lane >> 4) & 1) * 8;
    const int bgs   = (lane >> 3) & 1;

    const int r  = t >> 1;
    const int cb = (t & 1) * 4;
    const int x7 = r & 7;

    const uint32_t aQrow = (uint32_t)(wid * 16 + aoff8 + l8) * 128u;
    uint32_t bRow[8];
    #pragma unroll
    for (int pr = 0; pr < 8; pr++) bRow[pr] = (uint32_t)(pr * 16 + boff8 + l8) * 128u;

    for (;;) {
        // ---- acquire job (barrier also fences SMEM reuse between jobs) ----
        __syncthreads();
        if (t == 0) *jobslot = atomicAdd(&g_job, 1);
        __syncthreads();
        const int job = *jobslot;
        if (job >= NJOBS) return;

        const int qt = 15 - (job >> 4);   // heavy q-tiles first
        const int h  = job & 15;
        const int hkv = h >> 2;

        const __half* Qg  = g_qkv + h * HD;
        const __half* Kg  = g_qkv + NH * HD + hkv * HD;
        const __half* Vtg = g_vt + (size_t)hkv * HD * SQ;

        // ---- load Q tile ----
        {
            const __half* src = Qg + (size_t)(qt * 128 + r) * QKV_DIM;
            #pragma unroll
            for (int kc = 0; kc < 2; kc++)
                #pragma unroll
                for (int c = 0; c < 4; c++)
                    cpasync(Qb + kc * 16384u + (uint32_t)r * 128u +
                            ((uint32_t)((cb + c) ^ x7) << 4),
                            src + kc * 64 + (cb + c) * 8);
        }
        asm volatile("cp.async.commit_group;\n");

        const int T = qt + 1;

        auto issueKV = [&](int st, int kv0) {
            const uint32_t Ks = Kb + (uint32_t)st * 32768u;
            const __half* ksrc = Kg + (size_t)(kv0 + r) * QKV_DIM;
            #pragma unroll
            for (int kc = 0; kc < 2; kc++)
                #pragma unroll
                for (int c = 0; c < 4; c++)
                    cpasync(Ks + kc * 16384u + (uint32_t)r * 128u +
                            ((uint32_t)((cb + c) ^ x7) << 4),
                            ksrc + kc * 64 + (cb + c) * 8);
            const uint32_t Vs = Vb + (uint32_t)st * 32768u;
            const __half* vsrc = Vtg + (size_t)r * SQ + kv0;
            #pragma unroll
            for (int kc = 0; kc < 2; kc++)
                #pragma unroll
                for (int c = 0; c < 4; c++)
                    cpasync(Vs + kc * 16384u + (uint32_t)r * 128u +
                            ((uint32_t)((cb + c) ^ x7) << 4),
                            vsrc + kc * 64 + (cb + c) * 8);
        };
        issueKV(0, 0);
        asm volatile("cp.async.commit_group;\n");

        // ---- preload Q fragments ----
        uint32_t qf[8][4];
        asm volatile("cp.async.wait_group 1;\n");
        __syncthreads();
        #pragma unroll
        for (int j = 0; j < 8; j++) {
            const int kc = j >> 2, jj = j & 3;
            const uint32_t gA = (uint32_t)(((2 * jj + ags) ^ l8) << 4);
            ldmx4(qf[j], Qb + kc * 16384u + aQrow + gA);
        }

        float m0 = -1e30f, m1 = -1e30f, l0 = 0.f, l1 = 0.f;
        float O[16][4];
        #pragma unroll
        for (int i = 0; i < 16; i++)
            #pragma unroll
            for (int e = 0; e < 4; e++) O[i][e] = 0.f;

        const int q0 = qt * 128 + wid * 16 + grp;

        for (int tl = 0; tl < T; tl++) {
            asm volatile("cp.async.wait_group 0;\n");
            __syncthreads();
            if (tl + 1 < T) issueKV((tl + 1) & 1, (tl + 1) * 128);
            asm volatile("cp.async.commit_group;\n");

            const uint32_t Ks = Kb + (uint32_t)(tl & 1) * 32768u;
            const uint32_t Vs = Vb + (uint32_t)(tl & 1) * 32768u;
            const int kv0 = tl * 128;

            float s[16][4];
            #pragma unroll
            for (int i = 0; i < 16; i++)
                #pragma unroll
                for (int e = 0; e < 4; e++) s[i][e] = 0.f;

            #pragma unroll
            for (int j = 0; j < 8; j++) {
                const int kc = j >> 2, jj = j & 3;
                const uint32_t gB = (uint32_t)(((2 * jj + bgs) ^ l8) << 4);
                uint32_t bq[8][4];
                #pragma unroll
                for (int pr = 0; pr < 8; pr++)
                    ldmx4(bq[pr], Ks + kc * 16384u + bRow[pr] + gB);
                #pragma unroll
                for (int nt = 0; nt < 16; nt++)
                    mma_f16(s[nt], qf[j], &bq[nt >> 1][(nt & 1) * 2]);
            }

            const bool msk = (tl == qt);
            float rm0 = -1e30f, rm1 = -1e30f;
            #pragma unroll
            for (int nt = 0; nt < 16; nt++) {
                const int c0 = kv0 + nt * 8 + 2 * tid4;
                if (msk) {
                    if (c0     > q0)     s[nt][0] = -1e30f;
                    if (c0 + 1 > q0)     s[nt][1] = -1e30f;
                    if (c0     > q0 + 8) s[nt][2] = -1e30f;
                    if (c0 + 1 > q0 + 8) s[nt][3] = -1e30f;
                }
                rm0 = fmaxf(rm0, fmaxf(s[nt][0], s[nt][1]));
                rm1 = fmaxf(rm1, fmaxf(s[nt][2], s[nt][3]));
            }
            rm0 = fmaxf(rm0, __shfl_xor_sync(0xffffffffu, rm0, 1));
            rm0 = fmaxf(rm0, __shfl_xor_sync(0xffffffffu, rm0, 2));
            rm1 = fmaxf(rm1, __shfl_xor_sync(0xffffffffu, rm1, 1));
            rm1 = fmaxf(rm1, __shfl_xor_sync(0xffffffffu, rm1, 2));

            const float mn0 = fmaxf(m0, rm0), mn1 = fmaxf(m1, rm1);
            const float sc0 = exp2f((m0 - mn0) * SCL2), sc1 = exp2f((m1 - mn1) * SCL2);
            m0 = mn0; m1 = mn1;

            uint32_t P01[16], P23[16];
            float sum0 = 0.f, sum1 = 0.f;
            #pragma unroll
            for (int nt = 0; nt < 16; nt++) {
                __half2 a01 = __floats2half2_rn((s[nt][0] - m0) * SCL2, (s[nt][1] - m0) * SCL2);
                __half2 a23 = __floats2half2_rn((s[nt][2] - m1) * SCL2, (s[nt][3] - m1) * SCL2);
                P01[nt] = ex2h2(h2u(a01));
                P23[nt] = ex2h2(h2u(a23));
                float2 f01 = __half22float2(*reinterpret_cast<__half2*>(&P01[nt]));
                float2 f23 = __half22float2(*reinterpret_cast<__half2*>(&P23[nt]));
                sum0 += f01.x + f01.y;
                sum1 += f23.x + f23.y;
            }
            sum0 += __shfl_xor_sync(0xffffffffu, sum0, 1);
            sum0 += __shfl_xor_sync(0xffffffffu, sum0, 2);
            sum1 += __shfl_xor_sync(0xffffffffu, sum1, 1);
            sum1 += __shfl_xor_sync(0xffffffffu, sum1, 2);
            l0 = l0 * sc0 + sum0;
            l1 = l1 * sc1 + sum1;

            #pragma unroll
            for (int nt = 0; nt < 16; nt++) {
                O[nt][0] *= sc0; O[nt][1] *= sc0;
                O[nt][2] *= sc1; O[nt][3] *= sc1;
            }

            #pragma unroll
            for (int j = 0; j < 8; j++) {
                const int kc = j >> 2, jj = j & 3;
                const uint32_t gB = (uint32_t)(((2 * jj + bgs) ^ l8) << 4);
                uint32_t af[4] = { P01[2 * j], P23[2 * j], P01[2 * j + 1], P23[2 * j + 1] };
                uint32_t bq[8][4];
                #pragma unroll
                for (int pr = 0; pr < 8; pr++)
                    ldmx4(bq[pr], Vs + kc * 16384u + bRow[pr] + gB);
                #pragma unroll
                for (int nt = 0; nt < 16; nt++)
                    mma_f16(O[nt], af, &bq[nt >> 1][(nt & 1) * 2]);
            }
        }

        // ---- job epilogue ----
        const float inv0 = 1.f / l0, inv1 = 1.f / l1;
        const int row0 = qt * 128 + wid * 16 + grp;
        __half* o0 = g_att + (size_t)row0 * (NH * HD) + h * HD;
        __half* o1 = o0 + (size_t)8 * (NH * HD);
        #pragma unroll
        for (int nt = 0; nt < 16; nt++) {
            const int col = nt * 8 + 2 * tid4;
            *(__half2*)(o0 + col) = __floats2half2_rn(O[nt][0] * inv0, O[nt][1] * inv0);
            *(__half2*)(o1 + col) = __floats2half2_rn(O[nt][2] * inv1, O[nt][3] * inv1);
        }
    }
}

// ---------------- fp32 -> fp16 convert + job-counter reset ----------------
__global__ void __launch_bounds__(256) cvt_all(
    const float* __restrict__ a, const float* __restrict__ b, const float* __restrict__ c,
    __half* __restrict__ da, __half* __restrict__ db, __half* __restrict__ dc,
    int na4, int nb4, int nc4)
{
    if (blockIdx.x == 0 && threadIdx.x == 0) g_job = 0;
    int i = blockIdx.x * 256 + threadIdx.x;
    const float* src; __half* dst;
    if (i < na4)            { src = a; dst = da; }
    else if (i < na4 + nb4) { i -= na4; src = b; dst = db; }
    else if (i < na4 + nb4 + nc4) { i -= na4 + nb4; src = c; dst = dc; }
    else return;
    float4 v = ((const float4*)src)[i];
    uint2 u;
    u.x = h2u(__floats2half2_rn(v.x, v.y));
    u.y = h2u(__floats2half2_rn(v.z, v.w));
    ((uint2*)dst)[i] = u;
}

// ---------------- launch ----------------
extern "C" void kernel_launch(void* const* d_in, const int* in_sizes, int n_in,
                              void* d_out, int out_size)
{
    const float* hs     = (const float*)d_in[0];
    const float* w_qkv  = (const float*)d_in[1];
    const float* w_o    = (const float*)d_in[2];
    const float* qnw    = (const float*)d_in[3];
    const float* knw    = (const float*)d_in[4];
    const float* cosT   = (const float*)d_in[5];
    const float* sinT   = (const float*)d_in[6];
    const int* positions = (const int*)d_in[9];
    float* out = (float*)d_out;

    __half *qkv, *att, *hs_h, *wqkv_h, *wo_h;
    cudaGetSymbolAddress((void**)&qkv,    g_qkv);
    cudaGetSymbolAddress((void**)&att,    g_att);
    cudaGetSymbolAddress((void**)&hs_h,   g_hs_h);
    cudaGetSymbolAddress((void**)&wqkv_h, g_wqkv_h);
    cudaGetSymbolAddress((void**)&wo_h,   g_wo_h);

    const int GSMEM = 73728;    // 72 KB
    const int FSMEM = 163856;   // 160 KB + job slot
    cudaFuncSetAttribute(gemm64<0>,    cudaFuncAttributeMaxDynamicSharedMemorySize, GSMEM);
    cudaFuncSetAttribute(gemm64<1>,    cudaFuncAttributeMaxDynamicSharedMemorySize, GSMEM);
    cudaFuncSetAttribute(flash_kernel, cudaFuncAttributeMaxDynamicSharedMemorySize, FSMEM);

    // 0) convert all operands to fp16 (also resets flash job counter)
    const int na4 = SQ*HID/4, nb4 = QKV_DIM*HID/4, nc4 = HID*NH*HD/4;
    cvt_all<<<(na4 + nb4 + nc4 + 255)/256, 256>>>(
        hs, w_qkv, w_o, hs_h, wqkv_h, wo_h, na4, nb4, nc4);

    // 1) QKV projection + fused RMSNorm+RoPE (q,k) + fused V transpose (v)
    gemm64<0><<<dim3(QKV_DIM/128, SQ/64, 1), 256, GSMEM>>>(
        hs_h, wqkv_h, qkv, HID, HID, HID, QKV_DIM,
        qnw, knw, cosT, sinT, positions);

    // 2) persistent fused flash attention -> g_att (half)
    flash_kernel<<<148, 256, FSMEM>>>();

    // 3) output projection (float out)
    gemm64<1><<<dim3(HID/128, SQ/64, 1), 256, GSMEM>>>(
        att, wo_h, out, NH*HD, NH*HD, NH*HD, HID,
        nullptr, nullptr, nullptr, nullptr, nullptr);
}

// round 16
// speedup vs baseline: 1.3044x; 1.0165x over previous
#include <cuda_runtime.h>
#include <cuda_fp16.h>
#include <cstdint>

#define SQ   2048
#define HID  2560
#define NH   16
#define NKV  4
#define HD   128
#define QKV_DIM (NH*HD + 2*NKV*HD)   // 3072
#define EPS  1e-6f
#define ATT_SCALE 0.08838834764831845f
#define LOG2E 1.4426950408889634f
#define SCL2  (ATT_SCALE * LOG2E)
#define NJOBS (NH * 16)              // 256 flash jobs
#define WO_N4 (HID * NH * HD / 4)    // w_o float4 count
#define CVT_CTAS 120                 // QKV tail-filler CTAs (768+120=888=2*444)

// ---------------- scratch (device globals, no allocation) ----------------
__device__ __half g_qkv[(size_t)SQ * QKV_DIM];
__device__ __half g_att[(size_t)SQ * NH * HD];
__device__ __half g_hs_h[(size_t)SQ * HID];
__device__ __half g_wqkv_h[(size_t)QKV_DIM * HID];
__device__ __half g_wo_h[(size_t)HID * NH * HD];
__device__ __half g_vt[(size_t)NKV * HD * SQ];
__device__ int    g_job;

__device__ __forceinline__ void mma_f16(float* d, const uint32_t* a, const uint32_t* b) {
    asm volatile(
        "mma.sync.aligned.m16n8k16.row.col.f32.f16.f16.f32 "
        "{%0,%1,%2,%3}, {%4,%5,%6,%7}, {%8,%9}, {%0,%1,%2,%3};\n"
        : "+f"(d[0]), "+f"(d[1]), "+f"(d[2]), "+f"(d[3])
        : "r"(a[0]), "r"(a[1]), "r"(a[2]), "r"(a[3]), "r"(b[0]), "r"(b[1]));
}

__device__ __forceinline__ void ldmx4(uint32_t* r, uint32_t addr) {
    asm volatile("ldmatrix.sync.aligned.m8n8.x4.shared.b16 {%0,%1,%2,%3}, [%4];"
        : "=r"(r[0]), "=r"(r[1]), "=r"(r[2]), "=r"(r[3]) : "r"(addr));
}

__device__ __forceinline__ void cpasync(uint32_t d, const void* s) {
    asm volatile("cp.async.cg.shared.global [%0], [%1], 16;\n" :: "r"(d), "l"(s));
}

__device__ __forceinline__ uint32_t h2u(__half2 h) {
    return *reinterpret_cast<uint32_t*>(&h);
}
__device__ __forceinline__ uint32_t ex2h2(uint32_t x) {
    uint32_t r;
    asm("ex2.approx.f16x2 %0, %1;" : "=r"(r) : "r"(x));
    return r;
}

// ================= 64x128 GEMM engine, 3 CTAs/SM =================
// EPI 0 = QKV (+RMSNorm/RoPE or V-transpose epilogue, + w_o cvt tail blocks)
// EPI 1 = O-projection: split-K over gridDim.z, fp32 atomicAdd into zeroed C.
template<int EPI>
__global__ void __launch_bounds__(256, 3) gemm64(
    const __half* __restrict__ A, const __half* __restrict__ B, void* __restrict__ Cv,
    int K, int lda, int ldb, int ldc,
    const float* __restrict__ qnw, const float* __restrict__ knw,
    const float* __restrict__ cosT, const float* __restrict__ sinT,
    const int* __restrict__ positions,
    const float* __restrict__ wo_src)
{
    const int bx = blockIdx.x, by = blockIdx.y;
    const int t = threadIdx.x;

    if (EPI == 0 && by >= SQ / 64) {
        // ---- tail-filler blocks: convert w_o fp32 -> fp16 ----
        const int blk = (by - SQ / 64) * gridDim.x + bx;   // 0..CVT_CTAS-1
        for (int i = blk * 256 + t; i < WO_N4; i += CVT_CTAS * 256) {
            float4 v = ((const float4*)wo_src)[i];
            uint2 u;
            u.x = h2u(__floats2half2_rn(v.x, v.y));
            u.y = h2u(__floats2half2_rn(v.z, v.w));
            ((uint2*)g_wo_h)[i] = u;
        }
        return;
    }

    extern __shared__ char smem[];
    const uint32_t sbase = (uint32_t)__cvta_generic_to_shared(smem);

    const int lane = t & 31, wid = t >> 5;
    const int wm   = (wid & 1) * 32;
    const int wn   = (wid >> 1) * 32;
    const int m0   = by * 64, n0 = bx * 128;
    const int grp  = lane >> 2, tid4 = lane & 3;

    const int l8    = lane & 7;
    const int aoff8 = ((lane >> 3) & 1) * 8;
    const int ags   = (lane >> 4) & 1;
    const int boff8 = ((lane >> 4) & 1) * 8;
    const int bgs   = (lane >> 3) & 1;
    uint32_t arow[2], brow[2];
    #pragma unroll
    for (int mt = 0; mt < 2; mt++) arow[mt] = (uint32_t)(wm + mt * 16 + aoff8 + l8) * 128u;
    #pragma unroll
    for (int pr = 0; pr < 2; pr++) brow[pr] = (uint32_t)(wn + pr * 16 + boff8 + l8) * 128u;

    // split-K (gridDim.z = 1 for EPI 0)
    const int Keff = K / gridDim.z;
    const long long koff = (long long)blockIdx.z * Keff;

    const int lrA = t >> 2, cbA = (t & 3) * 2, x7A = lrA & 7;
    const int lrB = t >> 1, cbB = (t & 1) * 4, x7B = lrB & 7;
    const __half* Aptr = A + (long long)(m0 + lrA) * lda + koff;
    const __half* Bptr = B + (long long)(n0 + lrB) * ldb + koff;

    float acc[2][4][4];
    #pragma unroll
    for (int i = 0; i < 2; i++)
        #pragma unroll
        for (int j = 0; j < 4; j++)
            #pragma unroll
            for (int r = 0; r < 4; r++) acc[i][j][r] = 0.f;

    const int nK = Keff >> 6;

    auto issue = [&](int st, int k0) {
        const uint32_t ab = sbase + st * 8192u + (uint32_t)lrA * 128u;
        #pragma unroll
        for (int c = 0; c < 2; c++)
            cpasync(ab + (uint32_t)(((cbA + c) ^ x7A) << 4), Aptr + k0 + (cbA + c) * 8);
        const uint32_t bb = sbase + 24576u + st * 16384u + (uint32_t)lrB * 128u;
        #pragma unroll
        for (int c = 0; c < 4; c++)
            cpasync(bb + (uint32_t)(((cbB + c) ^ x7B) << 4), Bptr + k0 + (cbB + c) * 8);
    };

    issue(0, 0);
    asm volatile("cp.async.commit_group;\n");
    issue(1, 64);
    asm volatile("cp.async.commit_group;\n");

    for (int kt = 0; kt < nK; kt++) {
        asm volatile("cp.async.wait_group 1;\n");
        __syncthreads();

        const int st = kt - (kt / 3) * 3;
        const uint32_t sA = sbase + st * 8192u;
        const uint32_t sB = sbase + 24576u + st * 16384u;

        #pragma unroll
        for (int j = 0; j < 4; j++) {
            const uint32_t ga = (uint32_t)(((2 * j + ags) ^ l8) << 4);
            const uint32_t gb = (uint32_t)(((2 * j + bgs) ^ l8) << 4);
            uint32_t af[2][4], bq[2][4];
            ldmx4(af[0], sA + arow[0] + ga);
            ldmx4(af[1], sA + arow[1] + ga);
            ldmx4(bq[0], sB + brow[0] + gb);
            ldmx4(bq[1], sB + brow[1] + gb);
            #pragma unroll
            for (int mt = 0; mt < 2; mt++) {
                mma_f16(acc[mt][0], af[mt], &bq[0][0]);
                mma_f16(acc[mt][1], af[mt], &bq[0][2]);
                mma_f16(acc[mt][2], af[mt], &bq[1][0]);
                mma_f16(acc[mt][3], af[mt], &bq[1][2]);
            }
        }

        if (kt + 2 < nK) issue((kt + 2) - ((kt + 2) / 3) * 3, (kt + 2) << 6);
        asm volatile("cp.async.commit_group;\n");
    }

    if (EPI == 1) {
        // ---- split-K epilogue: fp32 atomic accumulate into zeroed C ----
        float* C = (float*)Cv;
        #pragma unroll
        for (int mt = 0; mt < 2; mt++) {
            #pragma unroll
            for (int nt = 0; nt < 4; nt++) {
                const int r0 = m0 + wm + mt * 16 + grp;
                const int col = n0 + wn + nt * 8 + tid4 * 2;
                float* p0 = C + (long long)r0 * ldc + col;
                float* p1 = C + (long long)(r0 + 8) * ldc + col;
                atomicAdd(p0,     acc[mt][nt][0]);
                atomicAdd(p0 + 1, acc[mt][nt][1]);
                atomicAdd(p1,     acc[mt][nt][2]);
                atomicAdd(p1 + 1, acc[mt][nt][3]);
            }
        }
        return;
    }

    __half* C = (__half*)Cv;
    const bool is_q = (bx < NH);
    const bool is_k = (bx >= NH) && (bx < NH + NKV);

    if (is_q || is_k) {
        const float* w = is_q ? qnw : knw;
        float* red = (float*)smem;
        __syncthreads();

        const int nw = wid >> 1;
        float rn0[2], rn1[2];

        #pragma unroll
        for (int mt = 0; mt < 2; mt++) {
            float p0 = 0.f, p1 = 0.f;
            #pragma unroll
            for (int nt = 0; nt < 4; nt++) {
                p0 += acc[mt][nt][0] * acc[mt][nt][0] + acc[mt][nt][1] * acc[mt][nt][1];
                p1 += acc[mt][nt][2] * acc[mt][nt][2] + acc[mt][nt][3] * acc[mt][nt][3];
            }
            p0 += __shfl_xor_sync(0xffffffffu, p0, 1);
            p0 += __shfl_xor_sync(0xffffffffu, p0, 2);
            p1 += __shfl_xor_sync(0xffffffffu, p1, 1);
            p1 += __shfl_xor_sync(0xffffffffu, p1, 2);
            if (tid4 == 0) {
                red[nw * 64 + wm + mt * 16 + grp]     = p0;
                red[nw * 64 + wm + mt * 16 + grp + 8] = p1;
            }
        }
        __syncthreads();

        #pragma unroll
        for (int mt = 0; mt < 2; mt++) {
            const int r0 = wm + mt * 16 + grp;
            float s0 = red[r0] + red[64 + r0] + red[128 + r0] + red[192 + r0];
            float s1 = red[r0 + 8] + red[64 + r0 + 8] + red[128 + r0 + 8] + red[192 + r0 + 8];
            rn0[mt] = rsqrtf(s0 * (1.0f / HD) + EPS);
            rn1[mt] = rsqrtf(s1 * (1.0f / HD) + EPS);
        }

        #pragma unroll
        for (int mt = 0; mt < 2; mt++) {
            const int tok0 = m0 + wm + mt * 16 + grp;
            const int tok1 = tok0 + 8;
            const int pos0 = positions[tok0];
            const int pos1 = positions[tok1];
            #pragma unroll
            for (int nt = 0; nt < 4; nt++) {
                const int col = wn + nt * 8 + tid4 * 2;
                const int p   = col >> 1;
                const float w0 = w[col], w1 = w[col + 1];
                const float c0 = cosT[pos0 * (HD/2) + p], sn0 = sinT[pos0 * (HD/2) + p];
                const float c1 = cosT[pos1 * (HD/2) + p], sn1 = sinT[pos1 * (HD/2) + p];

                float x0 = acc[mt][nt][0] * rn0[mt] * w0;
                float x1 = acc[mt][nt][1] * rn0[mt] * w1;
                float y0 = acc[mt][nt][2] * rn1[mt] * w0;
                float y1 = acc[mt][nt][3] * rn1[mt] * w1;

                __half2 lo = __floats2half2_rn(x0 * c0 - x1 * sn0, x0 * sn0 + x1 * c0);
                __half2 hi = __floats2half2_rn(y0 * c1 - y1 * sn1, y0 * sn1 + y1 * c1);
                *(__half2*)(C + (long long)tok0 * ldc + n0 + col) = lo;
                *(__half2*)(C + (long long)tok1 * ldc + n0 + col) = hi;
            }
        }
    } else {
        __half* tsm = (__half*)smem;   // [128 d][72 tok]
        __syncthreads();

        #pragma unroll
        for (int mt = 0; mt < 2; mt++) {
            const int tok0 = wm + mt * 16 + grp;
            const int tok1 = tok0 + 8;
            #pragma unroll
            for (int nt = 0; nt < 4; nt++) {
                const int d = wn + nt * 8 + tid4 * 2;
                tsm[(d    ) * 72 + tok0] = __float2half_rn(acc[mt][nt][0]);
                tsm[(d + 1) * 72 + tok0] = __float2half_rn(acc[mt][nt][1]);
                tsm[(d    ) * 72 + tok1] = __float2half_rn(acc[mt][nt][2]);
                tsm[(d + 1) * 72 + tok1] = __float2half_rn(acc[mt][nt][3]);
            }
        }
        __syncthreads();

        const int hkv = bx - (NH + NKV);
        #pragma unroll
        for (int i = t; i < 128 * 8; i += 256) {
            const int dr  = i >> 3;
            const int seg = i & 7;
            uint4 v = *(const uint4*)(tsm + dr * 72 + seg * 8);
            *(uint4*)(g_vt + (size_t)(hkv * HD + dr) * SQ + m0 + seg * 8) = v;
        }
    }
}

// ---------------- persistent fused flash attention (R15, unchanged) ----------------
__global__ void __launch_bounds__(256, 1) flash_kernel()
{
    extern __shared__ char fsm[];
    const uint32_t sb = (uint32_t)__cvta_generic_to_shared(fsm);
    const uint32_t Qb = sb;
    const uint32_t Kb = sb + 32768u;
    const uint32_t Vb = sb + 98304u;
    int* jobslot = (int*)(fsm + 163840);

    const int t = threadIdx.x, lane = t & 31, wid = t >> 5;
    const int grp = lane >> 2, tid4 = lane & 3;
    const int l8 = lane & 7;
    const int aoff8 = ((lane >> 3) & 1) * 8;
    const int ags   = (lane >> 4) & 1;
    const int boff8 = ((lane >> 4) & 1) * 8;
    const int bgs   = (lane >> 3) & 1;

    const int r  = t >> 1;
    const int cb = (t & 1) * 4;
    const int x7 = r & 7;

    const uint32_t aQrow = (uint32_t)(wid * 16 + aoff8 + l8) * 128u;
    uint32_t bRow[8];
    #pragma unroll
    for (int pr = 0; pr < 8; pr++) bRow[pr] = (uint32_t)(pr * 16 + boff8 + l8) * 128u;

    for (;;) {
        __syncthreads();
        if (t == 0) *jobslot = atomicAdd(&g_job, 1);
        __syncthreads();
        const int job = *jobslot;
        if (job >= NJOBS) return;

        const int qt = 15 - (job >> 4);
        const int h  = job & 15;
        const int hkv = h >> 2;

        const __half* Qg  = g_qkv + h * HD;
        const __half* Kg  = g_qkv + NH * HD + hkv * HD;
        const __half* Vtg = g_vt + (size_t)hkv * HD * SQ;

        {
            const __half* src = Qg + (size_t)(qt * 128 + r) * QKV_DIM;
            #pragma unroll
            for (int kc = 0; kc < 2; kc++)
                #pragma unroll
                for (int c = 0; c < 4; c++)
                    cpasync(Qb + kc * 16384u + (uint32_t)r * 128u +
                            ((uint32_t)((cb + c) ^ x7) << 4),
                            src + kc * 64 + (cb + c) * 8);
        }
        asm volatile("cp.async.commit_group;\n");

        const int T = qt + 1;

        auto issueKV = [&](int st, int kv0) {
            const uint32_t Ks = Kb + (uint32_t)st * 32768u;
            const __half* ksrc = Kg + (size_t)(kv0 + r) * QKV_DIM;
            #pragma unroll
            for (int kc = 0; kc < 2; kc++)
                #pragma unroll
                for (int c = 0; c < 4; c++)
                    cpasync(Ks + kc * 16384u + (uint32_t)r * 128u +
                            ((uint32_t)((cb + c) ^ x7) << 4),
                            ksrc + kc * 64 + (cb + c) * 8);
            const uint32_t Vs = Vb + (uint32_t)st * 32768u;
            const __half* vsrc = Vtg + (size_t)r * SQ + kv0;
            #pragma unroll
            for (int kc = 0; kc < 2; kc++)
                #pragma unroll
                for (int c = 0; c < 4; c++)
                    cpasync(Vs + kc * 16384u + (uint32_t)r * 128u +
                            ((uint32_t)((cb + c) ^ x7) << 4),
                            vsrc + kc * 64 + (cb + c) * 8);
        };
        issueKV(0, 0);
        asm volatile("cp.async.commit_group;\n");

        uint32_t qf[8][4];
        asm volatile("cp.async.wait_group 1;\n");
        __syncthreads();
        #pragma unroll
        for (int j = 0; j < 8; j++) {
            const int kc = j >> 2, jj = j & 3;
            const uint32_t gA = (uint32_t)(((2 * jj + ags) ^ l8) << 4);
            ldmx4(qf[j], Qb + kc * 16384u + aQrow + gA);
        }

        float m0 = -1e30f, m1 = -1e30f, l0 = 0.f, l1 = 0.f;
        float O[16][4];
        #pragma unroll
        for (int i = 0; i < 16; i++)
            #pragma unroll
            for (int e = 0; e < 4; e++) O[i][e] = 0.f;

        const int q0 = qt * 128 + wid * 16 + grp;

        for (int tl = 0; tl < T; tl++) {
            asm volatile("cp.async.wait_group 0;\n");
            __syncthreads();
            if (tl + 1 < T) issueKV((tl + 1) & 1, (tl + 1) * 128);
            asm volatile("cp.async.commit_group;\n");

            const uint32_t Ks = Kb + (uint32_t)(tl & 1) * 32768u;
            const uint32_t Vs = Vb + (uint32_t)(tl & 1) * 32768u;
            const int kv0 = tl * 128;

            float s[16][4];
            #pragma unroll
            for (int i = 0; i < 16; i++)
                #pragma unroll
                for (int e = 0; e < 4; e++) s[i][e] = 0.f;

            #pragma unroll
            for (int j = 0; j < 8; j++) {
                const int kc = j >> 2, jj = j & 3;
                const uint32_t gB = (uint32_t)(((2 * jj + bgs) ^ l8) << 4);
                uint32_t bq[8][4];
                #pragma unroll
                for (int pr = 0; pr < 8; pr++)
                    ldmx4(bq[pr], Ks + kc * 16384u + bRow[pr] + gB);
                #pragma unroll
                for (int nt = 0; nt < 16; nt++)
                    mma_f16(s[nt], qf[j], &bq[nt >> 1][(nt & 1) * 2]);
            }

            const bool msk = (tl == qt);
            float rm0 = -1e30f, rm1 = -1e30f;
            #pragma unroll
            for (int nt = 0; nt < 16; nt++) {
                const int c0 = kv0 + nt * 8 + 2 * tid4;
                if (msk) {
                    if (c0     > q0)     s[nt][0] = -1e30f;
                    if (c0 + 1 > q0)     s[nt][1] = -1e30f;
                    if (c0     > q0 + 8) s[nt][2] = -1e30f;
                    if (c0 + 1 > q0 + 8) s[nt][3] = -1e30f;
                }
                rm0 = fmaxf(rm0, fmaxf(s[nt][0], s[nt][1]));
                rm1 = fmaxf(rm1, fmaxf(s[nt][2], s[nt][3]));
            }
            rm0 = fmaxf(rm0, __shfl_xor_sync(0xffffffffu, rm0, 1));
            rm0 = fmaxf(rm0, __shfl_xor_sync(0xffffffffu, rm0, 2));
            rm1 = fmaxf(rm1, __shfl_xor_sync(0xffffffffu, rm1, 1));
            rm1 = fmaxf(rm1, __shfl_xor_sync(0xffffffffu, rm1, 2));

            const float mn0 = fmaxf(m0, rm0), mn1 = fmaxf(m1, rm1);
            const float sc0 = exp2f((m0 - mn0) * SCL2), sc1 = exp2f((m1 - mn1) * SCL2);
            m0 = mn0; m1 = mn1;

            uint32_t P01[16], P23[16];
            float sum0 = 0.f, sum1 = 0.f;
            #pragma unroll
            for (int nt = 0; nt < 16; nt++) {
                __half2 a01 = __floats2half2_rn((s[nt][0] - m0) * SCL2, (s[nt][1] - m0) * SCL2);
                __half2 a23 = __floats2half2_rn((s[nt][2] - m1) * SCL2, (s[nt][3] - m1) * SCL2);
                P01[nt] = ex2h2(h2u(a01));
                P23[nt] = ex2h2(h2u(a23));
                float2 f01 = __half22float2(*reinterpret_cast<__half2*>(&P01[nt]));
                float2 f23 = __half22float2(*reinterpret_cast<__half2*>(&P23[nt]));
                sum0 += f01.x + f01.y;
                sum1 += f23.x + f23.y;
            }
            sum0 += __shfl_xor_sync(0xffffffffu, sum0, 1);
            sum0 += __shfl_xor_sync(0xffffffffu, sum0, 2);
            sum1 += __shfl_xor_sync(0xffffffffu, sum1, 1);
            sum1 += __shfl_xor_sync(0xffffffffu, sum1, 2);
            l0 = l0 * sc0 + sum0;
            l1 = l1 * sc1 + sum1;

            #pragma unroll
            for (int nt = 0; nt < 16; nt++) {
                O[nt][0] *= sc0; O[nt][1] *= sc0;
                O[nt][2] *= sc1; O[nt][3] *= sc1;
            }

            #pragma unroll
            for (int j = 0; j < 8; j++) {
                const int kc = j >> 2, jj = j & 3;
                const uint32_t gB = (uint32_t)(((2 * jj + bgs) ^ l8) << 4);
                uint32_t af[4] = { P01[2 * j], P23[2 * j], P01[2 * j + 1], P23[2 * j + 1] };
                uint32_t bq[8][4];
                #pragma unroll
                for (int pr = 0; pr < 8; pr++)
                    ldmx4(bq[pr], Vs + kc * 16384u + bRow[pr] + gB);
                #pragma unroll
                for (int nt = 0; nt < 16; nt++)
                    mma_f16(O[nt], af, &bq[nt >> 1][(nt & 1) * 2]);
            }
        }

        const float inv0 = 1.f / l0, inv1 = 1.f / l1;
        const int row0 = qt * 128 + wid * 16 + grp;
        __half* o0 = g_att + (size_t)row0 * (NH * HD) + h * HD;
        __half* o1 = o0 + (size_t)8 * (NH * HD);
        #pragma unroll
        for (int nt = 0; nt < 16; nt++) {
            const int col = nt * 8 + 2 * tid4;
            *(__half2*)(o0 + col) = __floats2half2_rn(O[nt][0] * inv0, O[nt][1] * inv0);
            *(__half2*)(o1 + col) = __floats2half2_rn(O[nt][2] * inv1, O[nt][3] * inv1);
        }
    }
}

// ---------------- cvt hs + wqkv, zero d_out, reset job counter ----------------
__global__ void __launch_bounds__(256) cvt_all(
    const float* __restrict__ a, const float* __restrict__ b,
    __half* __restrict__ da, __half* __restrict__ db,
    float* __restrict__ outz,
    int na4, int nb4, int nd4)
{
    if (blockIdx.x == 0 && threadIdx.x == 0) g_job = 0;
    int i = blockIdx.x * 256 + threadIdx.x;
    if (i < na4) {
        float4 v = ((const float4*)a)[i];
        uint2 u;
        u.x = h2u(__floats2half2_rn(v.x, v.y));
        u.y = h2u(__floats2half2_rn(v.z, v.w));
        ((uint2*)da)[i] = u;
    } else if (i < na4 + nb4) {
        i -= na4;
        float4 v = ((const float4*)b)[i];
        uint2 u;
        u.x = h2u(__floats2half2_rn(v.x, v.y));
        u.y = h2u(__floats2half2_rn(v.z, v.w));
        ((uint2*)db)[i] = u;
    } else if (i < na4 + nb4 + nd4) {
        i -= na4 + nb4;
        ((float4*)outz)[i] = make_float4(0.f, 0.f, 0.f, 0.f);
    }
}

// ---------------- launch ----------------
extern "C" void kernel_launch(void* const* d_in, const int* in_sizes, int n_in,
                              void* d_out, int out_size)
{
    const float* hs     = (const float*)d_in[0];
    const float* w_qkv  = (const float*)d_in[1];
    const float* w_o    = (const float*)d_in[2];
    const float* qnw    = (const float*)d_in[3];
    const float* knw    = (const float*)d_in[4];
    const float* cosT   = (const float*)d_in[5];
    const float* sinT   = (const float*)d_in[6];
    const int* positions = (const int*)d_in[9];
    float* out = (float*)d_out;

    __half *qkv, *att, *hs_h, *wqkv_h, *wo_h;
    cudaGetSymbolAddress((void**)&qkv,    g_qkv);
    cudaGetSymbolAddress((void**)&att,    g_att);
    cudaGetSymbolAddress((void**)&hs_h,   g_hs_h);
    cudaGetSymbolAddress((void**)&wqkv_h, g_wqkv_h);
    cudaGetSymbolAddress((void**)&wo_h,   g_wo_h);

    const int GSMEM = 73728;    // 72 KB
    const int FSMEM = 163856;   // 160 KB + job slot
    cudaFuncSetAttribute(gemm64<0>,    cudaFuncAttributeMaxDynamicSharedMemorySize, GSMEM);
    cudaFuncSetAttribute(gemm64<1>,    cudaFuncAttributeMaxDynamicSharedMemorySize, GSMEM);
    cudaFuncSetAttribute(flash_kernel, cudaFuncAttributeMaxDynamicSharedMemorySize, FSMEM);

    // 0) cvt hs + wqkv -> fp16; zero d_out (for split-K atomics); reset flash jobs
    const int na4 = SQ*HID/4, nb4 = QKV_DIM*HID/4, nd4 = SQ*HID/4;
    cvt_all<<<(na4 + nb4 + nd4 + 255)/256, 256>>>(
        hs, w_qkv, hs_h, wqkv_h, out, na4, nb4, nd4);

    // 1) QKV projection (+fused epilogues) + w_o cvt tail blocks (wave filler)
    gemm64<0><<<dim3(QKV_DIM/128, SQ/64 + 5, 1), 256, GSMEM>>>(
        hs_h, wqkv_h, qkv, HID, HID, HID, QKV_DIM,
        qnw, knw, cosT, sinT, positions, w_o);

    // 2) persistent fused flash attention -> g_att (half)
    flash_kernel<<<148, 256, FSMEM>>>();

    // 3) output projection, split-K=2, atomic fp32 accumulate into d_out
    gemm64<1><<<dim3(HID/128, SQ/64, 2), 256, GSMEM>>>(
        att, wo_h, out, NH*HD, NH*HD, NH*HD, HID,
        nullptr, nullptr, nullptr, nullptr, nullptr, nullptr);
}

// round 17
// speedup vs baseline: 1.3179x; 1.0104x over previous
#include <cuda_runtime.h>
#include <cuda_fp16.h>
#include <cstdint>

#define SQ   2048
#define HID  2560
#define NH   16
#define NKV  4
#define HD   128
#define QKV_DIM (NH*HD + 2*NKV*HD)   // 3072
#define EPS  1e-6f
#define ATT_SCALE 0.08838834764831845f
#define LOG2E 1.4426950408889634f
#define SCL2  (ATT_SCALE * LOG2E)
#define NJOBS (NH * 16)              // 256 flash jobs
#define WO_N4 (HID * NH * HD / 4)    // w_o float4 count
#define CVT_CTAS 120                 // QKV tail-filler CTAs

// ---------------- scratch (device globals, no allocation) ----------------
__device__ __half g_qkv[(size_t)SQ * QKV_DIM];
__device__ __half g_att[(size_t)SQ * NH * HD];
__device__ __half g_hs_h[(size_t)SQ * HID];
__device__ __half g_wqkv_h[(size_t)QKV_DIM * HID];
__device__ __half g_wo_h[(size_t)HID * NH * HD];
__device__ __half g_vt[(size_t)NKV * HD * SQ];
__device__ int    g_job;

__device__ __forceinline__ void mma_f16(float* d, const uint32_t* a, const uint32_t* b) {
    asm volatile(
        "mma.sync.aligned.m16n8k16.row.col.f32.f16.f16.f32 "
        "{%0,%1,%2,%3}, {%4,%5,%6,%7}, {%8,%9}, {%0,%1,%2,%3};\n"
        : "+f"(d[0]), "+f"(d[1]), "+f"(d[2]), "+f"(d[3])
        : "r"(a[0]), "r"(a[1]), "r"(a[2]), "r"(a[3]), "r"(b[0]), "r"(b[1]));
}

__device__ __forceinline__ void ldmx4(uint32_t* r, uint32_t addr) {
    asm volatile("ldmatrix.sync.aligned.m8n8.x4.shared.b16 {%0,%1,%2,%3}, [%4];"
        : "=r"(r[0]), "=r"(r[1]), "=r"(r[2]), "=r"(r[3]) : "r"(addr));
}

__device__ __forceinline__ void cpasync(uint32_t d, const void* s) {
    asm volatile("cp.async.cg.shared.global [%0], [%1], 16;\n" :: "r"(d), "l"(s));
}

__device__ __forceinline__ uint32_t h2u(__half2 h) {
    return *reinterpret_cast<uint32_t*>(&h);
}
__device__ __forceinline__ uint32_t ex2h2(uint32_t x) {
    uint32_t r;
    asm("ex2.approx.f16x2 %0, %1;" : "=r"(r) : "r"(x));
    return r;
}

// ================= 64x128 GEMM engine, 3 CTAs/SM =================
// EPI 0 = QKV (+RMSNorm/RoPE or V-transpose epilogue, + w_o cvt tail blocks)
// EPI 1 = O-projection: plain fp32 store.
template<int EPI>
__global__ void __launch_bounds__(256, 3) gemm64(
    const __half* __restrict__ A, const __half* __restrict__ B, void* __restrict__ Cv,
    int K, int lda, int ldb, int ldc,
    const float* __restrict__ qnw, const float* __restrict__ knw,
    const float* __restrict__ cosT, const float* __restrict__ sinT,
    const int* __restrict__ positions,
    const float* __restrict__ wo_src)
{
    const int bx = blockIdx.x, by = blockIdx.y;
    const int t = threadIdx.x;

    if (EPI == 0 && by >= SQ / 64) {
        // ---- tail-filler blocks: convert w_o fp32 -> fp16 ----
        const int blk = (by - SQ / 64) * gridDim.x + bx;
        for (int i = blk * 256 + t; i < WO_N4; i += CVT_CTAS * 256) {
            float4 v = ((const float4*)wo_src)[i];
            uint2 u;
            u.x = h2u(__floats2half2_rn(v.x, v.y));
            u.y = h2u(__floats2half2_rn(v.z, v.w));
            ((uint2*)g_wo_h)[i] = u;
        }
        return;
    }

    extern __shared__ char smem[];
    const uint32_t sbase = (uint32_t)__cvta_generic_to_shared(smem);

    const int lane = t & 31, wid = t >> 5;
    const int wm   = (wid & 1) * 32;
    const int wn   = (wid >> 1) * 32;
    const int m0   = by * 64, n0 = bx * 128;
    const int grp  = lane >> 2, tid4 = lane & 3;

    const int l8    = lane & 7;
    const int aoff8 = ((lane >> 3) & 1) * 8;
    const int ags   = (lane >> 4) & 1;
    const int boff8 = ((lane >> 4) & 1) * 8;
    const int bgs   = (lane >> 3) & 1;
    uint32_t arow[2], brow[2];
    #pragma unroll
    for (int mt = 0; mt < 2; mt++) arow[mt] = (uint32_t)(wm + mt * 16 + aoff8 + l8) * 128u;
    #pragma unroll
    for (int pr = 0; pr < 2; pr++) brow[pr] = (uint32_t)(wn + pr * 16 + boff8 + l8) * 128u;

    const int lrA = t >> 2, cbA = (t & 3) * 2, x7A = lrA & 7;
    const int lrB = t >> 1, cbB = (t & 1) * 4, x7B = lrB & 7;
    const __half* Aptr = A + (long long)(m0 + lrA) * lda;
    const __half* Bptr = B + (long long)(n0 + lrB) * ldb;

    float acc[2][4][4];
    #pragma unroll
    for (int i = 0; i < 2; i++)
        #pragma unroll
        for (int j = 0; j < 4; j++)
            #pragma unroll
            for (int r = 0; r < 4; r++) acc[i][j][r] = 0.f;

    const int nK = K >> 6;

    auto issue = [&](int st, int k0) {
        const uint32_t ab = sbase + st * 8192u + (uint32_t)lrA * 128u;
        #pragma unroll
        for (int c = 0; c < 2; c++)
            cpasync(ab + (uint32_t)(((cbA + c) ^ x7A) << 4), Aptr + k0 + (cbA + c) * 8);
        const uint32_t bb = sbase + 24576u + st * 16384u + (uint32_t)lrB * 128u;
        #pragma unroll
        for (int c = 0; c < 4; c++)
            cpasync(bb + (uint32_t)(((cbB + c) ^ x7B) << 4), Bptr + k0 + (cbB + c) * 8);
    };

    issue(0, 0);
    asm volatile("cp.async.commit_group;\n");
    issue(1, 64);
    asm volatile("cp.async.commit_group;\n");

    for (int kt = 0; kt < nK; kt++) {
        asm volatile("cp.async.wait_group 1;\n");
        __syncthreads();

        const int st = kt - (kt / 3) * 3;
        const uint32_t sA = sbase + st * 8192u;
        const uint32_t sB = sbase + 24576u + st * 16384u;

        #pragma unroll
        for (int j = 0; j < 4; j++) {
            const uint32_t ga = (uint32_t)(((2 * j + ags) ^ l8) << 4);
            const uint32_t gb = (uint32_t)(((2 * j + bgs) ^ l8) << 4);
            uint32_t af[2][4], bq[2][4];
            ldmx4(af[0], sA + arow[0] + ga);
            ldmx4(af[1], sA + arow[1] + ga);
            ldmx4(bq[0], sB + brow[0] + gb);
            ldmx4(bq[1], sB + brow[1] + gb);
            #pragma unroll
            for (int mt = 0; mt < 2; mt++) {
                mma_f16(acc[mt][0], af[mt], &bq[0][0]);
                mma_f16(acc[mt][1], af[mt], &bq[0][2]);
                mma_f16(acc[mt][2], af[mt], &bq[1][0]);
                mma_f16(acc[mt][3], af[mt], &bq[1][2]);
            }
        }

        if (kt + 2 < nK) issue((kt + 2) - ((kt + 2) / 3) * 3, (kt + 2) << 6);
        asm volatile("cp.async.commit_group;\n");
    }

    if (EPI == 1) {
        float* C = (float*)Cv;
        #pragma unroll
        for (int mt = 0; mt < 2; mt++) {
            #pragma unroll
            for (int nt = 0; nt < 4; nt++) {
                const int r0 = m0 + wm + mt * 16 + grp;
                const int col = n0 + wn + nt * 8 + tid4 * 2;
                float2 lo, hi;
                lo.x = acc[mt][nt][0]; lo.y = acc[mt][nt][1];
                hi.x = acc[mt][nt][2]; hi.y = acc[mt][nt][3];
                *(float2*)(C + (long long)r0 * ldc + col)       = lo;
                *(float2*)(C + (long long)(r0 + 8) * ldc + col) = hi;
            }
        }
        return;
    }

    __half* C = (__half*)Cv;
    const bool is_q = (bx < NH);
    const bool is_k = (bx >= NH) && (bx < NH + NKV);

    if (is_q || is_k) {
        const float* w = is_q ? qnw : knw;
        float* red = (float*)smem;
        __syncthreads();

        const int nw = wid >> 1;
        float rn0[2], rn1[2];

        #pragma unroll
        for (int mt = 0; mt < 2; mt++) {
            float p0 = 0.f, p1 = 0.f;
            #pragma unroll
            for (int nt = 0; nt < 4; nt++) {
                p0 += acc[mt][nt][0] * acc[mt][nt][0] + acc[mt][nt][1] * acc[mt][nt][1];
                p1 += acc[mt][nt][2] * acc[mt][nt][2] + acc[mt][nt][3] * acc[mt][nt][3];
            }
            p0 += __shfl_xor_sync(0xffffffffu, p0, 1);
            p0 += __shfl_xor_sync(0xffffffffu, p0, 2);
            p1 += __shfl_xor_sync(0xffffffffu, p1, 1);
            p1 += __shfl_xor_sync(0xffffffffu, p1, 2);
            if (tid4 == 0) {
                red[nw * 64 + wm + mt * 16 + grp]     = p0;
                red[nw * 64 + wm + mt * 16 + grp + 8] = p1;
            }
        }
        __syncthreads();

        #pragma unroll
        for (int mt = 0; mt < 2; mt++) {
            const int r0 = wm + mt * 16 + grp;
            float s0 = red[r0] + red[64 + r0] + red[128 + r0] + red[192 + r0];
            float s1 = red[r0 + 8] + red[64 + r0 + 8] + red[128 + r0 + 8] + red[192 + r0 + 8];
            rn0[mt] = rsqrtf(s0 * (1.0f / HD) + EPS);
            rn1[mt] = rsqrtf(s1 * (1.0f / HD) + EPS);
        }

        #pragma unroll
        for (int mt = 0; mt < 2; mt++) {
            const int tok0 = m0 + wm + mt * 16 + grp;
            const int tok1 = tok0 + 8;
            const int pos0 = positions[tok0];
            const int pos1 = positions[tok1];
            #pragma unroll
            for (int nt = 0; nt < 4; nt++) {
                const int col = wn + nt * 8 + tid4 * 2;
                const int p   = col >> 1;
                const float w0 = w[col], w1 = w[col + 1];
                const float c0 = cosT[pos0 * (HD/2) + p], sn0 = sinT[pos0 * (HD/2) + p];
                const float c1 = cosT[pos1 * (HD/2) + p], sn1 = sinT[pos1 * (HD/2) + p];

                float x0 = acc[mt][nt][0] * rn0[mt] * w0;
                float x1 = acc[mt][nt][1] * rn0[mt] * w1;
                float y0 = acc[mt][nt][2] * rn1[mt] * w0;
                float y1 = acc[mt][nt][3] * rn1[mt] * w1;

                __half2 lo = __floats2half2_rn(x0 * c0 - x1 * sn0, x0 * sn0 + x1 * c0);
                __half2 hi = __floats2half2_rn(y0 * c1 - y1 * sn1, y0 * sn1 + y1 * c1);
                *(__half2*)(C + (long long)tok0 * ldc + n0 + col) = lo;
                *(__half2*)(C + (long long)tok1 * ldc + n0 + col) = hi;
            }
        }
    } else {
        __half* tsm = (__half*)smem;   // [128 d][72 tok]
        __syncthreads();

        #pragma unroll
        for (int mt = 0; mt < 2; mt++) {
            const int tok0 = wm + mt * 16 + grp;
            const int tok1 = tok0 + 8;
            #pragma unroll
            for (int nt = 0; nt < 4; nt++) {
                const int d = wn + nt * 8 + tid4 * 2;
                tsm[(d    ) * 72 + tok0] = __float2half_rn(acc[mt][nt][0]);
                tsm[(d + 1) * 72 + tok0] = __float2half_rn(acc[mt][nt][1]);
                tsm[(d    ) * 72 + tok1] = __float2half_rn(acc[mt][nt][2]);
                tsm[(d + 1) * 72 + tok1] = __float2half_rn(acc[mt][nt][3]);
            }
        }
        __syncthreads();

        const int hkv = bx - (NH + NKV);
        #pragma unroll
        for (int i = t; i < 128 * 8; i += 256) {
            const int dr  = i >> 3;
            const int seg = i & 7;
            uint4 v = *(const uint4*)(tsm + dr * 72 + seg * 8);
            *(uint4*)(g_vt + (size_t)(hkv * HD + dr) * SQ + m0 + seg * 8) = v;
        }
    }
}

// ---------------- persistent fused flash attention ----------------
// issueKV moved AFTER the QK MMA block (R9 lesson: keep cp.async issue
// traffic off the fragment-load critical path).
__global__ void __launch_bounds__(256, 1) flash_kernel()
{
    extern __shared__ char fsm[];
    const uint32_t sb = (uint32_t)__cvta_generic_to_shared(fsm);
    const uint32_t Qb = sb;
    const uint32_t Kb = sb + 32768u;
    const uint32_t Vb = sb + 98304u;
    int* jobslot = (int*)(fsm + 163840);

    const int t = threadIdx.x, lane = t & 31, wid = t >> 5;
    const int grp = lane >> 2, tid4 = lane & 3;
    const int l8 = lane & 7;
    const int aoff8 = ((lane >> 3) & 1) * 8;
    const int ags   = (lane >> 4) & 1;
    const int boff8 = ((lane >> 4) & 1) * 8;
    const int bgs   = (lane >> 3) & 1;

    const int r  = t >> 1;
    const int cb = (t & 1) * 4;
    const int x7 = r & 7;

    const uint32_t aQrow = (uint32_t)(wid * 16 + aoff8 + l8) * 128u;
    uint32_t bRow[8];
    #pragma unroll
    for (int pr = 0; pr < 8; pr++) bRow[pr] = (uint32_t)(pr * 16 + boff8 + l8) * 128u;

    for (;;) {
        __syncthreads();
        if (t == 0) *jobslot = atomicAdd(&g_job, 1);
        __syncthreads();
        const int job = *jobslot;
        if (job >= NJOBS) return;

        const int qt = 15 - (job >> 4);
        const int h  = job & 15;
        const int hkv = h >> 2;

        const __half* Qg  = g_qkv + h * HD;
        const __half* Kg  = g_qkv + NH * HD + hkv * HD;
        const __half* Vtg = g_vt + (size_t)hkv * HD * SQ;

        {
            const __half* src = Qg + (size_t)(qt * 128 + r) * QKV_DIM;
            #pragma unroll
            for (int kc = 0; kc < 2; kc++)
                #pragma unroll
                for (int c = 0; c < 4; c++)
                    cpasync(Qb + kc * 16384u + (uint32_t)r * 128u +
                            ((uint32_t)((cb + c) ^ x7) << 4),
                            src + kc * 64 + (cb + c) * 8);
        }
        asm volatile("cp.async.commit_group;\n");

        const int T = qt + 1;

        auto issueKV = [&](int st, int kv0) {
            const uint32_t Ks = Kb + (uint32_t)st * 32768u;
            const __half* ksrc = Kg + (size_t)(kv0 + r) * QKV_DIM;
            #pragma unroll
            for (int kc = 0; kc < 2; kc++)
                #pragma unroll
                for (int c = 0; c < 4; c++)
                    cpasync(Ks + kc * 16384u + (uint32_t)r * 128u +
                            ((uint32_t)((cb + c) ^ x7) << 4),
                            ksrc + kc * 64 + (cb + c) * 8);
            const uint32_t Vs = Vb + (uint32_t)st * 32768u;
            const __half* vsrc = Vtg + (size_t)r * SQ + kv0;
            #pragma unroll
            for (int kc = 0; kc < 2; kc++)
                #pragma unroll
                for (int c = 0; c < 4; c++)
                    cpasync(Vs + kc * 16384u + (uint32_t)r * 128u +
                            ((uint32_t)((cb + c) ^ x7) << 4),
                            vsrc + kc * 64 + (cb + c) * 8);
        };
        issueKV(0, 0);
        asm volatile("cp.async.commit_group;\n");

        uint32_t qf[8][4];
        asm volatile("cp.async.wait_group 1;\n");
        __syncthreads();
        #pragma unroll
        for (int j = 0; j < 8; j++) {
            const int kc = j >> 2, jj = j & 3;
            const uint32_t gA = (uint32_t)(((2 * jj + ags) ^ l8) << 4);
            ldmx4(qf[j], Qb + kc * 16384u + aQrow + gA);
        }

        float m0 = -1e30f, m1 = -1e30f, l0 = 0.f, l1 = 0.f;
        float O[16][4];
        #pragma unroll
        for (int i = 0; i < 16; i++)
            #pragma unroll
            for (int e = 0; e < 4; e++) O[i][e] = 0.f;

        const int q0 = qt * 128 + wid * 16 + grp;

        for (int tl = 0; tl < T; tl++) {
            asm volatile("cp.async.wait_group 0;\n");
            __syncthreads();

            const uint32_t Ks = Kb + (uint32_t)(tl & 1) * 32768u;
            const uint32_t Vs = Vb + (uint32_t)(tl & 1) * 32768u;
            const int kv0 = tl * 128;

            // ---- S = Q K^T ----
            float s[16][4];
            #pragma unroll
            for (int i = 0; i < 16; i++)
                #pragma unroll
                for (int e = 0; e < 4; e++) s[i][e] = 0.f;

            #pragma unroll
            for (int j = 0; j < 8; j++) {
                const int kc = j >> 2, jj = j & 3;
                const uint32_t gB = (uint32_t)(((2 * jj + bgs) ^ l8) << 4);
                uint32_t bq[8][4];
                #pragma unroll
                for (int pr = 0; pr < 8; pr++)
                    ldmx4(bq[pr], Ks + kc * 16384u + bRow[pr] + gB);
                #pragma unroll
                for (int nt = 0; nt < 16; nt++)
                    mma_f16(s[nt], qf[j], &bq[nt >> 1][(nt & 1) * 2]);
            }

            // issue next tile's loads AFTER QK fragment traffic
            if (tl + 1 < T) issueKV((tl + 1) & 1, (tl + 1) * 128);
            asm volatile("cp.async.commit_group;\n");

            const bool msk = (tl == qt);
            float rm0 = -1e30f, rm1 = -1e30f;
            #pragma unroll
            for (int nt = 0; nt < 16; nt++) {
                const int c0 = kv0 + nt * 8 + 2 * tid4;
                if (msk) {
                    if (c0     > q0)     s[nt][0] = -1e30f;
                    if (c0 + 1 > q0)     s[nt][1] = -1e30f;
                    if (c0     > q0 + 8) s[nt][2] = -1e30f;
                    if (c0 + 1 > q0 + 8) s[nt][3] = -1e30f;
                }
                rm0 = fmaxf(rm0, fmaxf(s[nt][0], s[nt][1]));
                rm1 = fmaxf(rm1, fmaxf(s[nt][2], s[nt][3]));
            }
            rm0 = fmaxf(rm0, __shfl_xor_sync(0xffffffffu, rm0, 1));
            rm0 = fmaxf(rm0, __shfl_xor_sync(0xffffffffu, rm0, 2));
            rm1 = fmaxf(rm1, __shfl_xor_sync(0xffffffffu, rm1, 1));
            rm1 = fmaxf(rm1, __shfl_xor_sync(0xffffffffu, rm1, 2));

            const float mn0 = fmaxf(m0, rm0), mn1 = fmaxf(m1, rm1);
            const float sc0 = exp2f((m0 - mn0) * SCL2), sc1 = exp2f((m1 - mn1) * SCL2);
            m0 = mn0; m1 = mn1;

            uint32_t P01[16], P23[16];
            float sum0 = 0.f, sum1 = 0.f;
            #pragma unroll
            for (int nt = 0; nt < 16; nt++) {
                __half2 a01 = __floats2half2_rn((s[nt][0] - m0) * SCL2, (s[nt][1] - m0) * SCL2);
                __half2 a23 = __floats2half2_rn((s[nt][2] - m1) * SCL2, (s[nt][3] - m1) * SCL2);
                P01[nt] = ex2h2(h2u(a01));
                P23[nt] = ex2h2(h2u(a23));
                float2 f01 = __half22float2(*reinterpret_cast<__half2*>(&P01[nt]));
                float2 f23 = __half22float2(*reinterpret_cast<__half2*>(&P23[nt]));
                sum0 += f01.x + f01.y;
                sum1 += f23.x + f23.y;
            }
            sum0 += __shfl_xor_sync(0xffffffffu, sum0, 1);
            sum0 += __shfl_xor_sync(0xffffffffu, sum0, 2);
            sum1 += __shfl_xor_sync(0xffffffffu, sum1, 1);
            sum1 += __shfl_xor_sync(0xffffffffu, sum1, 2);
            l0 = l0 * sc0 + sum0;
            l1 = l1 * sc1 + sum1;

            #pragma unroll
            for (int nt = 0; nt < 16; nt++) {
                O[nt][0] *= sc0; O[nt][1] *= sc0;
                O[nt][2] *= sc1; O[nt][3] *= sc1;
            }

            #pragma unroll
            for (int j = 0; j < 8; j++) {
                const int kc = j >> 2, jj = j & 3;
                const uint32_t gB = (uint32_t)(((2 * jj + bgs) ^ l8) << 4);
                uint32_t af[4] = { P01[2 * j], P23[2 * j], P01[2 * j + 1], P23[2 * j + 1] };
                uint32_t bq[8][4];
                #pragma unroll
                for (int pr = 0; pr < 8; pr++)
                    ldmx4(bq[pr], Vs + kc * 16384u + bRow[pr] + gB);
                #pragma unroll
                for (int nt = 0; nt < 16; nt++)
                    mma_f16(O[nt], af, &bq[nt >> 1][(nt & 1) * 2]);
            }
        }

        const float inv0 = 1.f / l0, inv1 = 1.f / l1;
        const int row0 = qt * 128 + wid * 16 + grp;
        __half* o0 = g_att + (size_t)row0 * (NH * HD) + h * HD;
        __half* o1 = o0 + (size_t)8 * (NH * HD);
        #pragma unroll
        for (int nt = 0; nt < 16; nt++) {
            const int col = nt * 8 + 2 * tid4;
            *(__half2*)(o0 + col) = __floats2half2_rn(O[nt][0] * inv0, O[nt][1] * inv0);
            *(__half2*)(o1 + col) = __floats2half2_rn(O[nt][2] * inv1, O[nt][3] * inv1);
        }
    }
}

// ---------------- cvt hs + wqkv, reset job counter ----------------
__global__ void __launch_bounds__(256) cvt_all(
    const float* __restrict__ a, const float* __restrict__ b,
    __half* __restrict__ da, __half* __restrict__ db,
    int na4, int nb4)
{
    if (blockIdx.x == 0 && threadIdx.x == 0) g_job = 0;
    int i = blockIdx.x * 256 + threadIdx.x;
    const float* src; __half* dst;
    if (i < na4)            { src = a; dst = da; }
    else if (i < na4 + nb4) { i -= na4; src = b; dst = db; }
    else return;
    float4 v = ((const float4*)src)[i];
    uint2 u;
    u.x = h2u(__floats2half2_rn(v.x, v.y));
    u.y = h2u(__floats2half2_rn(v.z, v.w));
    ((uint2*)dst)[i] = u;
}

// ---------------- launch ----------------
extern "C" void kernel_launch(void* const* d_in, const int* in_sizes, int n_in,
                              void* d_out, int out_size)
{
    const float* hs     = (const float*)d_in[0];
    const float* w_qkv  = (const float*)d_in[1];
    const float* w_o    = (const float*)d_in[2];
    const float* qnw    = (const float*)d_in[3];
    const float* knw    = (const float*)d_in[4];
    const float* cosT   = (const float*)d_in[5];
    const float* sinT   = (const float*)d_in[6];
    const int* positions = (const int*)d_in[9];
    float* out = (float*)d_out;

    __half *qkv, *att, *hs_h, *wqkv_h, *wo_h;
    cudaGetSymbolAddress((void**)&qkv,    g_qkv);
    cudaGetSymbolAddress((void**)&att,    g_att);
    cudaGetSymbolAddress((void**)&hs_h,   g_hs_h);
    cudaGetSymbolAddress((void**)&wqkv_h, g_wqkv_h);
    cudaGetSymbolAddress((void**)&wo_h,   g_wo_h);

    const int GSMEM = 73728;    // 72 KB
    const int FSMEM = 163856;   // 160 KB + job slot
    cudaFuncSetAttribute(gemm64<0>,    cudaFuncAttributeMaxDynamicSharedMemorySize, GSMEM);
    cudaFuncSetAttribute(gemm64<1>,    cudaFuncAttributeMaxDynamicSharedMemorySize, GSMEM);
    cudaFuncSetAttribute(flash_kernel, cudaFuncAttributeMaxDynamicSharedMemorySize, FSMEM);

    // 0) cvt hs + wqkv -> fp16; reset flash job counter
    const int na4 = SQ*HID/4, nb4 = QKV_DIM*HID/4;
    cvt_all<<<(na4 + nb4 + 255)/256, 256>>>(hs, w_qkv, hs_h, wqkv_h, na4, nb4);

    // 1) QKV projection (+fused epilogues) + w_o cvt tail blocks
    gemm64<0><<<dim3(QKV_DIM/128, SQ/64 + 5, 1), 256, GSMEM>>>(
        hs_h, wqkv_h, qkv, HID, HID, HID, QKV_DIM,
        qnw, knw, cosT, sinT, positions, w_o);

    // 2) persistent fused flash attention -> g_att (half)
    flash_kernel<<<148, 256, FSMEM>>>();

    // 3) output projection (plain fp32 stores)
    gemm64<1><<<dim3(HID/128, SQ/64, 1), 256, GSMEM>>>(
        att, wo_h, out, NH*HD, NH*HD, NH*HD, HID,
        nullptr, nullptr, nullptr, nullptr, nullptr, nullptr);
}